// round 1
// baseline (speedup 1.0000x reference)
#include <cuda_runtime.h>
#include <math.h>

#define BM 128
#define BN 128
#define BK 8
#define TM 8
#define TN 8

// Problem constants
#define BATCH 8
#define SEQ   4096
#define VDIM  1024
#define KQDIM 256

// Scratch in device globals (no runtime allocation allowed)
__device__ float g_q[(size_t)BATCH * SEQ * VDIM];
__device__ float g_k[(size_t)BATCH * SEQ * VDIM];
__device__ float g_v[(size_t)BATCH * SEQ * VDIM];
__device__ float g_attn[(size_t)BATCH * VDIM * VDIM];

// ---------------------------------------------------------------------------
// C[M,N] = A[M,K] * B[N,K]^T + bias[N]
// A row-major with leading dim lda, B row-major with leading dim ldb.
// M,N multiples of 128; K multiple of 8. 256 threads.
// ---------------------------------------------------------------------------
__global__ __launch_bounds__(256, 2) void gemm_nt_bias(
    const float* __restrict__ A, int lda,
    const float* __restrict__ B, int ldb,
    const float* __restrict__ bias,
    float* __restrict__ C, int ldc, int K)
{
    __shared__ float As[BK][BM];
    __shared__ float Bs[BK][BN];
    const int tid = threadIdx.x;
    const size_t m0 = (size_t)blockIdx.y * BM;
    const size_t n0 = (size_t)blockIdx.x * BN;

    // Load mapping: 2 threads per row, each one float4 of the 8-wide K slab
    const int sr = tid >> 1;          // 0..127 row within tile
    const int sc = (tid & 1) << 2;    // 0 or 4 within K slab
    const float* Ap = A + (m0 + sr) * (size_t)lda + sc;
    const float* Bp = B + (n0 + sr) * (size_t)ldb + sc;

    const int mo = (tid >> 4) * TM;
    const int no = (tid & 15) * TN;

    float acc[TM][TN] = {};

    for (int k0 = 0; k0 < K; k0 += BK) {
        float4 av = *(const float4*)(Ap + k0);
        float4 bv = *(const float4*)(Bp + k0);
        As[sc + 0][sr] = av.x; As[sc + 1][sr] = av.y;
        As[sc + 2][sr] = av.z; As[sc + 3][sr] = av.w;
        Bs[sc + 0][sr] = bv.x; Bs[sc + 1][sr] = bv.y;
        Bs[sc + 2][sr] = bv.z; Bs[sc + 3][sr] = bv.w;
        __syncthreads();
#pragma unroll
        for (int kk = 0; kk < BK; kk++) {
            float a[TM], b[TN];
            *(float4*)&a[0] = *(const float4*)&As[kk][mo];
            *(float4*)&a[4] = *(const float4*)&As[kk][mo + 4];
            *(float4*)&b[0] = *(const float4*)&Bs[kk][no];
            *(float4*)&b[4] = *(const float4*)&Bs[kk][no + 4];
#pragma unroll
            for (int i = 0; i < TM; i++)
#pragma unroll
                for (int j = 0; j < TN; j++)
                    acc[i][j] = fmaf(a[i], b[j], acc[i][j]);
        }
        __syncthreads();
    }

    float bb[TN];
#pragma unroll
    for (int j = 0; j < TN; j++) bb[j] = bias[n0 + no + j];
#pragma unroll
    for (int i = 0; i < TM; i++) {
        float* crow = C + (m0 + mo + i) * (size_t)ldc + n0 + no;
        float4 o0, o1;
        o0.x = acc[i][0] + bb[0]; o0.y = acc[i][1] + bb[1];
        o0.z = acc[i][2] + bb[2]; o0.w = acc[i][3] + bb[3];
        o1.x = acc[i][4] + bb[4]; o1.y = acc[i][5] + bb[5];
        o1.z = acc[i][6] + bb[6]; o1.w = acc[i][7] + bb[7];
        *(float4*)(crow) = o0;
        *(float4*)(crow + 4) = o1;
    }
}

// ---------------------------------------------------------------------------
// attn[b,i,j] = sum_n k[b,n,i] * q[b,n,j]   (TN GEMM, per-batch, K = SEQ)
// ---------------------------------------------------------------------------
__global__ __launch_bounds__(256, 2) void gemm_tn_batched(
    const float* __restrict__ Kmat,
    const float* __restrict__ Qmat,
    float* __restrict__ Attn)
{
    __shared__ float As[BK][BM];
    __shared__ float Bs[BK][BN];
    const int tid = threadIdx.x;
    const size_t b = blockIdx.z;
    const float* A = Kmat + b * (size_t)SEQ * VDIM;
    const float* B = Qmat + b * (size_t)SEQ * VDIM;
    float* C = Attn + b * (size_t)VDIM * VDIM;
    const size_t i0 = (size_t)blockIdx.y * BM;
    const size_t j0 = (size_t)blockIdx.x * BN;

    // Direct (non-transposed) loads: rows of A/B are contiguous along tile dim
    const int lr = tid >> 5;          // 0..7: n within slab
    const int lc = (tid & 31) << 2;   // 0..124

    const int mo = (tid >> 4) * TM;
    const int no = (tid & 15) * TN;

    float acc[TM][TN] = {};

    for (int n0 = 0; n0 < SEQ; n0 += BK) {
        float4 av = *(const float4*)(A + (size_t)(n0 + lr) * VDIM + i0 + lc);
        float4 bv = *(const float4*)(B + (size_t)(n0 + lr) * VDIM + j0 + lc);
        *(float4*)&As[lr][lc] = av;
        *(float4*)&Bs[lr][lc] = bv;
        __syncthreads();
#pragma unroll
        for (int kk = 0; kk < BK; kk++) {
            float a[TM], bb[TN];
            *(float4*)&a[0] = *(const float4*)&As[kk][mo];
            *(float4*)&a[4] = *(const float4*)&As[kk][mo + 4];
            *(float4*)&bb[0] = *(const float4*)&Bs[kk][no];
            *(float4*)&bb[4] = *(const float4*)&Bs[kk][no + 4];
#pragma unroll
            for (int i = 0; i < TM; i++)
#pragma unroll
                for (int j = 0; j < TN; j++)
                    acc[i][j] = fmaf(a[i], bb[j], acc[i][j]);
        }
        __syncthreads();
    }

#pragma unroll
    for (int i = 0; i < TM; i++) {
        float* crow = C + (i0 + mo + i) * (size_t)VDIM + j0 + no;
        *(float4*)(crow)     = *(float4*)&acc[i][0];
        *(float4*)(crow + 4) = *(float4*)&acc[i][4];
    }
}

// ---------------------------------------------------------------------------
// Row softmax over last dim (1024), one block per row, 256 threads.
// ---------------------------------------------------------------------------
__global__ void softmax1024(float* __restrict__ Attn)
{
    __shared__ float sred[8];
    __shared__ float sval;
    const size_t row = blockIdx.x;
    float4* p = (float4*)(Attn + row * (size_t)VDIM);
    const int tid = threadIdx.x;
    const int lane = tid & 31, wid = tid >> 5;

    float4 x = p[tid];
    float m = fmaxf(fmaxf(x.x, x.y), fmaxf(x.z, x.w));
#pragma unroll
    for (int o = 16; o; o >>= 1) m = fmaxf(m, __shfl_xor_sync(0xffffffffu, m, o));
    if (lane == 0) sred[wid] = m;
    __syncthreads();
    if (tid == 0) {
        float mm = sred[0];
#pragma unroll
        for (int i = 1; i < 8; i++) mm = fmaxf(mm, sred[i]);
        sval = mm;
    }
    __syncthreads();
    m = sval;
    __syncthreads();

    x.x = __expf(x.x - m); x.y = __expf(x.y - m);
    x.z = __expf(x.z - m); x.w = __expf(x.w - m);
    float s = x.x + x.y + x.z + x.w;
#pragma unroll
    for (int o = 16; o; o >>= 1) s += __shfl_xor_sync(0xffffffffu, s, o);
    if (lane == 0) sred[wid] = s;
    __syncthreads();
    if (tid == 0) {
        float ss = 0.f;
#pragma unroll
        for (int i = 0; i < 8; i++) ss += sred[i];
        sval = 1.0f / ss;
    }
    __syncthreads();
    float inv = sval;
    x.x *= inv; x.y *= inv; x.z *= inv; x.w *= inv;
    p[tid] = x;
}

// ---------------------------------------------------------------------------
// out[b,n,w] = gamma * sum_v V[b,n,v] * attn[b,v,w] + input[b,n,w]
// NN GEMM per batch, K = 1024, fused residual epilogue.
// ---------------------------------------------------------------------------
__global__ __launch_bounds__(256, 2) void gemm_nn_epi(
    const float* __restrict__ Vmat,
    const float* __restrict__ Attn,
    const float* __restrict__ input,
    const float* __restrict__ gamma,
    float* __restrict__ Out)
{
    __shared__ float As[BK][BM];
    __shared__ float Bs[BK][BN];
    const int tid = threadIdx.x;
    const size_t b = blockIdx.z;
    const float* A  = Vmat + b * (size_t)SEQ * VDIM;   // [SEQ, VDIM]
    const float* Bm = Attn + b * (size_t)VDIM * VDIM;  // [VDIM, VDIM]
    const size_t m0 = (size_t)blockIdx.y * BM;          // within batch
    const size_t n0 = (size_t)blockIdx.x * BN;

    // A: transpose-on-load (K contiguous in A's rows)
    const int sr = tid >> 1;
    const int sc = (tid & 1) << 2;
    // B: direct rows
    const int lr = tid >> 5;
    const int lc = (tid & 31) << 2;

    const int mo = (tid >> 4) * TM;
    const int no = (tid & 15) * TN;

    float acc[TM][TN] = {};

    for (int k0 = 0; k0 < VDIM; k0 += BK) {
        float4 av = *(const float4*)(A + (m0 + sr) * (size_t)VDIM + k0 + sc);
        float4 bv = *(const float4*)(Bm + (size_t)(k0 + lr) * VDIM + n0 + lc);
        As[sc + 0][sr] = av.x; As[sc + 1][sr] = av.y;
        As[sc + 2][sr] = av.z; As[sc + 3][sr] = av.w;
        *(float4*)&Bs[lr][lc] = bv;
        __syncthreads();
#pragma unroll
        for (int kk = 0; kk < BK; kk++) {
            float a[TM], bb[TN];
            *(float4*)&a[0] = *(const float4*)&As[kk][mo];
            *(float4*)&a[4] = *(const float4*)&As[kk][mo + 4];
            *(float4*)&bb[0] = *(const float4*)&Bs[kk][no];
            *(float4*)&bb[4] = *(const float4*)&Bs[kk][no + 4];
#pragma unroll
            for (int i = 0; i < TM; i++)
#pragma unroll
                for (int j = 0; j < TN; j++)
                    acc[i][j] = fmaf(a[i], bb[j], acc[i][j]);
        }
        __syncthreads();
    }

    const float g = *gamma;
#pragma unroll
    for (int i = 0; i < TM; i++) {
        const size_t grow = (b * SEQ + m0 + mo + i) * (size_t)VDIM + n0 + no;
        float4 r0 = *(const float4*)(input + grow);
        float4 r1 = *(const float4*)(input + grow + 4);
        float4 o0, o1;
        o0.x = fmaf(g, acc[i][0], r0.x); o0.y = fmaf(g, acc[i][1], r0.y);
        o0.z = fmaf(g, acc[i][2], r0.z); o0.w = fmaf(g, acc[i][3], r0.w);
        o1.x = fmaf(g, acc[i][4], r1.x); o1.y = fmaf(g, acc[i][5], r1.y);
        o1.z = fmaf(g, acc[i][6], r1.z); o1.w = fmaf(g, acc[i][7], r1.w);
        *(float4*)(Out + grow)     = o0;
        *(float4*)(Out + grow + 4) = o1;
    }
}

// ---------------------------------------------------------------------------
extern "C" void kernel_launch(void* const* d_in, const int* in_sizes, int n_in,
                              void* d_out, int out_size)
{
    const float* input = (const float*)d_in[0];
    const float* Wq    = (const float*)d_in[1];
    const float* bq    = (const float*)d_in[2];
    const float* Wk    = (const float*)d_in[3];
    const float* bk    = (const float*)d_in[4];
    const float* Wv    = (const float*)d_in[5];
    const float* bv    = (const float*)d_in[6];
    const float* gamma = (const float*)d_in[7];
    float* out = (float*)d_out;

    float *qp, *kp, *vp, *ap;
    cudaGetSymbolAddress((void**)&qp, g_q);
    cudaGetSymbolAddress((void**)&kp, g_k);
    cudaGetSymbolAddress((void**)&vp, g_v);
    cudaGetSymbolAddress((void**)&ap, g_attn);

    const dim3 blk(256);
    const int M = BATCH * SEQ;  // 32768

    // q, k from last-256 slice of input (columns 768..1023)
    gemm_nt_bias<<<dim3(VDIM / BN, M / BM), blk>>>(input + (VDIM - KQDIM), VDIM,
                                                   Wq, KQDIM, bq, qp, VDIM, KQDIM);
    gemm_nt_bias<<<dim3(VDIM / BN, M / BM), blk>>>(input + (VDIM - KQDIM), VDIM,
                                                   Wk, KQDIM, bk, kp, VDIM, KQDIM);
    // v from full input
    gemm_nt_bias<<<dim3(VDIM / BN, M / BM), blk>>>(input, VDIM,
                                                   Wv, VDIM, bv, vp, VDIM, VDIM);
    // attn = K^T Q per batch
    gemm_tn_batched<<<dim3(VDIM / BN, VDIM / BM, BATCH), blk>>>(kp, qp, ap);
    // softmax over last dim
    softmax1024<<<BATCH * VDIM, 256>>>(ap);
    // out = gamma * (V attn) + input
    gemm_nn_epi<<<dim3(VDIM / BN, SEQ / BM, BATCH), blk>>>(vp, ap, input, gamma, out);
}

// round 3
// speedup vs baseline: 1.6980x; 1.6980x over previous
#include <cuda_runtime.h>
#include <cuda_bf16.h>
#include <cstdint>
#include <math.h>

// Problem constants
#define BATCH 8
#define SEQ   4096
#define VDIM  1024
#define KQDIM 256

// ---------------------------------------------------------------------------
// Scratch (device globals; no runtime allocation allowed)
// ---------------------------------------------------------------------------
__device__ float g_qT[(size_t)VDIM * BATCH * SEQ];     // [1024 w][32768 n]
__device__ float g_kT[(size_t)VDIM * BATCH * SEQ];     // [1024 v][32768 n]
__device__ float g_v[(size_t)BATCH * SEQ * VDIM];      // [32768 n][1024 v]
__device__ float g_attnT[(size_t)BATCH * VDIM * VDIM]; // [8][1024 w][1024 v]

// ---------------------------------------------------------------------------
// Helpers
// ---------------------------------------------------------------------------
__device__ __forceinline__ uint32_t smem_to_u32(const void* p) {
    uint32_t a;
    asm("{ .reg .u64 t; cvta.to.shared.u64 t, %1; cvt.u32.u64 %0, t; }"
        : "=r"(a) : "l"(p));
    return a;
}

__device__ __forceinline__ void ldsm_x4(uint32_t addr, uint32_t* r) {
    asm volatile("ldmatrix.sync.aligned.m8n8.x4.shared.b16 {%0,%1,%2,%3}, [%4];"
        : "=r"(r[0]), "=r"(r[1]), "=r"(r[2]), "=r"(r[3]) : "r"(addr));
}

__device__ __forceinline__ void mma16816(float* d, const uint32_t* a, const uint32_t* b) {
    asm volatile(
        "mma.sync.aligned.m16n8k16.row.col.f32.bf16.bf16.f32 "
        "{%0,%1,%2,%3}, {%4,%5,%6,%7}, {%8,%9}, {%0,%1,%2,%3};"
        : "+f"(d[0]), "+f"(d[1]), "+f"(d[2]), "+f"(d[3])
        : "r"(a[0]), "r"(a[1]), "r"(a[2]), "r"(a[3]), "r"(b[0]), "r"(b[1]));
}

// split fp32 x4 -> bf16 hi x4 + bf16 lo x4 (each packed as uint2)
__device__ __forceinline__ void split4(float4 x, uint2& hi, uint2& lo) {
    __nv_bfloat162 h0 = __float22bfloat162_rn(make_float2(x.x, x.y));
    __nv_bfloat162 h1 = __float22bfloat162_rn(make_float2(x.z, x.w));
    float2 f0 = __bfloat1622float2(h0);
    float2 f1 = __bfloat1622float2(h1);
    __nv_bfloat162 l0 = __float22bfloat162_rn(make_float2(x.x - f0.x, x.y - f0.y));
    __nv_bfloat162 l1 = __float22bfloat162_rn(make_float2(x.z - f1.x, x.w - f1.y));
    hi.x = *reinterpret_cast<uint32_t*>(&h0);
    hi.y = *reinterpret_cast<uint32_t*>(&h1);
    lo.x = *reinterpret_cast<uint32_t*>(&l0);
    lo.y = *reinterpret_cast<uint32_t*>(&l1);
}

// SMEM tile geometry: K-chunk 32 bf16 per row = 64B + 16B pad = 80B rows.
// Components per stage: A_hi, A_lo, B_hi, B_lo, each 128 rows x 80B.
#define ROWB 80
#define TILE_COMP (128 * ROWB)        // 10240
#define STAGE_BYTES (4 * TILE_COMP)   // 40960
#define SMEM_BYTES (2 * STAGE_BYTES)  // 81920

// ---------------------------------------------------------------------------
// Unified NT GEMM: C[M,N] = A[M,K] * B[N,K]^T (+epilogue), bf16x3 mma.sync.
// CTA tile 128x128, K-chunk 32. 256 threads, 8 warps (2x4), warp tile 64x32.
// grid: x = N/128, y = M/128, z = batch.
// EPI: 0 none, 1 +bias[row], 2 +bias[col], 3 gamma*acc + resid.
// ---------------------------------------------------------------------------
template <int EPI>
__global__ __launch_bounds__(256) void gemm_mma(
    const float* __restrict__ A, long long lda, long long a_bs,
    const float* __restrict__ B, long long ldb, long long b_bs,
    float* __restrict__ C, long long ldc, long long c_bs,
    const float* __restrict__ bias,
    const float* __restrict__ resid, long long r_bs,
    const float* __restrict__ gamma,
    int nchunks)
{
    extern __shared__ char smem[];
    const int tid = threadIdx.x;
    const int wid = tid >> 5;
    const int lane = tid & 31;

    const size_t m0 = (size_t)blockIdx.y * 128;
    const size_t n0 = (size_t)blockIdx.x * 128;
    const size_t z = blockIdx.z;
    A += z * a_bs;
    B += z * b_bs;
    C += z * c_bs;

    // Global load mapping: thread -> (row, 16-col half)
    const int lr = tid >> 1;
    const int lh = tid & 1;
    const float* Ap = A + (m0 + lr) * (size_t)lda + lh * 16;
    const float* Bp = B + (n0 + lr) * (size_t)ldb + lh * 16;
    const int soff = lr * ROWB + lh * 32;

    // Warp tile origin
    const int wm = (wid >> 2) * 64;
    const int wn = (wid & 3) * 32;
    const uint32_t sb = smem_to_u32(smem);

    float acc[4][4][4];
#pragma unroll
    for (int i = 0; i < 4; i++)
#pragma unroll
        for (int j = 0; j < 4; j++)
#pragma unroll
            for (int k = 0; k < 4; k++) acc[i][j][k] = 0.f;

    float4 ra[4], rb4[4];
    auto gload = [&](int kc) {
#pragma unroll
        for (int j = 0; j < 4; j++) {
            ra[j]  = *(const float4*)(Ap + (size_t)kc * 32 + j * 4);
            rb4[j] = *(const float4*)(Bp + (size_t)kc * 32 + j * 4);
        }
    };
    auto sstore = [&](int s) {
        char* st = smem + s * STAGE_BYTES;
#pragma unroll
        for (int j = 0; j < 4; j++) {
            uint2 hi, lo;
            split4(ra[j], hi, lo);
            *(uint2*)(st + soff + j * 8) = hi;
            *(uint2*)(st + TILE_COMP + soff + j * 8) = lo;
            split4(rb4[j], hi, lo);
            *(uint2*)(st + 2 * TILE_COMP + soff + j * 8) = hi;
            *(uint2*)(st + 3 * TILE_COMP + soff + j * 8) = lo;
        }
    };

    // ldmatrix lane addressing components
    const uint32_t lrow16 = lane & 15;
    const uint32_t lcol16 = (lane >> 4) * 16;

    gload(0);
    sstore(0);
    __syncthreads();

    for (int i = 0; i < nchunks; i++) {
        const int s = i & 1;
        if (i + 1 < nchunks) gload(i + 1);

        const uint32_t st = sb + s * STAGE_BYTES;
#pragma unroll
        for (int kk = 0; kk < 2; kk++) {
            const uint32_t kb = kk * 32 + lcol16;
            uint32_t Ahi[4][4], Alo[4][4];
#pragma unroll
            for (int mt = 0; mt < 4; mt++) {
                uint32_t ad = st + (wm + mt * 16 + lrow16) * ROWB + kb;
                ldsm_x4(ad, Ahi[mt]);
                ldsm_x4(ad + TILE_COMP, Alo[mt]);
            }
            uint32_t Bhi[4][2], Blo[4][2];
#pragma unroll
            for (int p = 0; p < 2; p++) {
                uint32_t bd = st + 2 * TILE_COMP + (wn + p * 16 + lrow16) * ROWB + kb;
                uint32_t t[4];
                ldsm_x4(bd, t);
                Bhi[2 * p][0] = t[0]; Bhi[2 * p][1] = t[2];
                Bhi[2 * p + 1][0] = t[1]; Bhi[2 * p + 1][1] = t[3];
                ldsm_x4(bd + TILE_COMP, t);
                Blo[2 * p][0] = t[0]; Blo[2 * p][1] = t[2];
                Blo[2 * p + 1][0] = t[1]; Blo[2 * p + 1][1] = t[3];
            }
#pragma unroll
            for (int mt = 0; mt < 4; mt++)
#pragma unroll
                for (int nt = 0; nt < 4; nt++) {
                    mma16816(acc[mt][nt], Ahi[mt], Bhi[nt]);
                    mma16816(acc[mt][nt], Ahi[mt], Blo[nt]);
                    mma16816(acc[mt][nt], Alo[mt], Bhi[nt]);
                }
        }
        __syncthreads();
        if (i + 1 < nchunks) {
            sstore((i + 1) & 1);
            __syncthreads();
        }
    }

    // Epilogue
    const int er = lane >> 2;
    const int ec = (lane & 3) * 2;
    const float g = (EPI == 3) ? __ldg(gamma) : 0.f;
    const float* rz = (EPI == 3) ? (resid + z * r_bs) : (const float*)nullptr;
#pragma unroll
    for (int mt = 0; mt < 4; mt++) {
#pragma unroll
        for (int half = 0; half < 2; half++) {
            const size_t row = m0 + wm + mt * 16 + er + half * 8;
            float rowbias = 0.f;
            if (EPI == 1) rowbias = bias[row];
#pragma unroll
            for (int nt = 0; nt < 4; nt++) {
                const size_t col = n0 + wn + nt * 8 + ec;
                float2 v2;
                v2.x = acc[mt][nt][half * 2 + 0];
                v2.y = acc[mt][nt][half * 2 + 1];
                if (EPI == 1) { v2.x += rowbias; v2.y += rowbias; }
                if (EPI == 2) { v2.x += bias[col]; v2.y += bias[col + 1]; }
                if (EPI == 3) {
                    const float2 rv = *(const float2*)(rz + row * (size_t)ldc + col);
                    v2.x = fmaf(g, v2.x, rv.x);
                    v2.y = fmaf(g, v2.y, rv.y);
                }
                *(float2*)(C + row * (size_t)ldc + col) = v2;
            }
        }
    }
}

// ---------------------------------------------------------------------------
// Column softmax on attnT: softmax over w (rows) for each (batch, v column).
// block (32,16), grid (VDIM/32, BATCH).
// ---------------------------------------------------------------------------
__global__ __launch_bounds__(512) void softmax_col(float* __restrict__ attnT)
{
    __shared__ float red[16][33];
    const int tx = threadIdx.x, ty = threadIdx.y;
    const size_t base = (size_t)blockIdx.y * VDIM * VDIM + (size_t)blockIdx.x * 32 + tx;

    float vals[64];
    float m = -INFINITY;
#pragma unroll
    for (int k = 0; k < 64; k++) {
        vals[k] = attnT[base + (size_t)(ty + 16 * k) * VDIM];
        m = fmaxf(m, vals[k]);
    }
    red[ty][tx] = m;
    __syncthreads();
#pragma unroll
    for (int off = 8; off >= 1; off >>= 1) {
        if (ty < off) red[ty][tx] = fmaxf(red[ty][tx], red[ty + off][tx]);
        __syncthreads();
    }
    m = red[0][tx];
    __syncthreads();

    float s = 0.f;
#pragma unroll
    for (int k = 0; k < 64; k++) {
        vals[k] = __expf(vals[k] - m);
        s += vals[k];
    }
    red[ty][tx] = s;
    __syncthreads();
#pragma unroll
    for (int off = 8; off >= 1; off >>= 1) {
        if (ty < off) red[ty][tx] += red[ty + off][tx];
        __syncthreads();
    }
    const float inv = 1.0f / red[0][tx];

#pragma unroll
    for (int k = 0; k < 64; k++)
        attnT[base + (size_t)(ty + 16 * k) * VDIM] = vals[k] * inv;
}

// ---------------------------------------------------------------------------
extern "C" void kernel_launch(void* const* d_in, const int* in_sizes, int n_in,
                              void* d_out, int out_size)
{
    const float* input = (const float*)d_in[0];
    const float* Wq    = (const float*)d_in[1];
    const float* bq    = (const float*)d_in[2];
    const float* Wk    = (const float*)d_in[3];
    const float* bk    = (const float*)d_in[4];
    const float* Wv    = (const float*)d_in[5];
    const float* bv    = (const float*)d_in[6];
    const float* gamma = (const float*)d_in[7];
    float* out = (float*)d_out;

    float *qp, *kp, *vp, *ap;
    cudaGetSymbolAddress((void**)&qp, g_qT);
    cudaGetSymbolAddress((void**)&kp, g_kT);
    cudaGetSymbolAddress((void**)&vp, g_v);
    cudaGetSymbolAddress((void**)&ap, g_attnT);

    cudaFuncSetAttribute(gemm_mma<0>, cudaFuncAttributeMaxDynamicSharedMemorySize, SMEM_BYTES);
    cudaFuncSetAttribute(gemm_mma<1>, cudaFuncAttributeMaxDynamicSharedMemorySize, SMEM_BYTES);
    cudaFuncSetAttribute(gemm_mma<2>, cudaFuncAttributeMaxDynamicSharedMemorySize, SMEM_BYTES);
    cudaFuncSetAttribute(gemm_mma<3>, cudaFuncAttributeMaxDynamicSharedMemorySize, SMEM_BYTES);

    const long long MN = (long long)BATCH * SEQ;   // 32768
    const long long BSEQ = (long long)SEQ * VDIM;  // 4194304
    const long long AT = (long long)VDIM * VDIM;   // 1048576

    // qT[w, n] = sum_e Wq[w,e] * input[n, 768+e]   (M=1024, N=32768, K=256)
    gemm_mma<1><<<dim3(256, 8, 1), 256, SMEM_BYTES>>>(
        Wq, KQDIM, 0, input + (VDIM - KQDIM), VDIM, 0, qp, MN, 0,
        bq, nullptr, 0, nullptr, KQDIM / 32);
    // kT[v, n]
    gemm_mma<1><<<dim3(256, 8, 1), 256, SMEM_BYTES>>>(
        Wk, KQDIM, 0, input + (VDIM - KQDIM), VDIM, 0, kp, MN, 0,
        bk, nullptr, 0, nullptr, KQDIM / 32);
    // v[n, w] = sum_e input[n,e] * Wv[w,e]         (M=32768, N=1024, K=1024)
    gemm_mma<2><<<dim3(8, 256, 1), 256, SMEM_BYTES>>>(
        input, VDIM, 0, Wv, VDIM, 0, vp, VDIM, 0,
        bv, nullptr, 0, nullptr, VDIM / 32);
    // attnT[b][w, v] = sum_n qT[w, bn] * kT[v, bn] (per batch: M=N=1024, K=4096)
    gemm_mma<0><<<dim3(8, 8, 8), 256, SMEM_BYTES>>>(
        qp, MN, SEQ, kp, MN, SEQ, ap, VDIM, AT,
        nullptr, nullptr, 0, nullptr, SEQ / 32);
    // softmax over w (rows of attnT) for each column v
    softmax_col<<<dim3(VDIM / 32, BATCH), dim3(32, 16)>>>(ap);
    // out[b][n, w] = gamma * sum_v v[bn, v] * attnT[b][w, v] + input
    gemm_mma<3><<<dim3(8, 32, 8), 256, SMEM_BYTES>>>(
        vp, VDIM, BSEQ, ap, VDIM, AT, out, VDIM, BSEQ,
        nullptr, input, BSEQ, gamma, VDIM / 32);
}

// round 4
// speedup vs baseline: 2.0589x; 1.2125x over previous
#include <cuda_runtime.h>
#include <cuda_bf16.h>
#include <cstdint>
#include <math.h>

// Problem constants
#define BATCH 8
#define SEQ   4096
#define VDIM  1024
#define KQDIM 256

typedef __nv_bfloat16 bf16;

// ---------------------------------------------------------------------------
// Scratch (device globals; no runtime allocation allowed)
// ---------------------------------------------------------------------------
__device__ bf16 g_in_hi[(size_t)BATCH * SEQ * VDIM];
__device__ bf16 g_in_lo[(size_t)BATCH * SEQ * VDIM];
__device__ bf16 g_wq_hi[(size_t)VDIM * KQDIM];
__device__ bf16 g_wq_lo[(size_t)VDIM * KQDIM];
__device__ bf16 g_wk_hi[(size_t)VDIM * KQDIM];
__device__ bf16 g_wk_lo[(size_t)VDIM * KQDIM];
__device__ bf16 g_wv_hi[(size_t)VDIM * VDIM];
__device__ bf16 g_wv_lo[(size_t)VDIM * VDIM];
__device__ bf16 g_qT_hi[(size_t)VDIM * BATCH * SEQ];   // [1024 w][32768 n]
__device__ bf16 g_qT_lo[(size_t)VDIM * BATCH * SEQ];
__device__ bf16 g_kT_hi[(size_t)VDIM * BATCH * SEQ];
__device__ bf16 g_kT_lo[(size_t)VDIM * BATCH * SEQ];
__device__ bf16 g_v_hi[(size_t)BATCH * SEQ * VDIM];    // [32768 n][1024 v]
__device__ bf16 g_v_lo[(size_t)BATCH * SEQ * VDIM];
__device__ float g_attnT[(size_t)BATCH * VDIM * VDIM]; // [8][1024 w][1024 v]
__device__ bf16 g_att_hi[(size_t)BATCH * VDIM * VDIM];
__device__ bf16 g_att_lo[(size_t)BATCH * VDIM * VDIM];

// ---------------------------------------------------------------------------
// Helpers
// ---------------------------------------------------------------------------
__device__ __forceinline__ uint32_t smem_to_u32(const void* p) {
    uint32_t a;
    asm("{ .reg .u64 t; cvta.to.shared.u64 t, %1; cvt.u32.u64 %0, t; }"
        : "=r"(a) : "l"(p));
    return a;
}

__device__ __forceinline__ void ldsm_x4(uint32_t addr, uint32_t* r) {
    asm volatile("ldmatrix.sync.aligned.m8n8.x4.shared.b16 {%0,%1,%2,%3}, [%4];"
        : "=r"(r[0]), "=r"(r[1]), "=r"(r[2]), "=r"(r[3]) : "r"(addr));
}

__device__ __forceinline__ void mma16816(float* d, const uint32_t* a, const uint32_t* b) {
    asm volatile(
        "mma.sync.aligned.m16n8k16.row.col.f32.bf16.bf16.f32 "
        "{%0,%1,%2,%3}, {%4,%5,%6,%7}, {%8,%9}, {%0,%1,%2,%3};"
        : "+f"(d[0]), "+f"(d[1]), "+f"(d[2]), "+f"(d[3])
        : "r"(a[0]), "r"(a[1]), "r"(a[2]), "r"(a[3]), "r"(b[0]), "r"(b[1]));
}

#define CP_ASYNC16(s, g) \
    asm volatile("cp.async.cg.shared.global [%0], [%1], 16;" :: "r"(s), "l"(g))
#define CP_COMMIT() asm volatile("cp.async.commit_group;" ::: "memory")
#define CP_WAIT(n)  asm volatile("cp.async.wait_group %0;" :: "n"(n) : "memory")

__device__ __forceinline__ void split2(float x, float y, bf16& hx, bf16& hy,
                                       bf16& lx, bf16& ly) {
    hx = __float2bfloat16_rn(x);
    hy = __float2bfloat16_rn(y);
    lx = __float2bfloat16_rn(x - __bfloat162float(hx));
    ly = __float2bfloat16_rn(y - __bfloat162float(hy));
}

// SMEM tile geometry: K-chunk 32 bf16 = 64B + 16B pad = 80B rows.
// Per stage: A_hi, A_lo, B_hi, B_lo, each 128 rows x 80B.
#define ROWB 80
#define TILE_COMP (128 * ROWB)        // 10240
#define STAGE_BYTES (4 * TILE_COMP)   // 40960
#define PIPE 4
#define SMEM_BYTES (PIPE * STAGE_BYTES)  // 163840

// ---------------------------------------------------------------------------
// Unified NT GEMM: C = A * B^T where A, B are bf16 hi/lo pairs, K-major.
// CTA tile 128x128, K-chunk 32, cp.async 4-stage pipeline, 256 threads.
// bf16x3: acc += Ahi*Bhi + Ahi*Blo + Alo*Bhi (fp32 accum).
// EPI: 1 = +bias[row], write bf16 hi/lo (q/k projections)
//      2 = +bias[col], write bf16 hi/lo (v projection)
//      0 = write fp32 (attn scores)
//      3 = gamma*acc + resid, write fp32 (output)
// ---------------------------------------------------------------------------
template <int EPI>
__global__ __launch_bounds__(256) void gemm_bf(
    const bf16* __restrict__ Ahi, const bf16* __restrict__ Alo,
    long long lda, long long a_bs,
    const bf16* __restrict__ Bhi, const bf16* __restrict__ Blo,
    long long ldb, long long b_bs,
    float* __restrict__ Cf, bf16* __restrict__ Chi, bf16* __restrict__ Clo,
    long long ldc, long long c_bs,
    const float* __restrict__ bias,
    const float* __restrict__ resid,
    const float* __restrict__ gamma,
    int nchunks)
{
    extern __shared__ char smem[];
    const int tid = threadIdx.x;
    const int wid = tid >> 5;
    const int lane = tid & 31;

    const size_t m0 = (size_t)blockIdx.y * 128;
    const size_t n0 = (size_t)blockIdx.x * 128;
    const size_t z = blockIdx.z;
    Ahi += z * a_bs; Alo += z * a_bs;
    Bhi += z * b_bs; Blo += z * b_bs;

    // cp.async mapping: seg = tid&3 (16B = 8 bf16), rows tid>>2 and (tid>>2)+64
    const int seg = tid & 3;
    const int hr = tid >> 2;
    const uint32_t sb = smem_to_u32(smem);
    const uint32_t so0 = hr * ROWB + seg * 16;
    const uint32_t so1 = (hr + 64) * ROWB + seg * 16;

    const bf16* Ah0 = Ahi + (m0 + hr) * (size_t)lda + seg * 8;
    const bf16* Ah1 = Ahi + (m0 + hr + 64) * (size_t)lda + seg * 8;
    const bf16* Al0 = Alo + (m0 + hr) * (size_t)lda + seg * 8;
    const bf16* Al1 = Alo + (m0 + hr + 64) * (size_t)lda + seg * 8;
    const bf16* Bh0 = Bhi + (n0 + hr) * (size_t)ldb + seg * 8;
    const bf16* Bh1 = Bhi + (n0 + hr + 64) * (size_t)ldb + seg * 8;
    const bf16* Bl0 = Blo + (n0 + hr) * (size_t)ldb + seg * 8;
    const bf16* Bl1 = Blo + (n0 + hr + 64) * (size_t)ldb + seg * 8;

    auto load_stage = [&](int kc, int s) {
        const uint32_t st = sb + s * STAGE_BYTES;
        const size_t ko = (size_t)kc * 32;
        CP_ASYNC16(st + so0,                 Ah0 + ko);
        CP_ASYNC16(st + so1,                 Ah1 + ko);
        CP_ASYNC16(st + TILE_COMP + so0,     Al0 + ko);
        CP_ASYNC16(st + TILE_COMP + so1,     Al1 + ko);
        CP_ASYNC16(st + 2 * TILE_COMP + so0, Bh0 + ko);
        CP_ASYNC16(st + 2 * TILE_COMP + so1, Bh1 + ko);
        CP_ASYNC16(st + 3 * TILE_COMP + so0, Bl0 + ko);
        CP_ASYNC16(st + 3 * TILE_COMP + so1, Bl1 + ko);
        CP_COMMIT();
    };

    // Warp tile origin (8 warps: 2 x 4)
    const int wm = (wid >> 2) * 64;
    const int wn = (wid & 3) * 32;

    float acc[4][4][4];
#pragma unroll
    for (int i = 0; i < 4; i++)
#pragma unroll
        for (int j = 0; j < 4; j++)
#pragma unroll
            for (int k = 0; k < 4; k++) acc[i][j][k] = 0.f;

    // ldmatrix lane addressing
    const uint32_t lrow16 = lane & 15;
    const uint32_t lcol16 = (lane >> 4) * 16;

    // Prologue: fill PIPE-1 stages
#pragma unroll
    for (int s = 0; s < PIPE - 1; s++) load_stage(s, s);

    for (int i = 0; i < nchunks; i++) {
        CP_WAIT(PIPE - 2);
        __syncthreads();

        const uint32_t st = sb + (i % PIPE) * STAGE_BYTES;
#pragma unroll
        for (int kk = 0; kk < 2; kk++) {
            const uint32_t kb = kk * 32 + lcol16;
            uint32_t Afh[4][4], Afl[4][4];
#pragma unroll
            for (int mt = 0; mt < 4; mt++) {
                uint32_t ad = st + (wm + mt * 16 + lrow16) * ROWB + kb;
                ldsm_x4(ad, Afh[mt]);
                ldsm_x4(ad + TILE_COMP, Afl[mt]);
            }
            uint32_t Bfh[4][2], Bfl[4][2];
#pragma unroll
            for (int p = 0; p < 2; p++) {
                uint32_t bd = st + 2 * TILE_COMP + (wn + p * 16 + lrow16) * ROWB + kb;
                uint32_t t[4];
                ldsm_x4(bd, t);
                Bfh[2 * p][0] = t[0]; Bfh[2 * p][1] = t[2];
                Bfh[2 * p + 1][0] = t[1]; Bfh[2 * p + 1][1] = t[3];
                ldsm_x4(bd + TILE_COMP, t);
                Bfl[2 * p][0] = t[0]; Bfl[2 * p][1] = t[2];
                Bfl[2 * p + 1][0] = t[1]; Bfl[2 * p + 1][1] = t[3];
            }
#pragma unroll
            for (int mt = 0; mt < 4; mt++)
#pragma unroll
                for (int nt = 0; nt < 4; nt++) {
                    mma16816(acc[mt][nt], Afh[mt], Bfh[nt]);
                    mma16816(acc[mt][nt], Afh[mt], Bfl[nt]);
                    mma16816(acc[mt][nt], Afl[mt], Bfh[nt]);
                }
        }
        __syncthreads();
        if (i + PIPE - 1 < nchunks) load_stage(i + PIPE - 1, (i + PIPE - 1) % PIPE);
    }

    // Epilogue
    const int er = lane >> 2;
    const int ec = (lane & 3) * 2;
    const float g = (EPI == 3) ? __ldg(gamma) : 0.f;
    const float* rz = (EPI == 3) ? (resid + z * c_bs) : (const float*)nullptr;
    float* Cfz = (EPI == 0 || EPI == 3) ? (Cf + z * c_bs) : nullptr;
#pragma unroll
    for (int mt = 0; mt < 4; mt++) {
#pragma unroll
        for (int half = 0; half < 2; half++) {
            const size_t row = m0 + wm + mt * 16 + er + half * 8;
            float rowbias = 0.f;
            if (EPI == 1) rowbias = bias[row];
#pragma unroll
            for (int nt = 0; nt < 4; nt++) {
                const size_t col = n0 + wn + nt * 8 + ec;
                float vx = acc[mt][nt][half * 2 + 0];
                float vy = acc[mt][nt][half * 2 + 1];
                if (EPI == 1) { vx += rowbias; vy += rowbias; }
                if (EPI == 2) { vx += bias[col]; vy += bias[col + 1]; }
                if (EPI == 3) {
                    const float2 rv = *(const float2*)(rz + row * (size_t)ldc + col);
                    vx = fmaf(g, vx, rv.x);
                    vy = fmaf(g, vy, rv.y);
                }
                if (EPI == 0 || EPI == 3) {
                    float2 o = make_float2(vx, vy);
                    *(float2*)(Cfz + row * (size_t)ldc + col) = o;
                } else {
                    bf16 hx, hy, lx, ly;
                    split2(vx, vy, hx, hy, lx, ly);
                    __nv_bfloat162 h2(hx, hy), l2(lx, ly);
                    *(__nv_bfloat162*)(Chi + row * (size_t)ldc + col) = h2;
                    *(__nv_bfloat162*)(Clo + row * (size_t)ldc + col) = l2;
                }
            }
        }
    }
}

// ---------------------------------------------------------------------------
// Convert fp32 array -> bf16 hi/lo pair. Grid-stride, float4 granularity.
// ---------------------------------------------------------------------------
__global__ void convert_hilo(const float* __restrict__ x,
                             bf16* __restrict__ hi, bf16* __restrict__ lo,
                             size_t n4)
{
    for (size_t i = blockIdx.x * (size_t)blockDim.x + threadIdx.x; i < n4;
         i += (size_t)gridDim.x * blockDim.x) {
        float4 v = ((const float4*)x)[i];
        bf16 h0, h1, h2, h3, l0, l1, l2, l3;
        split2(v.x, v.y, h0, h1, l0, l1);
        split2(v.z, v.w, h2, h3, l2, l3);
        __nv_bfloat162 ha(h0, h1), hb(h2, h3), la(l0, l1), lb(l2, l3);
        ((__nv_bfloat162*)hi)[2 * i] = ha;
        ((__nv_bfloat162*)hi)[2 * i + 1] = hb;
        ((__nv_bfloat162*)lo)[2 * i] = la;
        ((__nv_bfloat162*)lo)[2 * i + 1] = lb;
    }
}

// ---------------------------------------------------------------------------
// Column softmax on attnT (softmax over w rows per (batch, v) column),
// writing bf16 hi/lo. block (32,16), grid (VDIM/32, BATCH).
// ---------------------------------------------------------------------------
__global__ __launch_bounds__(512) void softmax_col(
    const float* __restrict__ attnT,
    bf16* __restrict__ out_hi, bf16* __restrict__ out_lo)
{
    __shared__ float red[16][33];
    const int tx = threadIdx.x, ty = threadIdx.y;
    const size_t base = (size_t)blockIdx.y * VDIM * VDIM + (size_t)blockIdx.x * 32 + tx;

    float vals[64];
    float m = -INFINITY;
#pragma unroll
    for (int k = 0; k < 64; k++) {
        vals[k] = attnT[base + (size_t)(ty + 16 * k) * VDIM];
        m = fmaxf(m, vals[k]);
    }
    red[ty][tx] = m;
    __syncthreads();
#pragma unroll
    for (int off = 8; off >= 1; off >>= 1) {
        if (ty < off) red[ty][tx] = fmaxf(red[ty][tx], red[ty + off][tx]);
        __syncthreads();
    }
    m = red[0][tx];
    __syncthreads();

    float s = 0.f;
#pragma unroll
    for (int k = 0; k < 64; k++) {
        vals[k] = __expf(vals[k] - m);
        s += vals[k];
    }
    red[ty][tx] = s;
    __syncthreads();
#pragma unroll
    for (int off = 8; off >= 1; off >>= 1) {
        if (ty < off) red[ty][tx] += red[ty + off][tx];
        __syncthreads();
    }
    const float inv = 1.0f / red[0][tx];

#pragma unroll
    for (int k = 0; k < 64; k++) {
        const float v = vals[k] * inv;
        const size_t idx = base + (size_t)(ty + 16 * k) * VDIM;
        bf16 h = __float2bfloat16_rn(v);
        bf16 l = __float2bfloat16_rn(v - __bfloat162float(h));
        out_hi[idx] = h;
        out_lo[idx] = l;
    }
}

// ---------------------------------------------------------------------------
extern "C" void kernel_launch(void* const* d_in, const int* in_sizes, int n_in,
                              void* d_out, int out_size)
{
    const float* input = (const float*)d_in[0];
    const float* Wq    = (const float*)d_in[1];
    const float* bq    = (const float*)d_in[2];
    const float* Wk    = (const float*)d_in[3];
    const float* bk    = (const float*)d_in[4];
    const float* Wv    = (const float*)d_in[5];
    const float* bv    = (const float*)d_in[6];
    const float* gamma = (const float*)d_in[7];
    float* out = (float*)d_out;

    bf16 *in_hi, *in_lo, *wq_hi, *wq_lo, *wk_hi, *wk_lo, *wv_hi, *wv_lo;
    bf16 *qT_hi, *qT_lo, *kT_hi, *kT_lo, *v_hi, *v_lo, *att_hi, *att_lo;
    float* attnT;
    cudaGetSymbolAddress((void**)&in_hi, g_in_hi);
    cudaGetSymbolAddress((void**)&in_lo, g_in_lo);
    cudaGetSymbolAddress((void**)&wq_hi, g_wq_hi);
    cudaGetSymbolAddress((void**)&wq_lo, g_wq_lo);
    cudaGetSymbolAddress((void**)&wk_hi, g_wk_hi);
    cudaGetSymbolAddress((void**)&wk_lo, g_wk_lo);
    cudaGetSymbolAddress((void**)&wv_hi, g_wv_hi);
    cudaGetSymbolAddress((void**)&wv_lo, g_wv_lo);
    cudaGetSymbolAddress((void**)&qT_hi, g_qT_hi);
    cudaGetSymbolAddress((void**)&qT_lo, g_qT_lo);
    cudaGetSymbolAddress((void**)&kT_hi, g_kT_hi);
    cudaGetSymbolAddress((void**)&kT_lo, g_kT_lo);
    cudaGetSymbolAddress((void**)&v_hi, g_v_hi);
    cudaGetSymbolAddress((void**)&v_lo, g_v_lo);
    cudaGetSymbolAddress((void**)&att_hi, g_att_hi);
    cudaGetSymbolAddress((void**)&att_lo, g_att_lo);
    cudaGetSymbolAddress((void**)&attnT, g_attnT);

    cudaFuncSetAttribute(gemm_bf<0>, cudaFuncAttributeMaxDynamicSharedMemorySize, SMEM_BYTES);
    cudaFuncSetAttribute(gemm_bf<1>, cudaFuncAttributeMaxDynamicSharedMemorySize, SMEM_BYTES);
    cudaFuncSetAttribute(gemm_bf<2>, cudaFuncAttributeMaxDynamicSharedMemorySize, SMEM_BYTES);
    cudaFuncSetAttribute(gemm_bf<3>, cudaFuncAttributeMaxDynamicSharedMemorySize, SMEM_BYTES);

    const long long MN = (long long)BATCH * SEQ;   // 32768
    const long long BSEQ = (long long)SEQ * VDIM;  // 4194304
    const long long AT = (long long)VDIM * VDIM;   // 1048576

    // Convert inputs to bf16 hi/lo
    convert_hilo<<<2048, 256>>>(input, in_hi, in_lo, (size_t)MN * VDIM / 4);
    convert_hilo<<<64, 256>>>(Wq, wq_hi, wq_lo, (size_t)VDIM * KQDIM / 4);
    convert_hilo<<<64, 256>>>(Wk, wk_hi, wk_lo, (size_t)VDIM * KQDIM / 4);
    convert_hilo<<<256, 256>>>(Wv, wv_hi, wv_lo, (size_t)VDIM * VDIM / 4);

    // qT[w, n] = sum_e Wq[w,e] * input[n, 768+e]  (M=1024, N=32768, K=256)
    gemm_bf<1><<<dim3(256, 8, 1), 256, SMEM_BYTES>>>(
        wq_hi, wq_lo, KQDIM, 0,
        in_hi + (VDIM - KQDIM), in_lo + (VDIM - KQDIM), VDIM, 0,
        nullptr, qT_hi, qT_lo, MN, 0, bq, nullptr, nullptr, KQDIM / 32);
    // kT[v, n]
    gemm_bf<1><<<dim3(256, 8, 1), 256, SMEM_BYTES>>>(
        wk_hi, wk_lo, KQDIM, 0,
        in_hi + (VDIM - KQDIM), in_lo + (VDIM - KQDIM), VDIM, 0,
        nullptr, kT_hi, kT_lo, MN, 0, bk, nullptr, nullptr, KQDIM / 32);
    // v[n, w] = sum_e input[n,e] * Wv[w,e]  (M=32768, N=1024, K=1024)
    gemm_bf<2><<<dim3(8, 256, 1), 256, SMEM_BYTES>>>(
        in_hi, in_lo, VDIM, 0,
        wv_hi, wv_lo, VDIM, 0,
        nullptr, v_hi, v_lo, VDIM, 0, bv, nullptr, nullptr, VDIM / 32);
    // attnT[b][w, v] = sum_n qT[w, bn] * kT[v, bn]  (per batch M=N=1024, K=4096)
    gemm_bf<0><<<dim3(8, 8, 8), 256, SMEM_BYTES>>>(
        qT_hi, qT_lo, MN, SEQ,
        kT_hi, kT_lo, MN, SEQ,
        attnT, nullptr, nullptr, VDIM, AT, nullptr, nullptr, nullptr, SEQ / 32);
    // softmax over w; emit bf16 hi/lo
    softmax_col<<<dim3(VDIM / 32, BATCH), dim3(32, 16)>>>(attnT, att_hi, att_lo);
    // out[b][n, w] = gamma * sum_v v[bn, v] * attT[b][w, v] + input
    gemm_bf<3><<<dim3(8, 32, 8), 256, SMEM_BYTES>>>(
        v_hi, v_lo, VDIM, BSEQ,
        att_hi, att_lo, VDIM, AT,
        out, nullptr, nullptr, VDIM, BSEQ, nullptr, input, gamma, VDIM / 32);
}

// round 5
// speedup vs baseline: 2.2130x; 1.0749x over previous
#include <cuda_runtime.h>
#include <cuda_bf16.h>
#include <cstdint>
#include <math.h>

// Problem constants
#define BATCH 8
#define SEQ   4096
#define VDIM  1024
#define KQDIM 256

typedef __nv_bfloat16 bf16;

// ---------------------------------------------------------------------------
// Scratch (device globals; no runtime allocation allowed)
// ---------------------------------------------------------------------------
__device__ bf16 g_in_hi[(size_t)BATCH * SEQ * VDIM];
__device__ bf16 g_in_lo[(size_t)BATCH * SEQ * VDIM];
__device__ bf16 g_wq_hi[(size_t)VDIM * KQDIM];
__device__ bf16 g_wq_lo[(size_t)VDIM * KQDIM];
__device__ bf16 g_wk_hi[(size_t)VDIM * KQDIM];
__device__ bf16 g_wk_lo[(size_t)VDIM * KQDIM];
__device__ bf16 g_wv_hi[(size_t)VDIM * VDIM];
__device__ bf16 g_wv_lo[(size_t)VDIM * VDIM];
__device__ bf16 g_qT_hi[(size_t)VDIM * BATCH * SEQ];   // [1024 w][32768 n]
__device__ bf16 g_qT_lo[(size_t)VDIM * BATCH * SEQ];
__device__ bf16 g_kT_hi[(size_t)VDIM * BATCH * SEQ];
__device__ bf16 g_kT_lo[(size_t)VDIM * BATCH * SEQ];
__device__ bf16 g_v_hi[(size_t)BATCH * SEQ * VDIM];    // [32768 n][1024 v]
__device__ bf16 g_v_lo[(size_t)BATCH * SEQ * VDIM];
__device__ float g_attnT[(size_t)BATCH * VDIM * VDIM]; // [8][1024 w][1024 v]
__device__ bf16 g_att_hi[(size_t)BATCH * VDIM * VDIM];
__device__ bf16 g_att_lo[(size_t)BATCH * VDIM * VDIM];

// ---------------------------------------------------------------------------
// Helpers
// ---------------------------------------------------------------------------
__device__ __forceinline__ uint32_t smem_to_u32(const void* p) {
    uint32_t a;
    asm("{ .reg .u64 t; cvta.to.shared.u64 t, %1; cvt.u32.u64 %0, t; }"
        : "=r"(a) : "l"(p));
    return a;
}

__device__ __forceinline__ void ldsm_x4(uint32_t addr, uint32_t* r) {
    asm volatile("ldmatrix.sync.aligned.m8n8.x4.shared.b16 {%0,%1,%2,%3}, [%4];"
        : "=r"(r[0]), "=r"(r[1]), "=r"(r[2]), "=r"(r[3]) : "r"(addr));
}

__device__ __forceinline__ void mma16816(float* d, const uint32_t* a, const uint32_t* b) {
    asm volatile(
        "mma.sync.aligned.m16n8k16.row.col.f32.bf16.bf16.f32 "
        "{%0,%1,%2,%3}, {%4,%5,%6,%7}, {%8,%9}, {%0,%1,%2,%3};"
        : "+f"(d[0]), "+f"(d[1]), "+f"(d[2]), "+f"(d[3])
        : "r"(a[0]), "r"(a[1]), "r"(a[2]), "r"(a[3]), "r"(b[0]), "r"(b[1]));
}

#define CP_ASYNC16(s, g) \
    asm volatile("cp.async.cg.shared.global [%0], [%1], 16;" :: "r"(s), "l"(g))
#define CP_COMMIT() asm volatile("cp.async.commit_group;" ::: "memory")
#define CP_WAIT(n)  asm volatile("cp.async.wait_group %0;" :: "n"(n) : "memory")

__device__ __forceinline__ void split2(float x, float y, bf16& hx, bf16& hy,
                                       bf16& lx, bf16& ly) {
    hx = __float2bfloat16_rn(x);
    hy = __float2bfloat16_rn(y);
    lx = __float2bfloat16_rn(x - __bfloat162float(hx));
    ly = __float2bfloat16_rn(y - __bfloat162float(hy));
}

// SMEM tile geometry: K-chunk 32 bf16 = 64B + 16B pad = 80B rows.
// Per stage: A_hi (256 rows), A_lo (256), B_hi (128), B_lo (128).
#define ROWB 80
#define A_COMP (256 * ROWB)           // 20480
#define B_COMP (128 * ROWB)           // 10240
#define OFF_AHI 0
#define OFF_ALO A_COMP
#define OFF_BHI (2 * A_COMP)
#define OFF_BLO (2 * A_COMP + B_COMP)
#define STAGE_BYTES (2 * A_COMP + 2 * B_COMP)  // 61440
#define PIPE 3
#define SMEM_BYTES (PIPE * STAGE_BYTES)        // 184320

// ---------------------------------------------------------------------------
// Unified NT GEMM: C = A * B^T, A/B bf16 hi/lo pairs, K-major.
// CTA tile 256x128, K-chunk 32, cp.async 3-stage pipeline, 512 threads,
// 16 warps (4x4), warp tile 64x32. bf16x3: AhiBhi + AhiBlo + AloBhi.
// EPI: 1 = +bias[row] -> bf16 hi/lo; 2 = +bias[col] -> bf16 hi/lo;
//      0 = fp32; 3 = gamma*acc + resid -> fp32.
// ---------------------------------------------------------------------------
template <int EPI>
__global__ __launch_bounds__(512) void gemm_bf(
    const bf16* __restrict__ Ahi, const bf16* __restrict__ Alo,
    long long lda, long long a_bs,
    const bf16* __restrict__ Bhi, const bf16* __restrict__ Blo,
    long long ldb, long long b_bs,
    float* __restrict__ Cf, bf16* __restrict__ Chi, bf16* __restrict__ Clo,
    long long ldc, long long c_bs,
    const float* __restrict__ bias,
    const float* __restrict__ resid,
    const float* __restrict__ gamma,
    int nchunks)
{
    extern __shared__ char smem[];
    const int tid = threadIdx.x;
    const int wid = tid >> 5;
    const int lane = tid & 31;

    const size_t m0 = (size_t)blockIdx.y * 256;
    const size_t n0 = (size_t)blockIdx.x * 128;
    const size_t z = blockIdx.z;
    Ahi += z * a_bs; Alo += z * a_bs;
    Bhi += z * b_bs; Blo += z * b_bs;

    // cp.async mapping: seg = tid&3 (16B), r = tid>>2 (0..127)
    const int seg = tid & 3;
    const int r = tid >> 2;
    const uint32_t sb = smem_to_u32(smem);
    const uint32_t sr0 = r * ROWB + seg * 16;
    const uint32_t sr1 = (r + 128) * ROWB + seg * 16;

    const bf16* Ah0 = Ahi + (m0 + r) * (size_t)lda + seg * 8;
    const bf16* Ah1 = Ahi + (m0 + r + 128) * (size_t)lda + seg * 8;
    const bf16* Al0 = Alo + (m0 + r) * (size_t)lda + seg * 8;
    const bf16* Al1 = Alo + (m0 + r + 128) * (size_t)lda + seg * 8;
    const bf16* Bh0 = Bhi + (n0 + r) * (size_t)ldb + seg * 8;
    const bf16* Bl0 = Blo + (n0 + r) * (size_t)ldb + seg * 8;

    auto load_stage = [&](int kc, int s) {
        const uint32_t st = sb + s * STAGE_BYTES;
        const size_t ko = (size_t)kc * 32;
        CP_ASYNC16(st + OFF_AHI + sr0, Ah0 + ko);
        CP_ASYNC16(st + OFF_AHI + sr1, Ah1 + ko);
        CP_ASYNC16(st + OFF_ALO + sr0, Al0 + ko);
        CP_ASYNC16(st + OFF_ALO + sr1, Al1 + ko);
        CP_ASYNC16(st + OFF_BHI + sr0, Bh0 + ko);
        CP_ASYNC16(st + OFF_BLO + sr0, Bl0 + ko);
        CP_COMMIT();
    };

    // Warp tile origin (16 warps: 4 x 4)
    const int wm = (wid >> 2) * 64;
    const int wn = (wid & 3) * 32;

    float acc[4][4][4];
#pragma unroll
    for (int i = 0; i < 4; i++)
#pragma unroll
        for (int j = 0; j < 4; j++)
#pragma unroll
            for (int k = 0; k < 4; k++) acc[i][j][k] = 0.f;

    // ldmatrix lane addressing
    const uint32_t lrow16 = lane & 15;
    const uint32_t lcol16 = (lane >> 4) * 16;

    // Prologue: fill PIPE-1 stages
#pragma unroll
    for (int s = 0; s < PIPE - 1; s++) load_stage(s, s);

    for (int i = 0; i < nchunks; i++) {
        CP_WAIT(PIPE - 2);
        __syncthreads();   // stage i ready AND everyone done reading stage i-1

        if (i + PIPE - 1 < nchunks) load_stage(i + PIPE - 1, (i + PIPE - 1) % PIPE);

        const uint32_t st = sb + (i % PIPE) * STAGE_BYTES;
#pragma unroll
        for (int kk = 0; kk < 2; kk++) {
            const uint32_t kb = kk * 32 + lcol16;
            uint32_t Afh[4][4], Afl[4][4];
#pragma unroll
            for (int mt = 0; mt < 4; mt++) {
                uint32_t ad = st + OFF_AHI + (wm + mt * 16 + lrow16) * ROWB + kb;
                ldsm_x4(ad, Afh[mt]);
                ldsm_x4(ad + A_COMP, Afl[mt]);
            }
            uint32_t Bfh[4][2], Bfl[4][2];
#pragma unroll
            for (int p = 0; p < 2; p++) {
                uint32_t bd = st + OFF_BHI + (wn + p * 16 + lrow16) * ROWB + kb;
                uint32_t t[4];
                ldsm_x4(bd, t);
                Bfh[2 * p][0] = t[0]; Bfh[2 * p][1] = t[2];
                Bfh[2 * p + 1][0] = t[1]; Bfh[2 * p + 1][1] = t[3];
                ldsm_x4(bd + B_COMP, t);
                Bfl[2 * p][0] = t[0]; Bfl[2 * p][1] = t[2];
                Bfl[2 * p + 1][0] = t[1]; Bfl[2 * p + 1][1] = t[3];
            }
#pragma unroll
            for (int mt = 0; mt < 4; mt++)
#pragma unroll
                for (int nt = 0; nt < 4; nt++) {
                    mma16816(acc[mt][nt], Afh[mt], Bfh[nt]);
                    mma16816(acc[mt][nt], Afh[mt], Bfl[nt]);
                    mma16816(acc[mt][nt], Afl[mt], Bfh[nt]);
                }
        }
    }

    // Epilogue
    const int er = lane >> 2;
    const int ec = (lane & 3) * 2;
    const float g = (EPI == 3) ? __ldg(gamma) : 0.f;
    const float* rz = (EPI == 3) ? (resid + z * c_bs) : (const float*)nullptr;
    float* Cfz = (EPI == 0 || EPI == 3) ? (Cf + z * c_bs) : nullptr;
#pragma unroll
    for (int mt = 0; mt < 4; mt++) {
#pragma unroll
        for (int half = 0; half < 2; half++) {
            const size_t row = m0 + wm + mt * 16 + er + half * 8;
            float rowbias = 0.f;
            if (EPI == 1) rowbias = bias[row];
#pragma unroll
            for (int nt = 0; nt < 4; nt++) {
                const size_t col = n0 + wn + nt * 8 + ec;
                float vx = acc[mt][nt][half * 2 + 0];
                float vy = acc[mt][nt][half * 2 + 1];
                if (EPI == 1) { vx += rowbias; vy += rowbias; }
                if (EPI == 2) { vx += bias[col]; vy += bias[col + 1]; }
                if (EPI == 3) {
                    const float2 rv = *(const float2*)(rz + row * (size_t)ldc + col);
                    vx = fmaf(g, vx, rv.x);
                    vy = fmaf(g, vy, rv.y);
                }
                if (EPI == 0 || EPI == 3) {
                    float2 o = make_float2(vx, vy);
                    *(float2*)(Cfz + row * (size_t)ldc + col) = o;
                } else {
                    bf16 hx, hy, lx, ly;
                    split2(vx, vy, hx, hy, lx, ly);
                    __nv_bfloat162 h2(hx, hy), l2(lx, ly);
                    *(__nv_bfloat162*)(Chi + row * (size_t)ldc + col) = h2;
                    *(__nv_bfloat162*)(Clo + row * (size_t)ldc + col) = l2;
                }
            }
        }
    }
}

// ---------------------------------------------------------------------------
// Convert fp32 array -> bf16 hi/lo pair. Grid-stride, float4 granularity.
// ---------------------------------------------------------------------------
__global__ void convert_hilo(const float* __restrict__ x,
                             bf16* __restrict__ hi, bf16* __restrict__ lo,
                             size_t n4)
{
    for (size_t i = blockIdx.x * (size_t)blockDim.x + threadIdx.x; i < n4;
         i += (size_t)gridDim.x * blockDim.x) {
        float4 v = ((const float4*)x)[i];
        bf16 h0, h1, h2, h3, l0, l1, l2, l3;
        split2(v.x, v.y, h0, h1, l0, l1);
        split2(v.z, v.w, h2, h3, l2, l3);
        __nv_bfloat162 ha(h0, h1), hb(h2, h3), la(l0, l1), lb(l2, l3);
        ((__nv_bfloat162*)hi)[2 * i] = ha;
        ((__nv_bfloat162*)hi)[2 * i + 1] = hb;
        ((__nv_bfloat162*)lo)[2 * i] = la;
        ((__nv_bfloat162*)lo)[2 * i + 1] = lb;
    }
}

// ---------------------------------------------------------------------------
// Column softmax on attnT (softmax over w rows per (batch, v) column),
// writing bf16 hi/lo. block (32,16), grid (VDIM/32, BATCH).
// ---------------------------------------------------------------------------
__global__ __launch_bounds__(512) void softmax_col(
    const float* __restrict__ attnT,
    bf16* __restrict__ out_hi, bf16* __restrict__ out_lo)
{
    __shared__ float red[16][33];
    const int tx = threadIdx.x, ty = threadIdx.y;
    const size_t base = (size_t)blockIdx.y * VDIM * VDIM + (size_t)blockIdx.x * 32 + tx;

    float vals[64];
    float m = -INFINITY;
#pragma unroll
    for (int k = 0; k < 64; k++) {
        vals[k] = attnT[base + (size_t)(ty + 16 * k) * VDIM];
        m = fmaxf(m, vals[k]);
    }
    red[ty][tx] = m;
    __syncthreads();
#pragma unroll
    for (int off = 8; off >= 1; off >>= 1) {
        if (ty < off) red[ty][tx] = fmaxf(red[ty][tx], red[ty + off][tx]);
        __syncthreads();
    }
    m = red[0][tx];
    __syncthreads();

    float s = 0.f;
#pragma unroll
    for (int k = 0; k < 64; k++) {
        vals[k] = __expf(vals[k] - m);
        s += vals[k];
    }
    red[ty][tx] = s;
    __syncthreads();
#pragma unroll
    for (int off = 8; off >= 1; off >>= 1) {
        if (ty < off) red[ty][tx] += red[ty + off][tx];
        __syncthreads();
    }
    const float inv = 1.0f / red[0][tx];

#pragma unroll
    for (int k = 0; k < 64; k++) {
        const float v = vals[k] * inv;
        const size_t idx = base + (size_t)(ty + 16 * k) * VDIM;
        bf16 h = __float2bfloat16_rn(v);
        bf16 l = __float2bfloat16_rn(v - __bfloat162float(h));
        out_hi[idx] = h;
        out_lo[idx] = l;
    }
}

// ---------------------------------------------------------------------------
extern "C" void kernel_launch(void* const* d_in, const int* in_sizes, int n_in,
                              void* d_out, int out_size)
{
    const float* input = (const float*)d_in[0];
    const float* Wq    = (const float*)d_in[1];
    const float* bq    = (const float*)d_in[2];
    const float* Wk    = (const float*)d_in[3];
    const float* bk    = (const float*)d_in[4];
    const float* Wv    = (const float*)d_in[5];
    const float* bv    = (const float*)d_in[6];
    const float* gamma = (const float*)d_in[7];
    float* out = (float*)d_out;

    bf16 *in_hi, *in_lo, *wq_hi, *wq_lo, *wk_hi, *wk_lo, *wv_hi, *wv_lo;
    bf16 *qT_hi, *qT_lo, *kT_hi, *kT_lo, *v_hi, *v_lo, *att_hi, *att_lo;
    float* attnT;
    cudaGetSymbolAddress((void**)&in_hi, g_in_hi);
    cudaGetSymbolAddress((void**)&in_lo, g_in_lo);
    cudaGetSymbolAddress((void**)&wq_hi, g_wq_hi);
    cudaGetSymbolAddress((void**)&wq_lo, g_wq_lo);
    cudaGetSymbolAddress((void**)&wk_hi, g_wk_hi);
    cudaGetSymbolAddress((void**)&wk_lo, g_wk_lo);
    cudaGetSymbolAddress((void**)&wv_hi, g_wv_hi);
    cudaGetSymbolAddress((void**)&wv_lo, g_wv_lo);
    cudaGetSymbolAddress((void**)&qT_hi, g_qT_hi);
    cudaGetSymbolAddress((void**)&qT_lo, g_qT_lo);
    cudaGetSymbolAddress((void**)&kT_hi, g_kT_hi);
    cudaGetSymbolAddress((void**)&kT_lo, g_kT_lo);
    cudaGetSymbolAddress((void**)&v_hi, g_v_hi);
    cudaGetSymbolAddress((void**)&v_lo, g_v_lo);
    cudaGetSymbolAddress((void**)&att_hi, g_att_hi);
    cudaGetSymbolAddress((void**)&att_lo, g_att_lo);
    cudaGetSymbolAddress((void**)&attnT, g_attnT);

    cudaFuncSetAttribute(gemm_bf<0>, cudaFuncAttributeMaxDynamicSharedMemorySize, SMEM_BYTES);
    cudaFuncSetAttribute(gemm_bf<1>, cudaFuncAttributeMaxDynamicSharedMemorySize, SMEM_BYTES);
    cudaFuncSetAttribute(gemm_bf<2>, cudaFuncAttributeMaxDynamicSharedMemorySize, SMEM_BYTES);
    cudaFuncSetAttribute(gemm_bf<3>, cudaFuncAttributeMaxDynamicSharedMemorySize, SMEM_BYTES);

    const long long MN = (long long)BATCH * SEQ;   // 32768
    const long long BSEQ = (long long)SEQ * VDIM;  // 4194304
    const long long AT = (long long)VDIM * VDIM;   // 1048576

    // Convert inputs to bf16 hi/lo
    convert_hilo<<<2048, 256>>>(input, in_hi, in_lo, (size_t)MN * VDIM / 4);
    convert_hilo<<<64, 256>>>(Wq, wq_hi, wq_lo, (size_t)VDIM * KQDIM / 4);
    convert_hilo<<<64, 256>>>(Wk, wk_hi, wk_lo, (size_t)VDIM * KQDIM / 4);
    convert_hilo<<<256, 256>>>(Wv, wv_hi, wv_lo, (size_t)VDIM * VDIM / 4);

    // qT[w, n] = sum_e Wq[w,e] * input[n, 768+e]  (M=1024, N=32768, K=256)
    gemm_bf<1><<<dim3(256, 4, 1), 512, SMEM_BYTES>>>(
        wq_hi, wq_lo, KQDIM, 0,
        in_hi + (VDIM - KQDIM), in_lo + (VDIM - KQDIM), VDIM, 0,
        nullptr, qT_hi, qT_lo, MN, 0, bq, nullptr, nullptr, KQDIM / 32);
    // kT[v, n]
    gemm_bf<1><<<dim3(256, 4, 1), 512, SMEM_BYTES>>>(
        wk_hi, wk_lo, KQDIM, 0,
        in_hi + (VDIM - KQDIM), in_lo + (VDIM - KQDIM), VDIM, 0,
        nullptr, kT_hi, kT_lo, MN, 0, bk, nullptr, nullptr, KQDIM / 32);
    // v[n, w] = sum_e input[n,e] * Wv[w,e]  (M=32768, N=1024, K=1024)
    gemm_bf<2><<<dim3(8, 128, 1), 512, SMEM_BYTES>>>(
        in_hi, in_lo, VDIM, 0,
        wv_hi, wv_lo, VDIM, 0,
        nullptr, v_hi, v_lo, VDIM, 0, bv, nullptr, nullptr, VDIM / 32);
    // attnT[b][w, v] = sum_n qT[w, bn] * kT[v, bn]  (per batch M=N=1024, K=4096)
    gemm_bf<0><<<dim3(8, 4, 8), 512, SMEM_BYTES>>>(
        qT_hi, qT_lo, MN, SEQ,
        kT_hi, kT_lo, MN, SEQ,
        attnT, nullptr, nullptr, VDIM, AT, nullptr, nullptr, nullptr, SEQ / 32);
    // softmax over w; emit bf16 hi/lo
    softmax_col<<<dim3(VDIM / 32, BATCH), dim3(32, 16)>>>(attnT, att_hi, att_lo);
    // out[b][n, w] = gamma * sum_v v[bn, v] * attT[b][w, v] + input
    gemm_bf<3><<<dim3(8, 16, 8), 512, SMEM_BYTES>>>(
        v_hi, v_lo, VDIM, BSEQ,
        att_hi, att_lo, VDIM, AT,
        out, nullptr, nullptr, VDIM, BSEQ, nullptr, input, gamma, VDIM / 32);
}

// round 6
// speedup vs baseline: 2.2959x; 1.0374x over previous
#include <cuda_runtime.h>
#include <cuda_bf16.h>
#include <cstdint>
#include <math.h>

// Problem constants
#define BATCH 8
#define SEQ   4096
#define VDIM  1024
#define KQDIM 256

typedef __nv_bfloat16 bf16;

// ---------------------------------------------------------------------------
// Scratch (device globals; no runtime allocation allowed)
// ---------------------------------------------------------------------------
__device__ bf16 g_in_hi[(size_t)BATCH * SEQ * VDIM];
__device__ bf16 g_in_lo[(size_t)BATCH * SEQ * VDIM];
__device__ bf16 g_wq_hi[(size_t)VDIM * KQDIM];
__device__ bf16 g_wq_lo[(size_t)VDIM * KQDIM];
__device__ bf16 g_wk_hi[(size_t)VDIM * KQDIM];
__device__ bf16 g_wk_lo[(size_t)VDIM * KQDIM];
__device__ bf16 g_wv_hi[(size_t)VDIM * VDIM];
__device__ bf16 g_wv_lo[(size_t)VDIM * VDIM];
__device__ bf16 g_qT_hi[(size_t)VDIM * BATCH * SEQ];   // [1024 w][32768 n]
__device__ bf16 g_qT_lo[(size_t)VDIM * BATCH * SEQ];
__device__ bf16 g_kT_hi[(size_t)VDIM * BATCH * SEQ];
__device__ bf16 g_kT_lo[(size_t)VDIM * BATCH * SEQ];
__device__ bf16 g_v_hi[(size_t)BATCH * SEQ * VDIM];    // [32768 n][1024 v]
__device__ bf16 g_v_lo[(size_t)BATCH * SEQ * VDIM];
__device__ float g_attnT[(size_t)BATCH * VDIM * VDIM]; // [8][1024 w][1024 v]
__device__ bf16 g_att_hi[(size_t)BATCH * VDIM * VDIM];
__device__ bf16 g_att_lo[(size_t)BATCH * VDIM * VDIM];

// ---------------------------------------------------------------------------
// Helpers
// ---------------------------------------------------------------------------
__device__ __forceinline__ uint32_t smem_to_u32(const void* p) {
    uint32_t a;
    asm("{ .reg .u64 t; cvta.to.shared.u64 t, %1; cvt.u32.u64 %0, t; }"
        : "=r"(a) : "l"(p));
    return a;
}

__device__ __forceinline__ void ldsm_x4(uint32_t addr, uint32_t* r) {
    asm volatile("ldmatrix.sync.aligned.m8n8.x4.shared.b16 {%0,%1,%2,%3}, [%4];"
        : "=r"(r[0]), "=r"(r[1]), "=r"(r[2]), "=r"(r[3]) : "r"(addr));
}

__device__ __forceinline__ void mma16816(float* d, const uint32_t* a, const uint32_t* b) {
    asm volatile(
        "mma.sync.aligned.m16n8k16.row.col.f32.bf16.bf16.f32 "
        "{%0,%1,%2,%3}, {%4,%5,%6,%7}, {%8,%9}, {%0,%1,%2,%3};"
        : "+f"(d[0]), "+f"(d[1]), "+f"(d[2]), "+f"(d[3])
        : "r"(a[0]), "r"(a[1]), "r"(a[2]), "r"(a[3]), "r"(b[0]), "r"(b[1]));
}

#define CP_ASYNC16(s, g) \
    asm volatile("cp.async.cg.shared.global [%0], [%1], 16;" :: "r"(s), "l"(g))
#define CP_COMMIT() asm volatile("cp.async.commit_group;" ::: "memory")
#define CP_WAIT(n)  asm volatile("cp.async.wait_group %0;" :: "n"(n) : "memory")

__device__ __forceinline__ void split2(float x, float y, bf16& hx, bf16& hy,
                                       bf16& lx, bf16& ly) {
    hx = __float2bfloat16_rn(x);
    hy = __float2bfloat16_rn(y);
    lx = __float2bfloat16_rn(x - __bfloat162float(hx));
    ly = __float2bfloat16_rn(y - __bfloat162float(hy));
}

// SMEM tile geometry: K-chunk 32 bf16 = 64B + 16B pad = 80B rows.
// Per stage: A_hi (256 rows), A_lo (256), B_hi (128), B_lo (128).
#define ROWB 80
#define A_COMP (256 * ROWB)           // 20480
#define B_COMP (128 * ROWB)           // 10240
#define OFF_AHI 0
#define OFF_ALO A_COMP
#define OFF_BHI (2 * A_COMP)
#define OFF_BLO (2 * A_COMP + B_COMP)
#define STAGE_BYTES (2 * A_COMP + 2 * B_COMP)  // 61440
#define PIPE 3
#define SMEM_BYTES (PIPE * STAGE_BYTES)        // 184320

// ---------------------------------------------------------------------------
// Unified NT GEMM: C = A * B^T, A/B bf16 hi/lo pairs, K-major.
// CTA tile 256x128, K-chunk 32, cp.async 3-stage pipeline, 512 threads,
// 16 warps (4x4), warp tile 64x32. bf16x3: AhiBhi + AhiBlo + AloBhi.
// Register-budget mainloop: B frags resident (16 regs), A frags loaded in
// mt-pairs (16 regs) so peak live regs stay under the 128-reg/thread cap.
// EPI: 1 = +bias[row] -> bf16 hi/lo; 2 = +bias[col] -> bf16 hi/lo;
//      0 = fp32; 3 = gamma*acc + resid -> fp32.
// ---------------------------------------------------------------------------
template <int EPI>
__global__ __launch_bounds__(512) void gemm_bf(
    const bf16* __restrict__ Ahi, const bf16* __restrict__ Alo,
    long long lda, long long a_bs,
    const bf16* __restrict__ Bhi, const bf16* __restrict__ Blo,
    long long ldb, long long b_bs,
    float* __restrict__ Cf, bf16* __restrict__ Chi, bf16* __restrict__ Clo,
    long long ldc, long long c_bs,
    const float* __restrict__ bias,
    const float* __restrict__ resid,
    const float* __restrict__ gamma,
    int nchunks)
{
    extern __shared__ char smem[];
    const int tid = threadIdx.x;
    const int wid = tid >> 5;
    const int lane = tid & 31;

    const size_t m0 = (size_t)blockIdx.y * 256;
    const size_t n0 = (size_t)blockIdx.x * 128;
    const size_t z = blockIdx.z;
    Ahi += z * a_bs; Alo += z * a_bs;
    Bhi += z * b_bs; Blo += z * b_bs;

    // cp.async mapping: seg = tid&3 (16B), r = tid>>2 (0..127)
    const int seg = tid & 3;
    const int r = tid >> 2;
    const uint32_t sb = smem_to_u32(smem);
    const uint32_t sr0 = r * ROWB + seg * 16;
    const uint32_t sr1 = (r + 128) * ROWB + seg * 16;

    const bf16* Ah0 = Ahi + (m0 + r) * (size_t)lda + seg * 8;
    const bf16* Ah1 = Ahi + (m0 + r + 128) * (size_t)lda + seg * 8;
    const bf16* Al0 = Alo + (m0 + r) * (size_t)lda + seg * 8;
    const bf16* Al1 = Alo + (m0 + r + 128) * (size_t)lda + seg * 8;
    const bf16* Bh0 = Bhi + (n0 + r) * (size_t)ldb + seg * 8;
    const bf16* Bl0 = Blo + (n0 + r) * (size_t)ldb + seg * 8;

    auto load_stage = [&](int kc, int s) {
        const uint32_t st = sb + s * STAGE_BYTES;
        const size_t ko = (size_t)kc * 32;
        CP_ASYNC16(st + OFF_AHI + sr0, Ah0 + ko);
        CP_ASYNC16(st + OFF_AHI + sr1, Ah1 + ko);
        CP_ASYNC16(st + OFF_ALO + sr0, Al0 + ko);
        CP_ASYNC16(st + OFF_ALO + sr1, Al1 + ko);
        CP_ASYNC16(st + OFF_BHI + sr0, Bh0 + ko);
        CP_ASYNC16(st + OFF_BLO + sr0, Bl0 + ko);
        CP_COMMIT();
    };

    // Warp tile origin (16 warps: 4 x 4)
    const int wm = (wid >> 2) * 64;
    const int wn = (wid & 3) * 32;

    float acc[4][4][4];
#pragma unroll
    for (int i = 0; i < 4; i++)
#pragma unroll
        for (int j = 0; j < 4; j++)
#pragma unroll
            for (int k = 0; k < 4; k++) acc[i][j][k] = 0.f;

    // ldmatrix lane addressing
    const uint32_t lrow16 = lane & 15;
    const uint32_t lcol16 = (lane >> 4) * 16;

    // Prologue: fill PIPE-1 stages
#pragma unroll
    for (int s = 0; s < PIPE - 1; s++) load_stage(s, s);

    for (int i = 0; i < nchunks; i++) {
        CP_WAIT(PIPE - 2);
        __syncthreads();   // stage i ready AND everyone done reading stage i-1

        if (i + PIPE - 1 < nchunks) load_stage(i + PIPE - 1, (i + PIPE - 1) % PIPE);

        const uint32_t st = sb + (i % PIPE) * STAGE_BYTES;
#pragma unroll
        for (int kk = 0; kk < 2; kk++) {
            const uint32_t kb = kk * 32 + lcol16;
            // B fragments resident for this kk (16 regs)
            uint32_t Bfh[4][2], Bfl[4][2];
#pragma unroll
            for (int p = 0; p < 2; p++) {
                uint32_t bd = st + OFF_BHI + (wn + p * 16 + lrow16) * ROWB + kb;
                uint32_t t[4];
                ldsm_x4(bd, t);
                Bfh[2 * p][0] = t[0]; Bfh[2 * p][1] = t[2];
                Bfh[2 * p + 1][0] = t[1]; Bfh[2 * p + 1][1] = t[3];
                ldsm_x4(bd + B_COMP, t);
                Bfl[2 * p][0] = t[0]; Bfl[2 * p][1] = t[2];
                Bfl[2 * p + 1][0] = t[1]; Bfl[2 * p + 1][1] = t[3];
            }
            // A fragments in mt-pairs (16 regs live instead of 64)
#pragma unroll
            for (int mp = 0; mp < 2; mp++) {
                uint32_t Afh[2][4], Afl[2][4];
#pragma unroll
                for (int m2 = 0; m2 < 2; m2++) {
                    uint32_t ad = st + OFF_AHI +
                        (wm + (mp * 2 + m2) * 16 + lrow16) * ROWB + kb;
                    ldsm_x4(ad, Afh[m2]);
                    ldsm_x4(ad + A_COMP, Afl[m2]);
                }
#pragma unroll
                for (int m2 = 0; m2 < 2; m2++) {
                    const int mt = mp * 2 + m2;
#pragma unroll
                    for (int nt = 0; nt < 4; nt++) {
                        mma16816(acc[mt][nt], Afh[m2], Bfh[nt]);
                        mma16816(acc[mt][nt], Afh[m2], Bfl[nt]);
                        mma16816(acc[mt][nt], Afl[m2], Bfh[nt]);
                    }
                }
            }
        }
    }

    // Epilogue
    const int er = lane >> 2;
    const int ec = (lane & 3) * 2;
    const float g = (EPI == 3) ? __ldg(gamma) : 0.f;
    const float* rz = (EPI == 3) ? (resid + z * c_bs) : (const float*)nullptr;
    float* Cfz = (EPI == 0 || EPI == 3) ? (Cf + z * c_bs) : nullptr;
#pragma unroll
    for (int mt = 0; mt < 4; mt++) {
#pragma unroll
        for (int half = 0; half < 2; half++) {
            const size_t row = m0 + wm + mt * 16 + er + half * 8;
            float rowbias = 0.f;
            if (EPI == 1) rowbias = bias[row];
#pragma unroll
            for (int nt = 0; nt < 4; nt++) {
                const size_t col = n0 + wn + nt * 8 + ec;
                float vx = acc[mt][nt][half * 2 + 0];
                float vy = acc[mt][nt][half * 2 + 1];
                if (EPI == 1) { vx += rowbias; vy += rowbias; }
                if (EPI == 2) { vx += bias[col]; vy += bias[col + 1]; }
                if (EPI == 3) {
                    const float2 rv = *(const float2*)(rz + row * (size_t)ldc + col);
                    vx = fmaf(g, vx, rv.x);
                    vy = fmaf(g, vy, rv.y);
                }
                if (EPI == 0 || EPI == 3) {
                    float2 o = make_float2(vx, vy);
                    *(float2*)(Cfz + row * (size_t)ldc + col) = o;
                } else {
                    bf16 hx, hy, lx, ly;
                    split2(vx, vy, hx, hy, lx, ly);
                    __nv_bfloat162 h2(hx, hy), l2(lx, ly);
                    *(__nv_bfloat162*)(Chi + row * (size_t)ldc + col) = h2;
                    *(__nv_bfloat162*)(Clo + row * (size_t)ldc + col) = l2;
                }
            }
        }
    }
}

// ---------------------------------------------------------------------------
// Convert fp32 array -> bf16 hi/lo pair. Grid-stride, float4 granularity.
// ---------------------------------------------------------------------------
__global__ void convert_hilo(const float* __restrict__ x,
                             bf16* __restrict__ hi, bf16* __restrict__ lo,
                             size_t n4)
{
    for (size_t i = blockIdx.x * (size_t)blockDim.x + threadIdx.x; i < n4;
         i += (size_t)gridDim.x * blockDim.x) {
        float4 v = ((const float4*)x)[i];
        bf16 h0, h1, h2, h3, l0, l1, l2, l3;
        split2(v.x, v.y, h0, h1, l0, l1);
        split2(v.z, v.w, h2, h3, l2, l3);
        __nv_bfloat162 ha(h0, h1), hb(h2, h3), la(l0, l1), lb(l2, l3);
        ((__nv_bfloat162*)hi)[2 * i] = ha;
        ((__nv_bfloat162*)hi)[2 * i + 1] = hb;
        ((__nv_bfloat162*)lo)[2 * i] = la;
        ((__nv_bfloat162*)lo)[2 * i + 1] = lb;
    }
}

// ---------------------------------------------------------------------------
// Column softmax on attnT (softmax over w rows per (batch, v) column),
// writing bf16 hi/lo. block (32,16), grid (VDIM/32, BATCH).
// ---------------------------------------------------------------------------
__global__ __launch_bounds__(512) void softmax_col(
    const float* __restrict__ attnT,
    bf16* __restrict__ out_hi, bf16* __restrict__ out_lo)
{
    __shared__ float red[16][33];
    const int tx = threadIdx.x, ty = threadIdx.y;
    const size_t base = (size_t)blockIdx.y * VDIM * VDIM + (size_t)blockIdx.x * 32 + tx;

    float vals[64];
    float m = -INFINITY;
#pragma unroll
    for (int k = 0; k < 64; k++) {
        vals[k] = attnT[base + (size_t)(ty + 16 * k) * VDIM];
        m = fmaxf(m, vals[k]);
    }
    red[ty][tx] = m;
    __syncthreads();
#pragma unroll
    for (int off = 8; off >= 1; off >>= 1) {
        if (ty < off) red[ty][tx] = fmaxf(red[ty][tx], red[ty + off][tx]);
        __syncthreads();
    }
    m = red[0][tx];
    __syncthreads();

    float s = 0.f;
#pragma unroll
    for (int k = 0; k < 64; k++) {
        vals[k] = __expf(vals[k] - m);
        s += vals[k];
    }
    red[ty][tx] = s;
    __syncthreads();
#pragma unroll
    for (int off = 8; off >= 1; off >>= 1) {
        if (ty < off) red[ty][tx] += red[ty + off][tx];
        __syncthreads();
    }
    const float inv = 1.0f / red[0][tx];

#pragma unroll
    for (int k = 0; k < 64; k++) {
        const float v = vals[k] * inv;
        const size_t idx = base + (size_t)(ty + 16 * k) * VDIM;
        bf16 h = __float2bfloat16_rn(v);
        bf16 l = __float2bfloat16_rn(v - __bfloat162float(h));
        out_hi[idx] = h;
        out_lo[idx] = l;
    }
}

// ---------------------------------------------------------------------------
extern "C" void kernel_launch(void* const* d_in, const int* in_sizes, int n_in,
                              void* d_out, int out_size)
{
    const float* input = (const float*)d_in[0];
    const float* Wq    = (const float*)d_in[1];
    const float* bq    = (const float*)d_in[2];
    const float* Wk    = (const float*)d_in[3];
    const float* bk    = (const float*)d_in[4];
    const float* Wv    = (const float*)d_in[5];
    const float* bv    = (const float*)d_in[6];
    const float* gamma = (const float*)d_in[7];
    float* out = (float*)d_out;

    bf16 *in_hi, *in_lo, *wq_hi, *wq_lo, *wk_hi, *wk_lo, *wv_hi, *wv_lo;
    bf16 *qT_hi, *qT_lo, *kT_hi, *kT_lo, *v_hi, *v_lo, *att_hi, *att_lo;
    float* attnT;
    cudaGetSymbolAddress((void**)&in_hi, g_in_hi);
    cudaGetSymbolAddress((void**)&in_lo, g_in_lo);
    cudaGetSymbolAddress((void**)&wq_hi, g_wq_hi);
    cudaGetSymbolAddress((void**)&wq_lo, g_wq_lo);
    cudaGetSymbolAddress((void**)&wk_hi, g_wk_hi);
    cudaGetSymbolAddress((void**)&wk_lo, g_wk_lo);
    cudaGetSymbolAddress((void**)&wv_hi, g_wv_hi);
    cudaGetSymbolAddress((void**)&wv_lo, g_wv_lo);
    cudaGetSymbolAddress((void**)&qT_hi, g_qT_hi);
    cudaGetSymbolAddress((void**)&qT_lo, g_qT_lo);
    cudaGetSymbolAddress((void**)&kT_hi, g_kT_hi);
    cudaGetSymbolAddress((void**)&kT_lo, g_kT_lo);
    cudaGetSymbolAddress((void**)&v_hi, g_v_hi);
    cudaGetSymbolAddress((void**)&v_lo, g_v_lo);
    cudaGetSymbolAddress((void**)&att_hi, g_att_hi);
    cudaGetSymbolAddress((void**)&att_lo, g_att_lo);
    cudaGetSymbolAddress((void**)&attnT, g_attnT);

    cudaFuncSetAttribute(gemm_bf<0>, cudaFuncAttributeMaxDynamicSharedMemorySize, SMEM_BYTES);
    cudaFuncSetAttribute(gemm_bf<1>, cudaFuncAttributeMaxDynamicSharedMemorySize, SMEM_BYTES);
    cudaFuncSetAttribute(gemm_bf<2>, cudaFuncAttributeMaxDynamicSharedMemorySize, SMEM_BYTES);
    cudaFuncSetAttribute(gemm_bf<3>, cudaFuncAttributeMaxDynamicSharedMemorySize, SMEM_BYTES);

    const long long MN = (long long)BATCH * SEQ;   // 32768
    const long long BSEQ = (long long)SEQ * VDIM;  // 4194304
    const long long AT = (long long)VDIM * VDIM;   // 1048576

    // Convert inputs to bf16 hi/lo
    convert_hilo<<<2048, 256>>>(input, in_hi, in_lo, (size_t)MN * VDIM / 4);
    convert_hilo<<<64, 256>>>(Wq, wq_hi, wq_lo, (size_t)VDIM * KQDIM / 4);
    convert_hilo<<<64, 256>>>(Wk, wk_hi, wk_lo, (size_t)VDIM * KQDIM / 4);
    convert_hilo<<<256, 256>>>(Wv, wv_hi, wv_lo, (size_t)VDIM * VDIM / 4);

    // qT[w, n] = sum_e Wq[w,e] * input[n, 768+e]  (M=1024, N=32768, K=256)
    gemm_bf<1><<<dim3(256, 4, 1), 512, SMEM_BYTES>>>(
        wq_hi, wq_lo, KQDIM, 0,
        in_hi + (VDIM - KQDIM), in_lo + (VDIM - KQDIM), VDIM, 0,
        nullptr, qT_hi, qT_lo, MN, 0, bq, nullptr, nullptr, KQDIM / 32);
    // kT[v, n]
    gemm_bf<1><<<dim3(256, 4, 1), 512, SMEM_BYTES>>>(
        wk_hi, wk_lo, KQDIM, 0,
        in_hi + (VDIM - KQDIM), in_lo + (VDIM - KQDIM), VDIM, 0,
        nullptr, kT_hi, kT_lo, MN, 0, bk, nullptr, nullptr, KQDIM / 32);
    // v[n, w] = sum_e input[n,e] * Wv[w,e]  (M=32768, N=1024, K=1024)
    gemm_bf<2><<<dim3(8, 128, 1), 512, SMEM_BYTES>>>(
        in_hi, in_lo, VDIM, 0,
        wv_hi, wv_lo, VDIM, 0,
        nullptr, v_hi, v_lo, VDIM, 0, bv, nullptr, nullptr, VDIM / 32);
    // attnT[b][w, v] = sum_n qT[w, bn] * kT[v, bn]  (per batch M=N=1024, K=4096)
    gemm_bf<0><<<dim3(8, 4, 8), 512, SMEM_BYTES>>>(
        qT_hi, qT_lo, MN, SEQ,
        kT_hi, kT_lo, MN, SEQ,
        attnT, nullptr, nullptr, VDIM, AT, nullptr, nullptr, nullptr, SEQ / 32);
    // softmax over w; emit bf16 hi/lo
    softmax_col<<<dim3(VDIM / 32, BATCH), dim3(32, 16)>>>(attnT, att_hi, att_lo);
    // out[b][n, w] = gamma * sum_v v[bn, v] * attT[b][w, v] + input
    gemm_bf<3><<<dim3(8, 16, 8), 512, SMEM_BYTES>>>(
        v_hi, v_lo, VDIM, BSEQ,
        att_hi, att_lo, VDIM, AT,
        out, nullptr, nullptr, VDIM, BSEQ, nullptr, input, gamma, VDIM / 32);
}

// round 7
// speedup vs baseline: 3.2912x; 1.4335x over previous
#include <cuda_runtime.h>
#include <cuda_bf16.h>
#include <cuda_fp16.h>
#include <cstdint>
#include <math.h>

// Problem constants
#define BATCH 8
#define SEQ   4096
#define VDIM  1024
#define KQDIM 256

typedef __nv_bfloat16 bf16;

// ---------------------------------------------------------------------------
// Scratch (device globals; no runtime allocation allowed)
// ---------------------------------------------------------------------------
__device__ bf16 g_in_hi[(size_t)BATCH * SEQ * VDIM];
__device__ bf16 g_in_lo[(size_t)BATCH * SEQ * VDIM];
__device__ bf16 g_wq_hi[(size_t)VDIM * KQDIM];
__device__ bf16 g_wq_lo[(size_t)VDIM * KQDIM];
__device__ bf16 g_wk_hi[(size_t)VDIM * KQDIM];
__device__ bf16 g_wk_lo[(size_t)VDIM * KQDIM];
__device__ bf16 g_qT_hi[(size_t)VDIM * BATCH * SEQ];   // [1024 w][32768 n]
__device__ bf16 g_qT_lo[(size_t)VDIM * BATCH * SEQ];
__device__ bf16 g_kT_hi[(size_t)VDIM * BATCH * SEQ];
__device__ bf16 g_kT_lo[(size_t)VDIM * BATCH * SEQ];
__device__ float g_attnT[(size_t)BATCH * VDIM * VDIM]; // [8][1024 w][1024 v]
// fp16 path (v / out GEMMs)
__device__ half g_in_f16[(size_t)BATCH * SEQ * VDIM];
__device__ half g_wv_f16[(size_t)VDIM * VDIM];
__device__ half g_v_f16[(size_t)BATCH * SEQ * VDIM];   // [32768 n][1024 v]
__device__ half g_att_f16[(size_t)BATCH * VDIM * VDIM];

// ---------------------------------------------------------------------------
// Helpers
// ---------------------------------------------------------------------------
__device__ __forceinline__ uint32_t smem_to_u32(const void* p) {
    uint32_t a;
    asm("{ .reg .u64 t; cvta.to.shared.u64 t, %1; cvt.u32.u64 %0, t; }"
        : "=r"(a) : "l"(p));
    return a;
}

__device__ __forceinline__ void ldsm_x4(uint32_t addr, uint32_t* r) {
    asm volatile("ldmatrix.sync.aligned.m8n8.x4.shared.b16 {%0,%1,%2,%3}, [%4];"
        : "=r"(r[0]), "=r"(r[1]), "=r"(r[2]), "=r"(r[3]) : "r"(addr));
}

__device__ __forceinline__ void mma_bf16(float* d, const uint32_t* a, const uint32_t* b) {
    asm volatile(
        "mma.sync.aligned.m16n8k16.row.col.f32.bf16.bf16.f32 "
        "{%0,%1,%2,%3}, {%4,%5,%6,%7}, {%8,%9}, {%0,%1,%2,%3};"
        : "+f"(d[0]), "+f"(d[1]), "+f"(d[2]), "+f"(d[3])
        : "r"(a[0]), "r"(a[1]), "r"(a[2]), "r"(a[3]), "r"(b[0]), "r"(b[1]));
}

__device__ __forceinline__ void mma_fp16(float* d, const uint32_t* a, const uint32_t* b) {
    asm volatile(
        "mma.sync.aligned.m16n8k16.row.col.f32.f16.f16.f32 "
        "{%0,%1,%2,%3}, {%4,%5,%6,%7}, {%8,%9}, {%0,%1,%2,%3};"
        : "+f"(d[0]), "+f"(d[1]), "+f"(d[2]), "+f"(d[3])
        : "r"(a[0]), "r"(a[1]), "r"(a[2]), "r"(a[3]), "r"(b[0]), "r"(b[1]));
}

#define CP_ASYNC16(s, g) \
    asm volatile("cp.async.cg.shared.global [%0], [%1], 16;" :: "r"(s), "l"(g))
#define CP_COMMIT() asm volatile("cp.async.commit_group;" ::: "memory")
#define CP_WAIT(n)  asm volatile("cp.async.wait_group %0;" :: "n"(n) : "memory")

__device__ __forceinline__ void split2(float x, float y, bf16& hx, bf16& hy,
                                       bf16& lx, bf16& ly) {
    hx = __float2bfloat16_rn(x);
    hy = __float2bfloat16_rn(y);
    lx = __float2bfloat16_rn(x - __bfloat162float(hx));
    ly = __float2bfloat16_rn(y - __bfloat162float(hy));
}

// SMEM tile geometry: K-chunk 32 halfwords = 64B + 16B pad = 80B rows.
#define ROWB 80
#define A_COMP (256 * ROWB)           // 20480
#define B_COMP (128 * ROWB)           // 10240

// bf16x3 kernel: per stage A_hi, A_lo (256 rows each), B_hi, B_lo (128 each)
#define OFF_AHI 0
#define OFF_ALO A_COMP
#define OFF_BHI (2 * A_COMP)
#define OFF_BLO (2 * A_COMP + B_COMP)
#define STAGE_BYTES (2 * A_COMP + 2 * B_COMP)  // 61440
#define PIPE 3
#define SMEM_BYTES (PIPE * STAGE_BYTES)        // 184320

// fp16x1 kernel: per stage A (256 rows), B (128 rows)
#define STAGE_F16 (A_COMP + B_COMP)            // 30720
#define PIPE_F16 4
#define SMEM_F16 (PIPE_F16 * STAGE_F16)        // 122880

// ---------------------------------------------------------------------------
// bf16x3 NT GEMM: C = A * B^T, A/B bf16 hi/lo pairs, K-major.
// CTA tile 256x128, K-chunk 32, 3-stage cp.async, 512 threads, 16 warps.
// EPI: 1 = +bias[row] -> bf16 hi/lo (q/k); 0 = fp32 (attn scores).
// ---------------------------------------------------------------------------
template <int EPI>
__global__ __launch_bounds__(512) void gemm_bf(
    const bf16* __restrict__ Ahi, const bf16* __restrict__ Alo,
    long long lda, long long a_bs,
    const bf16* __restrict__ Bhi, const bf16* __restrict__ Blo,
    long long ldb, long long b_bs,
    float* __restrict__ Cf, bf16* __restrict__ Chi, bf16* __restrict__ Clo,
    long long ldc, long long c_bs,
    const float* __restrict__ bias,
    int nchunks)
{
    extern __shared__ char smem[];
    const int tid = threadIdx.x;
    const int wid = tid >> 5;
    const int lane = tid & 31;

    const size_t m0 = (size_t)blockIdx.y * 256;
    const size_t n0 = (size_t)blockIdx.x * 128;
    const size_t z = blockIdx.z;
    Ahi += z * a_bs; Alo += z * a_bs;
    Bhi += z * b_bs; Blo += z * b_bs;

    const int seg = tid & 3;
    const int r = tid >> 2;
    const uint32_t sb = smem_to_u32(smem);
    const uint32_t sr0 = r * ROWB + seg * 16;
    const uint32_t sr1 = (r + 128) * ROWB + seg * 16;

    const bf16* Ah0 = Ahi + (m0 + r) * (size_t)lda + seg * 8;
    const bf16* Ah1 = Ahi + (m0 + r + 128) * (size_t)lda + seg * 8;
    const bf16* Al0 = Alo + (m0 + r) * (size_t)lda + seg * 8;
    const bf16* Al1 = Alo + (m0 + r + 128) * (size_t)lda + seg * 8;
    const bf16* Bh0 = Bhi + (n0 + r) * (size_t)ldb + seg * 8;
    const bf16* Bl0 = Blo + (n0 + r) * (size_t)ldb + seg * 8;

    auto load_stage = [&](int kc, int s) {
        const uint32_t st = sb + s * STAGE_BYTES;
        const size_t ko = (size_t)kc * 32;
        CP_ASYNC16(st + OFF_AHI + sr0, Ah0 + ko);
        CP_ASYNC16(st + OFF_AHI + sr1, Ah1 + ko);
        CP_ASYNC16(st + OFF_ALO + sr0, Al0 + ko);
        CP_ASYNC16(st + OFF_ALO + sr1, Al1 + ko);
        CP_ASYNC16(st + OFF_BHI + sr0, Bh0 + ko);
        CP_ASYNC16(st + OFF_BLO + sr0, Bl0 + ko);
        CP_COMMIT();
    };

    const int wm = (wid >> 2) * 64;
    const int wn = (wid & 3) * 32;

    float acc[4][4][4];
#pragma unroll
    for (int i = 0; i < 4; i++)
#pragma unroll
        for (int j = 0; j < 4; j++)
#pragma unroll
            for (int k = 0; k < 4; k++) acc[i][j][k] = 0.f;

    const uint32_t lrow16 = lane & 15;
    const uint32_t lcol16 = (lane >> 4) * 16;

#pragma unroll
    for (int s = 0; s < PIPE - 1; s++) load_stage(s, s);

    for (int i = 0; i < nchunks; i++) {
        CP_WAIT(PIPE - 2);
        __syncthreads();

        if (i + PIPE - 1 < nchunks) load_stage(i + PIPE - 1, (i + PIPE - 1) % PIPE);

        const uint32_t st = sb + (i % PIPE) * STAGE_BYTES;
#pragma unroll
        for (int kk = 0; kk < 2; kk++) {
            const uint32_t kb = kk * 32 + lcol16;
            uint32_t Bfh[4][2], Bfl[4][2];
#pragma unroll
            for (int p = 0; p < 2; p++) {
                uint32_t bd = st + OFF_BHI + (wn + p * 16 + lrow16) * ROWB + kb;
                uint32_t t[4];
                ldsm_x4(bd, t);
                Bfh[2 * p][0] = t[0]; Bfh[2 * p][1] = t[2];
                Bfh[2 * p + 1][0] = t[1]; Bfh[2 * p + 1][1] = t[3];
                ldsm_x4(bd + B_COMP, t);
                Bfl[2 * p][0] = t[0]; Bfl[2 * p][1] = t[2];
                Bfl[2 * p + 1][0] = t[1]; Bfl[2 * p + 1][1] = t[3];
            }
#pragma unroll
            for (int mp = 0; mp < 2; mp++) {
                uint32_t Afh[2][4], Afl[2][4];
#pragma unroll
                for (int m2 = 0; m2 < 2; m2++) {
                    uint32_t ad = st + OFF_AHI +
                        (wm + (mp * 2 + m2) * 16 + lrow16) * ROWB + kb;
                    ldsm_x4(ad, Afh[m2]);
                    ldsm_x4(ad + A_COMP, Afl[m2]);
                }
#pragma unroll
                for (int m2 = 0; m2 < 2; m2++) {
                    const int mt = mp * 2 + m2;
#pragma unroll
                    for (int nt = 0; nt < 4; nt++) {
                        mma_bf16(acc[mt][nt], Afh[m2], Bfh[nt]);
                        mma_bf16(acc[mt][nt], Afh[m2], Bfl[nt]);
                        mma_bf16(acc[mt][nt], Afl[m2], Bfh[nt]);
                    }
                }
            }
        }
    }

    // Epilogue
    const int er = lane >> 2;
    const int ec = (lane & 3) * 2;
    float* Cfz = (EPI == 0) ? (Cf + z * c_bs) : nullptr;
#pragma unroll
    for (int mt = 0; mt < 4; mt++) {
#pragma unroll
        for (int half_i = 0; half_i < 2; half_i++) {
            const size_t row = m0 + wm + mt * 16 + er + half_i * 8;
            float rowbias = 0.f;
            if (EPI == 1) rowbias = bias[row];
#pragma unroll
            for (int nt = 0; nt < 4; nt++) {
                const size_t col = n0 + wn + nt * 8 + ec;
                float vx = acc[mt][nt][half_i * 2 + 0];
                float vy = acc[mt][nt][half_i * 2 + 1];
                if (EPI == 1) {
                    vx += rowbias; vy += rowbias;
                    bf16 hx, hy, lx, ly;
                    split2(vx, vy, hx, hy, lx, ly);
                    __nv_bfloat162 h2(hx, hy), l2(lx, ly);
                    *(__nv_bfloat162*)(Chi + row * (size_t)ldc + col) = h2;
                    *(__nv_bfloat162*)(Clo + row * (size_t)ldc + col) = l2;
                } else {
                    *(float2*)(Cfz + row * (size_t)ldc + col) = make_float2(vx, vy);
                }
            }
        }
    }
}

// ---------------------------------------------------------------------------
// fp16 single-MMA NT GEMM: C = A * B^T, A/B fp16, K-major.
// CTA tile 256x128, K-chunk 32, 4-stage cp.async, 512 threads, 16 warps.
// EPI: 2 = +bias[col] -> fp16 (v projection); 3 = gamma*acc + resid -> fp32.
// ---------------------------------------------------------------------------
template <int EPI>
__global__ __launch_bounds__(512) void gemm_f16(
    const half* __restrict__ A, long long lda, long long a_bs,
    const half* __restrict__ B, long long ldb, long long b_bs,
    float* __restrict__ Cf, half* __restrict__ Ch, long long ldc, long long c_bs,
    const float* __restrict__ bias,
    const float* __restrict__ resid,
    const float* __restrict__ gamma,
    int nchunks)
{
    extern __shared__ char smem[];
    const int tid = threadIdx.x;
    const int wid = tid >> 5;
    const int lane = tid & 31;

    const size_t m0 = (size_t)blockIdx.y * 256;
    const size_t n0 = (size_t)blockIdx.x * 128;
    const size_t z = blockIdx.z;
    A += z * a_bs;
    B += z * b_bs;

    const int seg = tid & 3;
    const int r = tid >> 2;
    const uint32_t sb = smem_to_u32(smem);
    const uint32_t sr0 = r * ROWB + seg * 16;
    const uint32_t sr1 = (r + 128) * ROWB + seg * 16;

    const half* A0 = A + (m0 + r) * (size_t)lda + seg * 8;
    const half* A1 = A + (m0 + r + 128) * (size_t)lda + seg * 8;
    const half* B0 = B + (n0 + r) * (size_t)ldb + seg * 8;

    auto load_stage = [&](int kc, int s) {
        const uint32_t st = sb + s * STAGE_F16;
        const size_t ko = (size_t)kc * 32;
        CP_ASYNC16(st + sr0, A0 + ko);
        CP_ASYNC16(st + sr1, A1 + ko);
        CP_ASYNC16(st + A_COMP + sr0, B0 + ko);
        CP_COMMIT();
    };

    const int wm = (wid >> 2) * 64;
    const int wn = (wid & 3) * 32;

    float acc[4][4][4];
#pragma unroll
    for (int i = 0; i < 4; i++)
#pragma unroll
        for (int j = 0; j < 4; j++)
#pragma unroll
            for (int k = 0; k < 4; k++) acc[i][j][k] = 0.f;

    const uint32_t lrow16 = lane & 15;
    const uint32_t lcol16 = (lane >> 4) * 16;

#pragma unroll
    for (int s = 0; s < PIPE_F16 - 1; s++) load_stage(s, s);

    for (int i = 0; i < nchunks; i++) {
        CP_WAIT(PIPE_F16 - 2);
        __syncthreads();

        if (i + PIPE_F16 - 1 < nchunks)
            load_stage(i + PIPE_F16 - 1, (i + PIPE_F16 - 1) % PIPE_F16);

        const uint32_t st = sb + (i % PIPE_F16) * STAGE_F16;
#pragma unroll
        for (int kk = 0; kk < 2; kk++) {
            const uint32_t kb = kk * 32 + lcol16;
            uint32_t Bf[4][2];
#pragma unroll
            for (int p = 0; p < 2; p++) {
                uint32_t bd = st + A_COMP + (wn + p * 16 + lrow16) * ROWB + kb;
                uint32_t t[4];
                ldsm_x4(bd, t);
                Bf[2 * p][0] = t[0]; Bf[2 * p][1] = t[2];
                Bf[2 * p + 1][0] = t[1]; Bf[2 * p + 1][1] = t[3];
            }
            uint32_t Af[4][4];
#pragma unroll
            for (int mt = 0; mt < 4; mt++) {
                uint32_t ad = st + (wm + mt * 16 + lrow16) * ROWB + kb;
                ldsm_x4(ad, Af[mt]);
            }
#pragma unroll
            for (int mt = 0; mt < 4; mt++)
#pragma unroll
                for (int nt = 0; nt < 4; nt++)
                    mma_fp16(acc[mt][nt], Af[mt], Bf[nt]);
        }
    }

    // Epilogue
    const int er = lane >> 2;
    const int ec = (lane & 3) * 2;
    const float g = (EPI == 3) ? __ldg(gamma) : 0.f;
    const float* rz = (EPI == 3) ? (resid + z * c_bs) : (const float*)nullptr;
    float* Cfz = (EPI == 3) ? (Cf + z * c_bs) : nullptr;
    half* Chz = (EPI == 2) ? (Ch + z * c_bs) : nullptr;
#pragma unroll
    for (int mt = 0; mt < 4; mt++) {
#pragma unroll
        for (int half_i = 0; half_i < 2; half_i++) {
            const size_t row = m0 + wm + mt * 16 + er + half_i * 8;
#pragma unroll
            for (int nt = 0; nt < 4; nt++) {
                const size_t col = n0 + wn + nt * 8 + ec;
                float vx = acc[mt][nt][half_i * 2 + 0];
                float vy = acc[mt][nt][half_i * 2 + 1];
                if (EPI == 2) {
                    vx += bias[col]; vy += bias[col + 1];
                    __half2 h2 = __floats2half2_rn(vx, vy);
                    *(__half2*)(Chz + row * (size_t)ldc + col) = h2;
                } else {
                    const float2 rv = *(const float2*)(rz + row * (size_t)ldc + col);
                    vx = fmaf(g, vx, rv.x);
                    vy = fmaf(g, vy, rv.y);
                    *(float2*)(Cfz + row * (size_t)ldc + col) = make_float2(vx, vy);
                }
            }
        }
    }
}

// ---------------------------------------------------------------------------
// Convert fp32 array -> bf16 hi/lo pair. Grid-stride, float4 granularity.
// ---------------------------------------------------------------------------
__global__ void convert_hilo(const float* __restrict__ x,
                             bf16* __restrict__ hi, bf16* __restrict__ lo,
                             size_t n4)
{
    for (size_t i = blockIdx.x * (size_t)blockDim.x + threadIdx.x; i < n4;
         i += (size_t)gridDim.x * blockDim.x) {
        float4 v = ((const float4*)x)[i];
        bf16 h0, h1, h2, h3, l0, l1, l2, l3;
        split2(v.x, v.y, h0, h1, l0, l1);
        split2(v.z, v.w, h2, h3, l2, l3);
        __nv_bfloat162 ha(h0, h1), hb(h2, h3), la(l0, l1), lb(l2, l3);
        ((__nv_bfloat162*)hi)[2 * i] = ha;
        ((__nv_bfloat162*)hi)[2 * i + 1] = hb;
        ((__nv_bfloat162*)lo)[2 * i] = la;
        ((__nv_bfloat162*)lo)[2 * i + 1] = lb;
    }
}

// ---------------------------------------------------------------------------
// Convert fp32 array -> fp16. Grid-stride, float4 granularity.
// ---------------------------------------------------------------------------
__global__ void convert_f16(const float* __restrict__ x, half* __restrict__ o,
                            size_t n4)
{
    for (size_t i = blockIdx.x * (size_t)blockDim.x + threadIdx.x; i < n4;
         i += (size_t)gridDim.x * blockDim.x) {
        float4 v = ((const float4*)x)[i];
        __half2 a = __floats2half2_rn(v.x, v.y);
        __half2 b = __floats2half2_rn(v.z, v.w);
        ((__half2*)o)[2 * i] = a;
        ((__half2*)o)[2 * i + 1] = b;
    }
}

// ---------------------------------------------------------------------------
// Column softmax on attnT (softmax over w rows per (batch, v) column),
// writing fp16. block (32,16), grid (VDIM/32, BATCH).
// ---------------------------------------------------------------------------
__global__ __launch_bounds__(512) void softmax_col(
    const float* __restrict__ attnT, half* __restrict__ out_h)
{
    __shared__ float red[16][33];
    const int tx = threadIdx.x, ty = threadIdx.y;
    const size_t base = (size_t)blockIdx.y * VDIM * VDIM + (size_t)blockIdx.x * 32 + tx;

    float vals[64];
    float m = -INFINITY;
#pragma unroll
    for (int k = 0; k < 64; k++) {
        vals[k] = attnT[base + (size_t)(ty + 16 * k) * VDIM];
        m = fmaxf(m, vals[k]);
    }
    red[ty][tx] = m;
    __syncthreads();
#pragma unroll
    for (int off = 8; off >= 1; off >>= 1) {
        if (ty < off) red[ty][tx] = fmaxf(red[ty][tx], red[ty + off][tx]);
        __syncthreads();
    }
    m = red[0][tx];
    __syncthreads();

    float s = 0.f;
#pragma unroll
    for (int k = 0; k < 64; k++) {
        vals[k] = __expf(vals[k] - m);
        s += vals[k];
    }
    red[ty][tx] = s;
    __syncthreads();
#pragma unroll
    for (int off = 8; off >= 1; off >>= 1) {
        if (ty < off) red[ty][tx] += red[ty + off][tx];
        __syncthreads();
    }
    const float inv = 1.0f / red[0][tx];

#pragma unroll
    for (int k = 0; k < 64; k++) {
        const size_t idx = base + (size_t)(ty + 16 * k) * VDIM;
        out_h[idx] = __float2half_rn(vals[k] * inv);
    }
}

// ---------------------------------------------------------------------------
extern "C" void kernel_launch(void* const* d_in, const int* in_sizes, int n_in,
                              void* d_out, int out_size)
{
    const float* input = (const float*)d_in[0];
    const float* Wq    = (const float*)d_in[1];
    const float* bq    = (const float*)d_in[2];
    const float* Wk    = (const float*)d_in[3];
    const float* bk    = (const float*)d_in[4];
    const float* Wv    = (const float*)d_in[5];
    const float* bv    = (const float*)d_in[6];
    const float* gamma = (const float*)d_in[7];
    float* out = (float*)d_out;

    bf16 *in_hi, *in_lo, *wq_hi, *wq_lo, *wk_hi, *wk_lo;
    bf16 *qT_hi, *qT_lo, *kT_hi, *kT_lo;
    half *in_f16, *wv_f16, *v_f16, *att_f16;
    float* attnT;
    cudaGetSymbolAddress((void**)&in_hi, g_in_hi);
    cudaGetSymbolAddress((void**)&in_lo, g_in_lo);
    cudaGetSymbolAddress((void**)&wq_hi, g_wq_hi);
    cudaGetSymbolAddress((void**)&wq_lo, g_wq_lo);
    cudaGetSymbolAddress((void**)&wk_hi, g_wk_hi);
    cudaGetSymbolAddress((void**)&wk_lo, g_wk_lo);
    cudaGetSymbolAddress((void**)&qT_hi, g_qT_hi);
    cudaGetSymbolAddress((void**)&qT_lo, g_qT_lo);
    cudaGetSymbolAddress((void**)&kT_hi, g_kT_hi);
    cudaGetSymbolAddress((void**)&kT_lo, g_kT_lo);
    cudaGetSymbolAddress((void**)&in_f16, g_in_f16);
    cudaGetSymbolAddress((void**)&wv_f16, g_wv_f16);
    cudaGetSymbolAddress((void**)&v_f16, g_v_f16);
    cudaGetSymbolAddress((void**)&att_f16, g_att_f16);
    cudaGetSymbolAddress((void**)&attnT, g_attnT);

    cudaFuncSetAttribute(gemm_bf<0>, cudaFuncAttributeMaxDynamicSharedMemorySize, SMEM_BYTES);
    cudaFuncSetAttribute(gemm_bf<1>, cudaFuncAttributeMaxDynamicSharedMemorySize, SMEM_BYTES);
    cudaFuncSetAttribute(gemm_f16<2>, cudaFuncAttributeMaxDynamicSharedMemorySize, SMEM_F16);
    cudaFuncSetAttribute(gemm_f16<3>, cudaFuncAttributeMaxDynamicSharedMemorySize, SMEM_F16);

    const long long MN = (long long)BATCH * SEQ;   // 32768
    const long long BSEQ = (long long)SEQ * VDIM;  // 4194304
    const long long AT = (long long)VDIM * VDIM;   // 1048576

    // Conversions
    convert_hilo<<<2048, 256>>>(input, in_hi, in_lo, (size_t)MN * VDIM / 4);
    convert_hilo<<<64, 256>>>(Wq, wq_hi, wq_lo, (size_t)VDIM * KQDIM / 4);
    convert_hilo<<<64, 256>>>(Wk, wk_hi, wk_lo, (size_t)VDIM * KQDIM / 4);
    convert_f16<<<2048, 256>>>(input, in_f16, (size_t)MN * VDIM / 4);
    convert_f16<<<256, 256>>>(Wv, wv_f16, (size_t)VDIM * VDIM / 4);

    // qT[w, n] = sum_e Wq[w,e] * input[n, 768+e]  (M=1024, N=32768, K=256)
    gemm_bf<1><<<dim3(256, 4, 1), 512, SMEM_BYTES>>>(
        wq_hi, wq_lo, KQDIM, 0,
        in_hi + (VDIM - KQDIM), in_lo + (VDIM - KQDIM), VDIM, 0,
        nullptr, qT_hi, qT_lo, MN, 0, bq, KQDIM / 32);
    // kT[v, n]
    gemm_bf<1><<<dim3(256, 4, 1), 512, SMEM_BYTES>>>(
        wk_hi, wk_lo, KQDIM, 0,
        in_hi + (VDIM - KQDIM), in_lo + (VDIM - KQDIM), VDIM, 0,
        nullptr, kT_hi, kT_lo, MN, 0, bk, KQDIM / 32);
    // v[n, w] = sum_e input[n,e] * Wv[w,e]  (M=32768, N=1024, K=1024), fp16 x1
    gemm_f16<2><<<dim3(8, 128, 1), 512, SMEM_F16>>>(
        in_f16, VDIM, 0, wv_f16, VDIM, 0,
        nullptr, v_f16, VDIM, 0, bv, nullptr, nullptr, VDIM / 32);
    // attnT[b][w, v] = sum_n qT[w, bn] * kT[v, bn]  (per batch M=N=1024, K=4096)
    gemm_bf<0><<<dim3(8, 4, 8), 512, SMEM_BYTES>>>(
        qT_hi, qT_lo, MN, SEQ,
        kT_hi, kT_lo, MN, SEQ,
        attnT, nullptr, nullptr, VDIM, AT, nullptr, SEQ / 32);
    // softmax over w; emit fp16
    softmax_col<<<dim3(VDIM / 32, BATCH), dim3(32, 16)>>>(attnT, att_f16);
    // out[b][n, w] = gamma * sum_v v[bn, v] * attT[b][w, v] + input, fp16 x1
    gemm_f16<3><<<dim3(8, 16, 8), 512, SMEM_F16>>>(
        v_f16, VDIM, BSEQ, att_f16, VDIM, AT,
        out, nullptr, VDIM, BSEQ, nullptr, input, gamma, VDIM / 32);
}

// round 8
// speedup vs baseline: 3.8109x; 1.1579x over previous
#include <cuda_runtime.h>
#include <cuda_bf16.h>
#include <cuda_fp16.h>
#include <cstdint>
#include <math.h>

// Problem constants
#define BATCH 8
#define SEQ   4096
#define VDIM  1024
#define KQDIM 256

typedef __nv_bfloat16 bf16;

// ---------------------------------------------------------------------------
// Scratch (device globals; no runtime allocation allowed)
// ---------------------------------------------------------------------------
__device__ bf16 g_in_hi[(size_t)BATCH * SEQ * VDIM];
__device__ bf16 g_in_lo[(size_t)BATCH * SEQ * VDIM];
__device__ bf16 g_wq_hi[(size_t)VDIM * KQDIM];
__device__ bf16 g_wq_lo[(size_t)VDIM * KQDIM];
__device__ bf16 g_wk_hi[(size_t)VDIM * KQDIM];
__device__ bf16 g_wk_lo[(size_t)VDIM * KQDIM];
__device__ half g_qT_hi[(size_t)VDIM * BATCH * SEQ];   // [1024 w][32768 n] fp16
__device__ half g_qT_lo[(size_t)VDIM * BATCH * SEQ];
__device__ half g_kT_hi[(size_t)VDIM * BATCH * SEQ];   // fp16, hi only
__device__ float g_attnT[(size_t)BATCH * VDIM * VDIM]; // [8][1024 w][1024 v]
// fp16 path (v / out GEMMs)
__device__ half g_in_f16[(size_t)BATCH * SEQ * VDIM];
__device__ half g_wv_f16[(size_t)VDIM * VDIM];
__device__ half g_v_f16[(size_t)BATCH * SEQ * VDIM];   // [32768 n][1024 v]
__device__ half g_att_f16[(size_t)BATCH * VDIM * VDIM];

// ---------------------------------------------------------------------------
// Helpers
// ---------------------------------------------------------------------------
__device__ __forceinline__ uint32_t smem_to_u32(const void* p) {
    uint32_t a;
    asm("{ .reg .u64 t; cvta.to.shared.u64 t, %1; cvt.u32.u64 %0, t; }"
        : "=r"(a) : "l"(p));
    return a;
}

__device__ __forceinline__ void ldsm_x4(uint32_t addr, uint32_t* r) {
    asm volatile("ldmatrix.sync.aligned.m8n8.x4.shared.b16 {%0,%1,%2,%3}, [%4];"
        : "=r"(r[0]), "=r"(r[1]), "=r"(r[2]), "=r"(r[3]) : "r"(addr));
}

__device__ __forceinline__ void mma_bf16(float* d, const uint32_t* a, const uint32_t* b) {
    asm volatile(
        "mma.sync.aligned.m16n8k16.row.col.f32.bf16.bf16.f32 "
        "{%0,%1,%2,%3}, {%4,%5,%6,%7}, {%8,%9}, {%0,%1,%2,%3};"
        : "+f"(d[0]), "+f"(d[1]), "+f"(d[2]), "+f"(d[3])
        : "r"(a[0]), "r"(a[1]), "r"(a[2]), "r"(a[3]), "r"(b[0]), "r"(b[1]));
}

__device__ __forceinline__ void mma_fp16(float* d, const uint32_t* a, const uint32_t* b) {
    asm volatile(
        "mma.sync.aligned.m16n8k16.row.col.f32.f16.f16.f32 "
        "{%0,%1,%2,%3}, {%4,%5,%6,%7}, {%8,%9}, {%0,%1,%2,%3};"
        : "+f"(d[0]), "+f"(d[1]), "+f"(d[2]), "+f"(d[3])
        : "r"(a[0]), "r"(a[1]), "r"(a[2]), "r"(a[3]), "r"(b[0]), "r"(b[1]));
}

#define CP_ASYNC16(s, g) \
    asm volatile("cp.async.cg.shared.global [%0], [%1], 16;" :: "r"(s), "l"(g))
#define CP_COMMIT() asm volatile("cp.async.commit_group;" ::: "memory")
#define CP_WAIT(n)  asm volatile("cp.async.wait_group %0;" :: "n"(n) : "memory")

__device__ __forceinline__ void split2(float x, float y, bf16& hx, bf16& hy,
                                       bf16& lx, bf16& ly) {
    hx = __float2bfloat16_rn(x);
    hy = __float2bfloat16_rn(y);
    lx = __float2bfloat16_rn(x - __bfloat162float(hx));
    ly = __float2bfloat16_rn(y - __bfloat162float(hy));
}

// SMEM tile geometry: K-chunk 32 halfwords = 64B + 16B pad = 80B rows.
#define ROWB 80
#define A_COMP (256 * ROWB)           // 20480
#define B_COMP (128 * ROWB)           // 10240

// bf16x3 q/k kernel: per stage A_hi, A_lo (256 rows), B_hi, B_lo (128 rows)
#define OFF_AHI 0
#define OFF_ALO A_COMP
#define OFF_BHI (2 * A_COMP)
#define OFF_BLO (2 * A_COMP + B_COMP)
#define STAGE_BYTES (2 * A_COMP + 2 * B_COMP)  // 61440
#define PIPE 3
#define SMEM_BYTES (PIPE * STAGE_BYTES)        // 184320

// fp16x1 kernel (v/out): per stage A (256 rows), B (128 rows)
#define STAGE_F16 (A_COMP + B_COMP)            // 30720
#define PIPE_F16 4
#define SMEM_F16 (PIPE_F16 * STAGE_F16)        // 122880

// fp16x2 attn kernel: per stage A_hi, A_lo (256 rows), B (128 rows)
#define STAGE_QK (2 * A_COMP + B_COMP)         // 51200
#define PIPE_QK 3
#define SMEM_QK (PIPE_QK * STAGE_QK)           // 153600

// ---------------------------------------------------------------------------
// bf16x3 NT GEMM for q/k projections: C = A * B^T + bias[row], A/B bf16
// hi/lo pairs, K-major. CTA 256x128, 512 threads, 3-stage cp.async.
// EPI: 1 = write fp16 hi/lo (q); 4 = write fp16 hi only (k).
// ---------------------------------------------------------------------------
template <int EPI>
__global__ __launch_bounds__(512) void gemm_bf(
    const bf16* __restrict__ Ahi, const bf16* __restrict__ Alo, long long lda,
    const bf16* __restrict__ Bhi, const bf16* __restrict__ Blo, long long ldb,
    half* __restrict__ Chi, half* __restrict__ Clo, long long ldc,
    const float* __restrict__ bias,
    int nchunks)
{
    extern __shared__ char smem[];
    const int tid = threadIdx.x;
    const int wid = tid >> 5;
    const int lane = tid & 31;

    const size_t m0 = (size_t)blockIdx.y * 256;
    const size_t n0 = (size_t)blockIdx.x * 128;

    const int seg = tid & 3;
    const int r = tid >> 2;
    const uint32_t sb = smem_to_u32(smem);
    const uint32_t sr0 = r * ROWB + seg * 16;
    const uint32_t sr1 = (r + 128) * ROWB + seg * 16;

    const bf16* Ah0 = Ahi + (m0 + r) * (size_t)lda + seg * 8;
    const bf16* Ah1 = Ahi + (m0 + r + 128) * (size_t)lda + seg * 8;
    const bf16* Al0 = Alo + (m0 + r) * (size_t)lda + seg * 8;
    const bf16* Al1 = Alo + (m0 + r + 128) * (size_t)lda + seg * 8;
    const bf16* Bh0 = Bhi + (n0 + r) * (size_t)ldb + seg * 8;
    const bf16* Bl0 = Blo + (n0 + r) * (size_t)ldb + seg * 8;

    auto load_stage = [&](int kc, int s) {
        const uint32_t st = sb + s * STAGE_BYTES;
        const size_t ko = (size_t)kc * 32;
        CP_ASYNC16(st + OFF_AHI + sr0, Ah0 + ko);
        CP_ASYNC16(st + OFF_AHI + sr1, Ah1 + ko);
        CP_ASYNC16(st + OFF_ALO + sr0, Al0 + ko);
        CP_ASYNC16(st + OFF_ALO + sr1, Al1 + ko);
        CP_ASYNC16(st + OFF_BHI + sr0, Bh0 + ko);
        CP_ASYNC16(st + OFF_BLO + sr0, Bl0 + ko);
        CP_COMMIT();
    };

    const int wm = (wid >> 2) * 64;
    const int wn = (wid & 3) * 32;

    float acc[4][4][4];
#pragma unroll
    for (int i = 0; i < 4; i++)
#pragma unroll
        for (int j = 0; j < 4; j++)
#pragma unroll
            for (int k = 0; k < 4; k++) acc[i][j][k] = 0.f;

    const uint32_t lrow16 = lane & 15;
    const uint32_t lcol16 = (lane >> 4) * 16;

#pragma unroll
    for (int s = 0; s < PIPE - 1; s++) load_stage(s, s);

    for (int i = 0; i < nchunks; i++) {
        CP_WAIT(PIPE - 2);
        __syncthreads();

        if (i + PIPE - 1 < nchunks) load_stage(i + PIPE - 1, (i + PIPE - 1) % PIPE);

        const uint32_t st = sb + (i % PIPE) * STAGE_BYTES;
#pragma unroll
        for (int kk = 0; kk < 2; kk++) {
            const uint32_t kb = kk * 32 + lcol16;
            uint32_t Bfh[4][2], Bfl[4][2];
#pragma unroll
            for (int p = 0; p < 2; p++) {
                uint32_t bd = st + OFF_BHI + (wn + p * 16 + lrow16) * ROWB + kb;
                uint32_t t[4];
                ldsm_x4(bd, t);
                Bfh[2 * p][0] = t[0]; Bfh[2 * p][1] = t[2];
                Bfh[2 * p + 1][0] = t[1]; Bfh[2 * p + 1][1] = t[3];
                ldsm_x4(bd + B_COMP, t);
                Bfl[2 * p][0] = t[0]; Bfl[2 * p][1] = t[2];
                Bfl[2 * p + 1][0] = t[1]; Bfl[2 * p + 1][1] = t[3];
            }
#pragma unroll
            for (int mp = 0; mp < 2; mp++) {
                uint32_t Afh[2][4], Afl[2][4];
#pragma unroll
                for (int m2 = 0; m2 < 2; m2++) {
                    uint32_t ad = st + OFF_AHI +
                        (wm + (mp * 2 + m2) * 16 + lrow16) * ROWB + kb;
                    ldsm_x4(ad, Afh[m2]);
                    ldsm_x4(ad + A_COMP, Afl[m2]);
                }
#pragma unroll
                for (int m2 = 0; m2 < 2; m2++) {
                    const int mt = mp * 2 + m2;
#pragma unroll
                    for (int nt = 0; nt < 4; nt++) {
                        mma_bf16(acc[mt][nt], Afh[m2], Bfh[nt]);
                        mma_bf16(acc[mt][nt], Afh[m2], Bfl[nt]);
                        mma_bf16(acc[mt][nt], Afl[m2], Bfh[nt]);
                    }
                }
            }
        }
    }

    // Epilogue: +bias[row], write fp16 hi (+lo for EPI==1)
    const int er = lane >> 2;
    const int ec = (lane & 3) * 2;
#pragma unroll
    for (int mt = 0; mt < 4; mt++) {
#pragma unroll
        for (int half_i = 0; half_i < 2; half_i++) {
            const size_t row = m0 + wm + mt * 16 + er + half_i * 8;
            const float rowbias = bias[row];
#pragma unroll
            for (int nt = 0; nt < 4; nt++) {
                const size_t col = n0 + wn + nt * 8 + ec;
                float vx = acc[mt][nt][half_i * 2 + 0] + rowbias;
                float vy = acc[mt][nt][half_i * 2 + 1] + rowbias;
                half hx = __float2half_rn(vx);
                half hy = __float2half_rn(vy);
                *(__half2*)(Chi + row * (size_t)ldc + col) = __half2(hx, hy);
                if (EPI == 1) {
                    half lx = __float2half_rn(vx - __half2float(hx));
                    half ly = __float2half_rn(vy - __half2float(hy));
                    *(__half2*)(Clo + row * (size_t)ldc + col) = __half2(lx, ly);
                }
            }
        }
    }
}

// ---------------------------------------------------------------------------
// fp16x2 attn GEMM: attnT = q * k^T, q fp16 hi/lo, k fp16. 2 MMAs per pair:
// qh*kh + ql*kh = q*kh exactly (only k's rounding survives).
// CTA 256x128, K-chunk 32, 3-stage cp.async, 512 threads, 16 warps.
// ---------------------------------------------------------------------------
__global__ __launch_bounds__(512) void gemm_attn(
    const half* __restrict__ Qh, const half* __restrict__ Ql, long long lda,
    long long a_bs,
    const half* __restrict__ Kh, long long ldb, long long b_bs,
    float* __restrict__ C, long long ldc, long long c_bs,
    int nchunks)
{
    extern __shared__ char smem[];
    const int tid = threadIdx.x;
    const int wid = tid >> 5;
    const int lane = tid & 31;

    const size_t m0 = (size_t)blockIdx.y * 256;
    const size_t n0 = (size_t)blockIdx.x * 128;
    const size_t z = blockIdx.z;
    Qh += z * a_bs; Ql += z * a_bs;
    Kh += z * b_bs;

    const int seg = tid & 3;
    const int r = tid >> 2;
    const uint32_t sb = smem_to_u32(smem);
    const uint32_t sr0 = r * ROWB + seg * 16;
    const uint32_t sr1 = (r + 128) * ROWB + seg * 16;

    const half* Qh0 = Qh + (m0 + r) * (size_t)lda + seg * 8;
    const half* Qh1 = Qh + (m0 + r + 128) * (size_t)lda + seg * 8;
    const half* Ql0 = Ql + (m0 + r) * (size_t)lda + seg * 8;
    const half* Ql1 = Ql + (m0 + r + 128) * (size_t)lda + seg * 8;
    const half* Kh0 = Kh + (n0 + r) * (size_t)ldb + seg * 8;

    auto load_stage = [&](int kc, int s) {
        const uint32_t st = sb + s * STAGE_QK;
        const size_t ko = (size_t)kc * 32;
        CP_ASYNC16(st + sr0, Qh0 + ko);
        CP_ASYNC16(st + sr1, Qh1 + ko);
        CP_ASYNC16(st + A_COMP + sr0, Ql0 + ko);
        CP_ASYNC16(st + A_COMP + sr1, Ql1 + ko);
        CP_ASYNC16(st + 2 * A_COMP + sr0, Kh0 + ko);
        CP_COMMIT();
    };

    const int wm = (wid >> 2) * 64;
    const int wn = (wid & 3) * 32;

    float acc[4][4][4];
#pragma unroll
    for (int i = 0; i < 4; i++)
#pragma unroll
        for (int j = 0; j < 4; j++)
#pragma unroll
            for (int k = 0; k < 4; k++) acc[i][j][k] = 0.f;

    const uint32_t lrow16 = lane & 15;
    const uint32_t lcol16 = (lane >> 4) * 16;

#pragma unroll
    for (int s = 0; s < PIPE_QK - 1; s++) load_stage(s, s);

    for (int i = 0; i < nchunks; i++) {
        CP_WAIT(PIPE_QK - 2);
        __syncthreads();

        if (i + PIPE_QK - 1 < nchunks)
            load_stage(i + PIPE_QK - 1, (i + PIPE_QK - 1) % PIPE_QK);

        const uint32_t st = sb + (i % PIPE_QK) * STAGE_QK;
#pragma unroll
        for (int kk = 0; kk < 2; kk++) {
            const uint32_t kb = kk * 32 + lcol16;
            uint32_t Bf[4][2];
#pragma unroll
            for (int p = 0; p < 2; p++) {
                uint32_t bd = st + 2 * A_COMP + (wn + p * 16 + lrow16) * ROWB + kb;
                uint32_t t[4];
                ldsm_x4(bd, t);
                Bf[2 * p][0] = t[0]; Bf[2 * p][1] = t[2];
                Bf[2 * p + 1][0] = t[1]; Bf[2 * p + 1][1] = t[3];
            }
#pragma unroll
            for (int mp = 0; mp < 2; mp++) {
                uint32_t Ah[2][4], Al[2][4];
#pragma unroll
                for (int m2 = 0; m2 < 2; m2++) {
                    uint32_t ad = st + (wm + (mp * 2 + m2) * 16 + lrow16) * ROWB + kb;
                    ldsm_x4(ad, Ah[m2]);
                    ldsm_x4(ad + A_COMP, Al[m2]);
                }
#pragma unroll
                for (int m2 = 0; m2 < 2; m2++) {
                    const int mt = mp * 2 + m2;
#pragma unroll
                    for (int nt = 0; nt < 4; nt++) {
                        mma_fp16(acc[mt][nt], Ah[m2], Bf[nt]);
                        mma_fp16(acc[mt][nt], Al[m2], Bf[nt]);
                    }
                }
            }
        }
    }

    // Epilogue: fp32 store
    const int er = lane >> 2;
    const int ec = (lane & 3) * 2;
    float* Cz = C + z * c_bs;
#pragma unroll
    for (int mt = 0; mt < 4; mt++) {
#pragma unroll
        for (int half_i = 0; half_i < 2; half_i++) {
            const size_t row = m0 + wm + mt * 16 + er + half_i * 8;
#pragma unroll
            for (int nt = 0; nt < 4; nt++) {
                const size_t col = n0 + wn + nt * 8 + ec;
                *(float2*)(Cz + row * (size_t)ldc + col) = make_float2(
                    acc[mt][nt][half_i * 2 + 0], acc[mt][nt][half_i * 2 + 1]);
            }
        }
    }
}

// ---------------------------------------------------------------------------
// fp16 single-MMA NT GEMM (v / out). CTA 256x128, 4-stage cp.async.
// EPI: 2 = +bias[col] -> fp16; 3 = gamma*acc + resid -> fp32.
// ---------------------------------------------------------------------------
template <int EPI>
__global__ __launch_bounds__(512) void gemm_f16(
    const half* __restrict__ A, long long lda, long long a_bs,
    const half* __restrict__ B, long long ldb, long long b_bs,
    float* __restrict__ Cf, half* __restrict__ Ch, long long ldc, long long c_bs,
    const float* __restrict__ bias,
    const float* __restrict__ resid,
    const float* __restrict__ gamma,
    int nchunks)
{
    extern __shared__ char smem[];
    const int tid = threadIdx.x;
    const int wid = tid >> 5;
    const int lane = tid & 31;

    const size_t m0 = (size_t)blockIdx.y * 256;
    const size_t n0 = (size_t)blockIdx.x * 128;
    const size_t z = blockIdx.z;
    A += z * a_bs;
    B += z * b_bs;

    const int seg = tid & 3;
    const int r = tid >> 2;
    const uint32_t sb = smem_to_u32(smem);
    const uint32_t sr0 = r * ROWB + seg * 16;
    const uint32_t sr1 = (r + 128) * ROWB + seg * 16;

    const half* A0 = A + (m0 + r) * (size_t)lda + seg * 8;
    const half* A1 = A + (m0 + r + 128) * (size_t)lda + seg * 8;
    const half* B0 = B + (n0 + r) * (size_t)ldb + seg * 8;

    auto load_stage = [&](int kc, int s) {
        const uint32_t st = sb + s * STAGE_F16;
        const size_t ko = (size_t)kc * 32;
        CP_ASYNC16(st + sr0, A0 + ko);
        CP_ASYNC16(st + sr1, A1 + ko);
        CP_ASYNC16(st + A_COMP + sr0, B0 + ko);
        CP_COMMIT();
    };

    const int wm = (wid >> 2) * 64;
    const int wn = (wid & 3) * 32;

    float acc[4][4][4];
#pragma unroll
    for (int i = 0; i < 4; i++)
#pragma unroll
        for (int j = 0; j < 4; j++)
#pragma unroll
            for (int k = 0; k < 4; k++) acc[i][j][k] = 0.f;

    const uint32_t lrow16 = lane & 15;
    const uint32_t lcol16 = (lane >> 4) * 16;

#pragma unroll
    for (int s = 0; s < PIPE_F16 - 1; s++) load_stage(s, s);

    for (int i = 0; i < nchunks; i++) {
        CP_WAIT(PIPE_F16 - 2);
        __syncthreads();

        if (i + PIPE_F16 - 1 < nchunks)
            load_stage(i + PIPE_F16 - 1, (i + PIPE_F16 - 1) % PIPE_F16);

        const uint32_t st = sb + (i % PIPE_F16) * STAGE_F16;
#pragma unroll
        for (int kk = 0; kk < 2; kk++) {
            const uint32_t kb = kk * 32 + lcol16;
            uint32_t Bf[4][2];
#pragma unroll
            for (int p = 0; p < 2; p++) {
                uint32_t bd = st + A_COMP + (wn + p * 16 + lrow16) * ROWB + kb;
                uint32_t t[4];
                ldsm_x4(bd, t);
                Bf[2 * p][0] = t[0]; Bf[2 * p][1] = t[2];
                Bf[2 * p + 1][0] = t[1]; Bf[2 * p + 1][1] = t[3];
            }
            uint32_t Af[4][4];
#pragma unroll
            for (int mt = 0; mt < 4; mt++) {
                uint32_t ad = st + (wm + mt * 16 + lrow16) * ROWB + kb;
                ldsm_x4(ad, Af[mt]);
            }
#pragma unroll
            for (int mt = 0; mt < 4; mt++)
#pragma unroll
                for (int nt = 0; nt < 4; nt++)
                    mma_fp16(acc[mt][nt], Af[mt], Bf[nt]);
        }
    }

    // Epilogue
    const int er = lane >> 2;
    const int ec = (lane & 3) * 2;
    const float g = (EPI == 3) ? __ldg(gamma) : 0.f;
    const float* rz = (EPI == 3) ? (resid + z * c_bs) : (const float*)nullptr;
    float* Cfz = (EPI == 3) ? (Cf + z * c_bs) : nullptr;
    half* Chz = (EPI == 2) ? (Ch + z * c_bs) : nullptr;
#pragma unroll
    for (int mt = 0; mt < 4; mt++) {
#pragma unroll
        for (int half_i = 0; half_i < 2; half_i++) {
            const size_t row = m0 + wm + mt * 16 + er + half_i * 8;
#pragma unroll
            for (int nt = 0; nt < 4; nt++) {
                const size_t col = n0 + wn + nt * 8 + ec;
                float vx = acc[mt][nt][half_i * 2 + 0];
                float vy = acc[mt][nt][half_i * 2 + 1];
                if (EPI == 2) {
                    vx += bias[col]; vy += bias[col + 1];
                    __half2 h2 = __floats2half2_rn(vx, vy);
                    *(__half2*)(Chz + row * (size_t)ldc + col) = h2;
                } else {
                    const float2 rv = *(const float2*)(rz + row * (size_t)ldc + col);
                    vx = fmaf(g, vx, rv.x);
                    vy = fmaf(g, vy, rv.y);
                    *(float2*)(Cfz + row * (size_t)ldc + col) = make_float2(vx, vy);
                }
            }
        }
    }
}

// ---------------------------------------------------------------------------
// Fused input conversion: fp32 -> bf16 hi/lo + fp16. Reads input once.
// ---------------------------------------------------------------------------
__global__ void convert_input(const float* __restrict__ x,
                              bf16* __restrict__ hi, bf16* __restrict__ lo,
                              half* __restrict__ f16, size_t n4)
{
    for (size_t i = blockIdx.x * (size_t)blockDim.x + threadIdx.x; i < n4;
         i += (size_t)gridDim.x * blockDim.x) {
        float4 v = ((const float4*)x)[i];
        bf16 h0, h1, h2, h3, l0, l1, l2, l3;
        split2(v.x, v.y, h0, h1, l0, l1);
        split2(v.z, v.w, h2, h3, l2, l3);
        ((__nv_bfloat162*)hi)[2 * i] = __nv_bfloat162(h0, h1);
        ((__nv_bfloat162*)hi)[2 * i + 1] = __nv_bfloat162(h2, h3);
        ((__nv_bfloat162*)lo)[2 * i] = __nv_bfloat162(l0, l1);
        ((__nv_bfloat162*)lo)[2 * i + 1] = __nv_bfloat162(l2, l3);
        ((__half2*)f16)[2 * i] = __floats2half2_rn(v.x, v.y);
        ((__half2*)f16)[2 * i + 1] = __floats2half2_rn(v.z, v.w);
    }
}

__global__ void convert_hilo(const float* __restrict__ x,
                             bf16* __restrict__ hi, bf16* __restrict__ lo,
                             size_t n4)
{
    for (size_t i = blockIdx.x * (size_t)blockDim.x + threadIdx.x; i < n4;
         i += (size_t)gridDim.x * blockDim.x) {
        float4 v = ((const float4*)x)[i];
        bf16 h0, h1, h2, h3, l0, l1, l2, l3;
        split2(v.x, v.y, h0, h1, l0, l1);
        split2(v.z, v.w, h2, h3, l2, l3);
        ((__nv_bfloat162*)hi)[2 * i] = __nv_bfloat162(h0, h1);
        ((__nv_bfloat162*)hi)[2 * i + 1] = __nv_bfloat162(h2, h3);
        ((__nv_bfloat162*)lo)[2 * i] = __nv_bfloat162(l0, l1);
        ((__nv_bfloat162*)lo)[2 * i + 1] = __nv_bfloat162(l2, l3);
    }
}

__global__ void convert_f16(const float* __restrict__ x, half* __restrict__ o,
                            size_t n4)
{
    for (size_t i = blockIdx.x * (size_t)blockDim.x + threadIdx.x; i < n4;
         i += (size_t)gridDim.x * blockDim.x) {
        float4 v = ((const float4*)x)[i];
        ((__half2*)o)[2 * i] = __floats2half2_rn(v.x, v.y);
        ((__half2*)o)[2 * i + 1] = __floats2half2_rn(v.z, v.w);
    }
}

// ---------------------------------------------------------------------------
// Column softmax on attnT (softmax over w rows per (batch, v) column),
// writing fp16. block (32,16), grid (VDIM/32, BATCH).
// ---------------------------------------------------------------------------
__global__ __launch_bounds__(512) void softmax_col(
    const float* __restrict__ attnT, half* __restrict__ out_h)
{
    __shared__ float red[16][33];
    const int tx = threadIdx.x, ty = threadIdx.y;
    const size_t base = (size_t)blockIdx.y * VDIM * VDIM + (size_t)blockIdx.x * 32 + tx;

    float vals[64];
    float m = -INFINITY;
#pragma unroll
    for (int k = 0; k < 64; k++) {
        vals[k] = attnT[base + (size_t)(ty + 16 * k) * VDIM];
        m = fmaxf(m, vals[k]);
    }
    red[ty][tx] = m;
    __syncthreads();
#pragma unroll
    for (int off = 8; off >= 1; off >>= 1) {
        if (ty < off) red[ty][tx] = fmaxf(red[ty][tx], red[ty + off][tx]);
        __syncthreads();
    }
    m = red[0][tx];
    __syncthreads();

    float s = 0.f;
#pragma unroll
    for (int k = 0; k < 64; k++) {
        vals[k] = __expf(vals[k] - m);
        s += vals[k];
    }
    red[ty][tx] = s;
    __syncthreads();
#pragma unroll
    for (int off = 8; off >= 1; off >>= 1) {
        if (ty < off) red[ty][tx] += red[ty + off][tx];
        __syncthreads();
    }
    const float inv = 1.0f / red[0][tx];

#pragma unroll
    for (int k = 0; k < 64; k++) {
        const size_t idx = base + (size_t)(ty + 16 * k) * VDIM;
        out_h[idx] = __float2half_rn(vals[k] * inv);
    }
}

// ---------------------------------------------------------------------------
extern "C" void kernel_launch(void* const* d_in, const int* in_sizes, int n_in,
                              void* d_out, int out_size)
{
    const float* input = (const float*)d_in[0];
    const float* Wq    = (const float*)d_in[1];
    const float* bq    = (const float*)d_in[2];
    const float* Wk    = (const float*)d_in[3];
    const float* bk    = (const float*)d_in[4];
    const float* Wv    = (const float*)d_in[5];
    const float* bv    = (const float*)d_in[6];
    const float* gamma = (const float*)d_in[7];
    float* out = (float*)d_out;

    bf16 *in_hi, *in_lo, *wq_hi, *wq_lo, *wk_hi, *wk_lo;
    half *qT_hi, *qT_lo, *kT_hi;
    half *in_f16, *wv_f16, *v_f16, *att_f16;
    float* attnT;
    cudaGetSymbolAddress((void**)&in_hi, g_in_hi);
    cudaGetSymbolAddress((void**)&in_lo, g_in_lo);
    cudaGetSymbolAddress((void**)&wq_hi, g_wq_hi);
    cudaGetSymbolAddress((void**)&wq_lo, g_wq_lo);
    cudaGetSymbolAddress((void**)&wk_hi, g_wk_hi);
    cudaGetSymbolAddress((void**)&wk_lo, g_wk_lo);
    cudaGetSymbolAddress((void**)&qT_hi, g_qT_hi);
    cudaGetSymbolAddress((void**)&qT_lo, g_qT_lo);
    cudaGetSymbolAddress((void**)&kT_hi, g_kT_hi);
    cudaGetSymbolAddress((void**)&in_f16, g_in_f16);
    cudaGetSymbolAddress((void**)&wv_f16, g_wv_f16);
    cudaGetSymbolAddress((void**)&v_f16, g_v_f16);
    cudaGetSymbolAddress((void**)&att_f16, g_att_f16);
    cudaGetSymbolAddress((void**)&attnT, g_attnT);

    cudaFuncSetAttribute(gemm_bf<1>, cudaFuncAttributeMaxDynamicSharedMemorySize, SMEM_BYTES);
    cudaFuncSetAttribute(gemm_bf<4>, cudaFuncAttributeMaxDynamicSharedMemorySize, SMEM_BYTES);
    cudaFuncSetAttribute(gemm_attn, cudaFuncAttributeMaxDynamicSharedMemorySize, SMEM_QK);
    cudaFuncSetAttribute(gemm_f16<2>, cudaFuncAttributeMaxDynamicSharedMemorySize, SMEM_F16);
    cudaFuncSetAttribute(gemm_f16<3>, cudaFuncAttributeMaxDynamicSharedMemorySize, SMEM_F16);

    const long long MN = (long long)BATCH * SEQ;   // 32768
    const long long BSEQ = (long long)SEQ * VDIM;  // 4194304
    const long long AT = (long long)VDIM * VDIM;   // 1048576

    // Conversions (input read once)
    convert_input<<<2048, 256>>>(input, in_hi, in_lo, in_f16,
                                 (size_t)MN * VDIM / 4);
    convert_hilo<<<64, 256>>>(Wq, wq_hi, wq_lo, (size_t)VDIM * KQDIM / 4);
    convert_hilo<<<64, 256>>>(Wk, wk_hi, wk_lo, (size_t)VDIM * KQDIM / 4);
    convert_f16<<<256, 256>>>(Wv, wv_f16, (size_t)VDIM * VDIM / 4);

    // qT[w, n] = sum_e Wq[w,e] * input[n, 768+e]  (M=1024, N=32768, K=256)
    // bf16x3, epilogue emits fp16 hi/lo
    gemm_bf<1><<<dim3(256, 4, 1), 512, SMEM_BYTES>>>(
        wq_hi, wq_lo, KQDIM,
        in_hi + (VDIM - KQDIM), in_lo + (VDIM - KQDIM), VDIM,
        qT_hi, qT_lo, MN, bq, KQDIM / 32);
    // kT[v, n] — fp16 hi only
    gemm_bf<4><<<dim3(256, 4, 1), 512, SMEM_BYTES>>>(
        wk_hi, wk_lo, KQDIM,
        in_hi + (VDIM - KQDIM), in_lo + (VDIM - KQDIM), VDIM,
        kT_hi, nullptr, MN, bk, KQDIM / 32);
    // v[n, w] = sum_e input[n,e] * Wv[w,e]  (M=32768, N=1024, K=1024), fp16 x1
    gemm_f16<2><<<dim3(8, 128, 1), 512, SMEM_F16>>>(
        in_f16, VDIM, 0, wv_f16, VDIM, 0,
        nullptr, v_f16, VDIM, 0, bv, nullptr, nullptr, VDIM / 32);
    // attnT[b][w, v] = sum_n q[w, bn] * kh[v, bn]  (fp16 x2, M=N=1024, K=4096)
    gemm_attn<<<dim3(8, 4, 8), 512, SMEM_QK>>>(
        qT_hi, qT_lo, MN, SEQ,
        kT_hi, MN, SEQ,
        attnT, VDIM, AT, SEQ / 32);
    // softmax over w; emit fp16
    softmax_col<<<dim3(VDIM / 32, BATCH), dim3(32, 16)>>>(attnT, att_f16);
    // out[b][n, w] = gamma * sum_v v[bn, v] * attT[b][w, v] + input, fp16 x1
    gemm_f16<3><<<dim3(8, 16, 8), 512, SMEM_F16>>>(
        v_f16, VDIM, BSEQ, att_f16, VDIM, AT,
        out, nullptr, VDIM, BSEQ, nullptr, input, gamma, VDIM / 32);
}

// round 9
// speedup vs baseline: 5.4963x; 1.4423x over previous
#include <cuda_runtime.h>
#include <cuda_fp16.h>
#include <cstdint>
#include <math.h>

// Problem constants
#define BATCH 8
#define SEQ   4096
#define VDIM  1024
#define KQDIM 256

// ---------------------------------------------------------------------------
// Scratch (device globals; no runtime allocation allowed) — all fp16 path
// ---------------------------------------------------------------------------
__device__ half g_in_f16[(size_t)BATCH * SEQ * VDIM];
__device__ half g_wq_f16[(size_t)VDIM * KQDIM];
__device__ half g_wk_f16[(size_t)VDIM * KQDIM];
__device__ half g_wv_f16[(size_t)VDIM * VDIM];
__device__ half g_qT[(size_t)VDIM * BATCH * SEQ];      // [1024 w][32768 n]
__device__ half g_kT[(size_t)VDIM * BATCH * SEQ];
__device__ half g_v_f16[(size_t)BATCH * SEQ * VDIM];   // [32768 n][1024 v]
__device__ float g_attnT[(size_t)BATCH * VDIM * VDIM]; // [8][1024 w][1024 v]
__device__ half g_att_f16[(size_t)BATCH * VDIM * VDIM];

// ---------------------------------------------------------------------------
// Helpers
// ---------------------------------------------------------------------------
__device__ __forceinline__ uint32_t smem_to_u32(const void* p) {
    uint32_t a;
    asm("{ .reg .u64 t; cvta.to.shared.u64 t, %1; cvt.u32.u64 %0, t; }"
        : "=r"(a) : "l"(p));
    return a;
}

__device__ __forceinline__ void ldsm_x4(uint32_t addr, uint32_t* r) {
    asm volatile("ldmatrix.sync.aligned.m8n8.x4.shared.b16 {%0,%1,%2,%3}, [%4];"
        : "=r"(r[0]), "=r"(r[1]), "=r"(r[2]), "=r"(r[3]) : "r"(addr));
}

__device__ __forceinline__ void mma_fp16(float* d, const uint32_t* a, const uint32_t* b) {
    asm volatile(
        "mma.sync.aligned.m16n8k16.row.col.f32.f16.f16.f32 "
        "{%0,%1,%2,%3}, {%4,%5,%6,%7}, {%8,%9}, {%0,%1,%2,%3};"
        : "+f"(d[0]), "+f"(d[1]), "+f"(d[2]), "+f"(d[3])
        : "r"(a[0]), "r"(a[1]), "r"(a[2]), "r"(a[3]), "r"(b[0]), "r"(b[1]));
}

#define CP_ASYNC16(s, g) \
    asm volatile("cp.async.cg.shared.global [%0], [%1], 16;" :: "r"(s), "l"(g))
#define CP_COMMIT() asm volatile("cp.async.commit_group;" ::: "memory")
#define CP_WAIT(n)  asm volatile("cp.async.wait_group %0;" :: "n"(n) : "memory")

// SMEM tile geometry: K-chunk 32 halfwords = 64B + 16B pad = 80B rows.
#define ROWB 80
#define A_COMP (256 * ROWB)           // 20480
#define B_COMP (128 * ROWB)           // 10240
#define STAGE_F16 (A_COMP + B_COMP)   // 30720
#define PIPE_F16 4
#define SMEM_F16 (PIPE_F16 * STAGE_F16)  // 122880

// ---------------------------------------------------------------------------
// Unified fp16 NT GEMM: C = A * B^T, K-major fp16 operands.
// CTA tile 256x128, K-chunk 32, 4-stage cp.async, 512 threads, 16 warps
// (4x4), warp tile 64x32. fp32 accumulate.
// EPI: 0 = fp32 store (attn logits)
//      1 = +bias[row] -> fp16 (q/k projections, output transposed layout)
//      2 = +bias[col] -> fp16 (v projection)
//      3 = gamma*acc + resid -> fp32 (final output)
// ---------------------------------------------------------------------------
template <int EPI>
__global__ __launch_bounds__(512) void gemm_f16(
    const half* __restrict__ A, long long lda, long long a_bs,
    const half* __restrict__ B, long long ldb, long long b_bs,
    float* __restrict__ Cf, half* __restrict__ Ch, long long ldc, long long c_bs,
    const float* __restrict__ bias,
    const float* __restrict__ resid,
    const float* __restrict__ gamma,
    int nchunks)
{
    extern __shared__ char smem[];
    const int tid = threadIdx.x;
    const int wid = tid >> 5;
    const int lane = tid & 31;

    const size_t m0 = (size_t)blockIdx.y * 256;
    const size_t n0 = (size_t)blockIdx.x * 128;
    const size_t z = blockIdx.z;
    A += z * a_bs;
    B += z * b_bs;

    const int seg = tid & 3;
    const int r = tid >> 2;
    const uint32_t sb = smem_to_u32(smem);
    const uint32_t sr0 = r * ROWB + seg * 16;
    const uint32_t sr1 = (r + 128) * ROWB + seg * 16;

    const half* A0 = A + (m0 + r) * (size_t)lda + seg * 8;
    const half* A1 = A + (m0 + r + 128) * (size_t)lda + seg * 8;
    const half* B0 = B + (n0 + r) * (size_t)ldb + seg * 8;

    auto load_stage = [&](int kc, int s) {
        const uint32_t st = sb + s * STAGE_F16;
        const size_t ko = (size_t)kc * 32;
        CP_ASYNC16(st + sr0, A0 + ko);
        CP_ASYNC16(st + sr1, A1 + ko);
        CP_ASYNC16(st + A_COMP + sr0, B0 + ko);
        CP_COMMIT();
    };

    const int wm = (wid >> 2) * 64;
    const int wn = (wid & 3) * 32;

    float acc[4][4][4];
#pragma unroll
    for (int i = 0; i < 4; i++)
#pragma unroll
        for (int j = 0; j < 4; j++)
#pragma unroll
            for (int k = 0; k < 4; k++) acc[i][j][k] = 0.f;

    const uint32_t lrow16 = lane & 15;
    const uint32_t lcol16 = (lane >> 4) * 16;

#pragma unroll
    for (int s = 0; s < PIPE_F16 - 1; s++) load_stage(s, s);

    for (int i = 0; i < nchunks; i++) {
        CP_WAIT(PIPE_F16 - 2);
        __syncthreads();

        if (i + PIPE_F16 - 1 < nchunks)
            load_stage(i + PIPE_F16 - 1, (i + PIPE_F16 - 1) % PIPE_F16);

        const uint32_t st = sb + (i % PIPE_F16) * STAGE_F16;
#pragma unroll
        for (int kk = 0; kk < 2; kk++) {
            const uint32_t kb = kk * 32 + lcol16;
            uint32_t Bf[4][2];
#pragma unroll
            for (int p = 0; p < 2; p++) {
                uint32_t bd = st + A_COMP + (wn + p * 16 + lrow16) * ROWB + kb;
                uint32_t t[4];
                ldsm_x4(bd, t);
                Bf[2 * p][0] = t[0]; Bf[2 * p][1] = t[2];
                Bf[2 * p + 1][0] = t[1]; Bf[2 * p + 1][1] = t[3];
            }
            uint32_t Af[4][4];
#pragma unroll
            for (int mt = 0; mt < 4; mt++) {
                uint32_t ad = st + (wm + mt * 16 + lrow16) * ROWB + kb;
                ldsm_x4(ad, Af[mt]);
            }
#pragma unroll
            for (int mt = 0; mt < 4; mt++)
#pragma unroll
                for (int nt = 0; nt < 4; nt++)
                    mma_fp16(acc[mt][nt], Af[mt], Bf[nt]);
        }
    }

    // Epilogue
    const int er = lane >> 2;
    const int ec = (lane & 3) * 2;
    const float g = (EPI == 3) ? __ldg(gamma) : 0.f;
    const float* rz = (EPI == 3) ? (resid + z * c_bs) : (const float*)nullptr;
    float* Cfz = (EPI == 0 || EPI == 3) ? (Cf + z * c_bs) : nullptr;
    half* Chz = (EPI == 1 || EPI == 2) ? (Ch + z * c_bs) : nullptr;
#pragma unroll
    for (int mt = 0; mt < 4; mt++) {
#pragma unroll
        for (int half_i = 0; half_i < 2; half_i++) {
            const size_t row = m0 + wm + mt * 16 + er + half_i * 8;
            float rowbias = 0.f;
            if (EPI == 1) rowbias = bias[row];
#pragma unroll
            for (int nt = 0; nt < 4; nt++) {
                const size_t col = n0 + wn + nt * 8 + ec;
                float vx = acc[mt][nt][half_i * 2 + 0];
                float vy = acc[mt][nt][half_i * 2 + 1];
                if (EPI == 1) {
                    vx += rowbias; vy += rowbias;
                    *(__half2*)(Chz + row * (size_t)ldc + col) =
                        __floats2half2_rn(vx, vy);
                } else if (EPI == 2) {
                    vx += bias[col]; vy += bias[col + 1];
                    *(__half2*)(Chz + row * (size_t)ldc + col) =
                        __floats2half2_rn(vx, vy);
                } else if (EPI == 3) {
                    const float2 rv = *(const float2*)(rz + row * (size_t)ldc + col);
                    vx = fmaf(g, vx, rv.x);
                    vy = fmaf(g, vy, rv.y);
                    *(float2*)(Cfz + row * (size_t)ldc + col) = make_float2(vx, vy);
                } else {
                    *(float2*)(Cfz + row * (size_t)ldc + col) = make_float2(vx, vy);
                }
            }
        }
    }
}

// ---------------------------------------------------------------------------
// Convert fp32 array -> fp16. Grid-stride, float4 granularity.
// ---------------------------------------------------------------------------
__global__ void convert_f16(const float* __restrict__ x, half* __restrict__ o,
                            size_t n4)
{
    for (size_t i = blockIdx.x * (size_t)blockDim.x + threadIdx.x; i < n4;
         i += (size_t)gridDim.x * blockDim.x) {
        float4 v = ((const float4*)x)[i];
        ((__half2*)o)[2 * i] = __floats2half2_rn(v.x, v.y);
        ((__half2*)o)[2 * i + 1] = __floats2half2_rn(v.z, v.w);
    }
}

// ---------------------------------------------------------------------------
// Column softmax on attnT (softmax over w rows per (batch, v) column),
// writing fp16. block (32,16), grid (VDIM/32, BATCH).
// ---------------------------------------------------------------------------
__global__ __launch_bounds__(512) void softmax_col(
    const float* __restrict__ attnT, half* __restrict__ out_h)
{
    __shared__ float red[16][33];
    const int tx = threadIdx.x, ty = threadIdx.y;
    const size_t base = (size_t)blockIdx.y * VDIM * VDIM + (size_t)blockIdx.x * 32 + tx;

    float vals[64];
    float m = -INFINITY;
#pragma unroll
    for (int k = 0; k < 64; k++) {
        vals[k] = attnT[base + (size_t)(ty + 16 * k) * VDIM];
        m = fmaxf(m, vals[k]);
    }
    red[ty][tx] = m;
    __syncthreads();
#pragma unroll
    for (int off = 8; off >= 1; off >>= 1) {
        if (ty < off) red[ty][tx] = fmaxf(red[ty][tx], red[ty + off][tx]);
        __syncthreads();
    }
    m = red[0][tx];
    __syncthreads();

    float s = 0.f;
#pragma unroll
    for (int k = 0; k < 64; k++) {
        vals[k] = __expf(vals[k] - m);
        s += vals[k];
    }
    red[ty][tx] = s;
    __syncthreads();
#pragma unroll
    for (int off = 8; off >= 1; off >>= 1) {
        if (ty < off) red[ty][tx] += red[ty + off][tx];
        __syncthreads();
    }
    const float inv = 1.0f / red[0][tx];

#pragma unroll
    for (int k = 0; k < 64; k++) {
        const size_t idx = base + (size_t)(ty + 16 * k) * VDIM;
        out_h[idx] = __float2half_rn(vals[k] * inv);
    }
}

// ---------------------------------------------------------------------------
extern "C" void kernel_launch(void* const* d_in, const int* in_sizes, int n_in,
                              void* d_out, int out_size)
{
    const float* input = (const float*)d_in[0];
    const float* Wq    = (const float*)d_in[1];
    const float* bq    = (const float*)d_in[2];
    const float* Wk    = (const float*)d_in[3];
    const float* bk    = (const float*)d_in[4];
    const float* Wv    = (const float*)d_in[5];
    const float* bv    = (const float*)d_in[6];
    const float* gamma = (const float*)d_in[7];
    float* out = (float*)d_out;

    half *in_f16, *wq_f16, *wk_f16, *wv_f16, *qT, *kT, *v_f16, *att_f16;
    float* attnT;
    cudaGetSymbolAddress((void**)&in_f16, g_in_f16);
    cudaGetSymbolAddress((void**)&wq_f16, g_wq_f16);
    cudaGetSymbolAddress((void**)&wk_f16, g_wk_f16);
    cudaGetSymbolAddress((void**)&wv_f16, g_wv_f16);
    cudaGetSymbolAddress((void**)&qT, g_qT);
    cudaGetSymbolAddress((void**)&kT, g_kT);
    cudaGetSymbolAddress((void**)&v_f16, g_v_f16);
    cudaGetSymbolAddress((void**)&att_f16, g_att_f16);
    cudaGetSymbolAddress((void**)&attnT, g_attnT);

    cudaFuncSetAttribute(gemm_f16<0>, cudaFuncAttributeMaxDynamicSharedMemorySize, SMEM_F16);
    cudaFuncSetAttribute(gemm_f16<1>, cudaFuncAttributeMaxDynamicSharedMemorySize, SMEM_F16);
    cudaFuncSetAttribute(gemm_f16<2>, cudaFuncAttributeMaxDynamicSharedMemorySize, SMEM_F16);
    cudaFuncSetAttribute(gemm_f16<3>, cudaFuncAttributeMaxDynamicSharedMemorySize, SMEM_F16);

    const long long MN = (long long)BATCH * SEQ;   // 32768
    const long long BSEQ = (long long)SEQ * VDIM;  // 4194304
    const long long AT = (long long)VDIM * VDIM;   // 1048576

    // Conversions — all fp16
    convert_f16<<<2048, 256>>>(input, in_f16, (size_t)MN * VDIM / 4);
    convert_f16<<<64, 256>>>(Wq, wq_f16, (size_t)VDIM * KQDIM / 4);
    convert_f16<<<64, 256>>>(Wk, wk_f16, (size_t)VDIM * KQDIM / 4);
    convert_f16<<<256, 256>>>(Wv, wv_f16, (size_t)VDIM * VDIM / 4);

    // qT[w, n] = sum_e Wq[w,e] * input[n, 768+e]  (M=1024, N=32768, K=256)
    gemm_f16<1><<<dim3(256, 4, 1), 512, SMEM_F16>>>(
        wq_f16, KQDIM, 0,
        in_f16 + (VDIM - KQDIM), VDIM, 0,
        nullptr, qT, MN, 0, bq, nullptr, nullptr, KQDIM / 32);
    // kT[v, n]
    gemm_f16<1><<<dim3(256, 4, 1), 512, SMEM_F16>>>(
        wk_f16, KQDIM, 0,
        in_f16 + (VDIM - KQDIM), VDIM, 0,
        nullptr, kT, MN, 0, bk, nullptr, nullptr, KQDIM / 32);
    // v[n, w] = sum_e input[n,e] * Wv[w,e]  (M=32768, N=1024, K=1024)
    gemm_f16<2><<<dim3(8, 128, 1), 512, SMEM_F16>>>(
        in_f16, VDIM, 0, wv_f16, VDIM, 0,
        nullptr, v_f16, VDIM, 0, bv, nullptr, nullptr, VDIM / 32);
    // attnT[b][w, v] = sum_n qT[w, bn] * kT[v, bn]  (per batch M=N=1024, K=4096)
    gemm_f16<0><<<dim3(8, 4, 8), 512, SMEM_F16>>>(
        qT, MN, SEQ, kT, MN, SEQ,
        attnT, nullptr, VDIM, AT, nullptr, nullptr, nullptr, SEQ / 32);
    // softmax over w; emit fp16
    softmax_col<<<dim3(VDIM / 32, BATCH), dim3(32, 16)>>>(attnT, att_f16);
    // out[b][n, w] = gamma * sum_v v[bn, v] * attT[b][w, v] + input
    gemm_f16<3><<<dim3(8, 16, 8), 512, SMEM_F16>>>(
        v_f16, VDIM, BSEQ, att_f16, VDIM, AT,
        out, nullptr, VDIM, BSEQ, nullptr, input, gamma, VDIM / 32);
}

// round 10
// speedup vs baseline: 6.1548x; 1.1198x over previous
#include <cuda_runtime.h>
#include <cuda_fp16.h>
#include <cstdint>
#include <math.h>

// Problem constants
#define BATCH 8
#define SEQ   4096
#define VDIM  1024
#define KQDIM 256

// ---------------------------------------------------------------------------
// Scratch (device globals; no runtime allocation allowed) — all fp16 path
// ---------------------------------------------------------------------------
__device__ half g_in_f16[(size_t)BATCH * SEQ * VDIM];
__device__ half g_wq_f16[(size_t)VDIM * KQDIM];
__device__ half g_wk_f16[(size_t)VDIM * KQDIM];
__device__ half g_wv_f16[(size_t)VDIM * VDIM];
__device__ half g_qT[(size_t)VDIM * BATCH * SEQ];      // [1024 w][32768 n]
__device__ half g_kT[(size_t)VDIM * BATCH * SEQ];
__device__ half g_v_f16[(size_t)BATCH * SEQ * VDIM];   // [32768 n][1024 v]
__device__ float g_attnT[(size_t)BATCH * VDIM * VDIM]; // [8][1024 w][1024 v]
__device__ half g_att_f16[(size_t)BATCH * VDIM * VDIM];

// ---------------------------------------------------------------------------
// Helpers
// ---------------------------------------------------------------------------
__device__ __forceinline__ uint32_t smem_to_u32(const void* p) {
    uint32_t a;
    asm("{ .reg .u64 t; cvta.to.shared.u64 t, %1; cvt.u32.u64 %0, t; }"
        : "=r"(a) : "l"(p));
    return a;
}

__device__ __forceinline__ void ldsm_x4(uint32_t addr, uint32_t* r) {
    asm volatile("ldmatrix.sync.aligned.m8n8.x4.shared.b16 {%0,%1,%2,%3}, [%4];"
        : "=r"(r[0]), "=r"(r[1]), "=r"(r[2]), "=r"(r[3]) : "r"(addr));
}

__device__ __forceinline__ void mma_fp16(float* d, const uint32_t* a, const uint32_t* b) {
    asm volatile(
        "mma.sync.aligned.m16n8k16.row.col.f32.f16.f16.f32 "
        "{%0,%1,%2,%3}, {%4,%5,%6,%7}, {%8,%9}, {%0,%1,%2,%3};"
        : "+f"(d[0]), "+f"(d[1]), "+f"(d[2]), "+f"(d[3])
        : "r"(a[0]), "r"(a[1]), "r"(a[2]), "r"(a[3]), "r"(b[0]), "r"(b[1]));
}

#define CP_ASYNC16(s, g) \
    asm volatile("cp.async.cg.shared.global [%0], [%1], 16;" :: "r"(s), "l"(g))
#define CP_COMMIT() asm volatile("cp.async.commit_group;" ::: "memory")
#define CP_WAIT(n)  asm volatile("cp.async.wait_group %0;" :: "n"(n) : "memory")

// SMEM tile geometry: K-chunk 64 halfwords = 128B data + 16B pad = 144B rows.
// 144B = 9 x 16B (odd multiple) => ldsm / STS.128 phases stay conflict-free.
#define ROWB 144
#define A_COMP (256 * ROWB)            // 36864
#define B_COMP (128 * ROWB)            // 18432
#define STAGE_F16 (A_COMP + B_COMP)    // 55296
#define PIPE_F16 3
#define SMEM_F16 (PIPE_F16 * STAGE_F16)  // 165888

// ---------------------------------------------------------------------------
// Unified fp16 NT GEMM: C = A * B^T, K-major fp16 operands.
// CTA tile 256x128, K-chunk 64, 3-stage cp.async, 512 threads, 16 warps
// (4x4), warp tile 64x32. fp32 accumulate.
// EPI: 0 = fp32 store (attn logits)
//      1 = +bias[row] -> fp16 (q/k projections, transposed layout)
//      2 = +bias[col] -> fp16 (v projection)
//      3 = gamma*acc + resid -> fp32 (final output)
// ---------------------------------------------------------------------------
template <int EPI>
__global__ __launch_bounds__(512) void gemm_f16(
    const half* __restrict__ A, long long lda, long long a_bs,
    const half* __restrict__ B, long long ldb, long long b_bs,
    float* __restrict__ Cf, half* __restrict__ Ch, long long ldc, long long c_bs,
    const float* __restrict__ bias,
    const float* __restrict__ resid,
    const float* __restrict__ gamma,
    int nchunks)
{
    extern __shared__ char smem[];
    const int tid = threadIdx.x;
    const int wid = tid >> 5;
    const int lane = tid & 31;

    const size_t m0 = (size_t)blockIdx.y * 256;
    const size_t n0 = (size_t)blockIdx.x * 128;
    const size_t z = blockIdx.z;
    A += z * a_bs;
    B += z * b_bs;

    // cp.async mapping: seg = tid&7 (16B of the 128B row), r = tid>>3 (0..63)
    const int seg = tid & 7;
    const int r = tid >> 3;
    const uint32_t sb = smem_to_u32(smem);

    const half* Ag[4];
    uint32_t Asm[4];
#pragma unroll
    for (int j = 0; j < 4; j++) {
        Ag[j] = A + (m0 + r + 64 * j) * (size_t)lda + seg * 8;
        Asm[j] = (r + 64 * j) * ROWB + seg * 16;
    }
    const half* Bg[2];
    uint32_t Bsm[2];
#pragma unroll
    for (int j = 0; j < 2; j++) {
        Bg[j] = B + (n0 + r + 64 * j) * (size_t)ldb + seg * 8;
        Bsm[j] = A_COMP + (r + 64 * j) * ROWB + seg * 16;
    }

    auto load_stage = [&](int kc, int s) {
        const uint32_t st = sb + s * STAGE_F16;
        const size_t ko = (size_t)kc * 64;
#pragma unroll
        for (int j = 0; j < 4; j++) CP_ASYNC16(st + Asm[j], Ag[j] + ko);
#pragma unroll
        for (int j = 0; j < 2; j++) CP_ASYNC16(st + Bsm[j], Bg[j] + ko);
        CP_COMMIT();
    };

    const int wm = (wid >> 2) * 64;
    const int wn = (wid & 3) * 32;

    float acc[4][4][4];
#pragma unroll
    for (int i = 0; i < 4; i++)
#pragma unroll
        for (int j = 0; j < 4; j++)
#pragma unroll
            for (int k = 0; k < 4; k++) acc[i][j][k] = 0.f;

    const uint32_t lrow16 = lane & 15;
    const uint32_t lcol16 = (lane >> 4) * 16;

#pragma unroll
    for (int s = 0; s < PIPE_F16 - 1; s++) load_stage(s, s);

    for (int i = 0; i < nchunks; i++) {
        CP_WAIT(PIPE_F16 - 2);
        __syncthreads();

        if (i + PIPE_F16 - 1 < nchunks)
            load_stage(i + PIPE_F16 - 1, (i + PIPE_F16 - 1) % PIPE_F16);

        const uint32_t st = sb + (i % PIPE_F16) * STAGE_F16;
#pragma unroll
        for (int kk = 0; kk < 4; kk++) {
            const uint32_t kb = kk * 32 + lcol16;
            uint32_t Bf[4][2];
#pragma unroll
            for (int p = 0; p < 2; p++) {
                uint32_t bd = st + A_COMP + (wn + p * 16 + lrow16) * ROWB + kb;
                uint32_t t[4];
                ldsm_x4(bd, t);
                Bf[2 * p][0] = t[0]; Bf[2 * p][1] = t[2];
                Bf[2 * p + 1][0] = t[1]; Bf[2 * p + 1][1] = t[3];
            }
            uint32_t Af[4][4];
#pragma unroll
            for (int mt = 0; mt < 4; mt++) {
                uint32_t ad = st + (wm + mt * 16 + lrow16) * ROWB + kb;
                ldsm_x4(ad, Af[mt]);
            }
#pragma unroll
            for (int mt = 0; mt < 4; mt++)
#pragma unroll
                for (int nt = 0; nt < 4; nt++)
                    mma_fp16(acc[mt][nt], Af[mt], Bf[nt]);
        }
    }

    // Epilogue
    const int er = lane >> 2;
    const int ec = (lane & 3) * 2;
    const float g = (EPI == 3) ? __ldg(gamma) : 0.f;
    const float* rz = (EPI == 3) ? (resid + z * c_bs) : (const float*)nullptr;
    float* Cfz = (EPI == 0 || EPI == 3) ? (Cf + z * c_bs) : nullptr;
    half* Chz = (EPI == 1 || EPI == 2) ? (Ch + z * c_bs) : nullptr;
#pragma unroll
    for (int mt = 0; mt < 4; mt++) {
#pragma unroll
        for (int half_i = 0; half_i < 2; half_i++) {
            const size_t row = m0 + wm + mt * 16 + er + half_i * 8;
            float rowbias = 0.f;
            if (EPI == 1) rowbias = bias[row];
#pragma unroll
            for (int nt = 0; nt < 4; nt++) {
                const size_t col = n0 + wn + nt * 8 + ec;
                float vx = acc[mt][nt][half_i * 2 + 0];
                float vy = acc[mt][nt][half_i * 2 + 1];
                if (EPI == 1) {
                    vx += rowbias; vy += rowbias;
                    *(__half2*)(Chz + row * (size_t)ldc + col) =
                        __floats2half2_rn(vx, vy);
                } else if (EPI == 2) {
                    vx += bias[col]; vy += bias[col + 1];
                    *(__half2*)(Chz + row * (size_t)ldc + col) =
                        __floats2half2_rn(vx, vy);
                } else if (EPI == 3) {
                    const float2 rv = *(const float2*)(rz + row * (size_t)ldc + col);
                    vx = fmaf(g, vx, rv.x);
                    vy = fmaf(g, vy, rv.y);
                    *(float2*)(Cfz + row * (size_t)ldc + col) = make_float2(vx, vy);
                } else {
                    *(float2*)(Cfz + row * (size_t)ldc + col) = make_float2(vx, vy);
                }
            }
        }
    }
}

// ---------------------------------------------------------------------------
// Convert fp32 array -> fp16. Grid-stride, float4 granularity.
// ---------------------------------------------------------------------------
__global__ void convert_f16(const float* __restrict__ x, half* __restrict__ o,
                            size_t n4)
{
    for (size_t i = blockIdx.x * (size_t)blockDim.x + threadIdx.x; i < n4;
         i += (size_t)gridDim.x * blockDim.x) {
        float4 v = ((const float4*)x)[i];
        ((__half2*)o)[2 * i] = __floats2half2_rn(v.x, v.y);
        ((__half2*)o)[2 * i + 1] = __floats2half2_rn(v.z, v.w);
    }
}

// ---------------------------------------------------------------------------
// Column softmax on attnT (softmax over w rows per (batch, v) column),
// writing fp16. block (32,16), grid (VDIM/32, BATCH).
// ---------------------------------------------------------------------------
__global__ __launch_bounds__(512) void softmax_col(
    const float* __restrict__ attnT, half* __restrict__ out_h)
{
    __shared__ float red[16][33];
    const int tx = threadIdx.x, ty = threadIdx.y;
    const size_t base = (size_t)blockIdx.y * VDIM * VDIM + (size_t)blockIdx.x * 32 + tx;

    float vals[64];
    float m = -INFINITY;
#pragma unroll
    for (int k = 0; k < 64; k++) {
        vals[k] = attnT[base + (size_t)(ty + 16 * k) * VDIM];
        m = fmaxf(m, vals[k]);
    }
    red[ty][tx] = m;
    __syncthreads();
#pragma unroll
    for (int off = 8; off >= 1; off >>= 1) {
        if (ty < off) red[ty][tx] = fmaxf(red[ty][tx], red[ty + off][tx]);
        __syncthreads();
    }
    m = red[0][tx];
    __syncthreads();

    float s = 0.f;
#pragma unroll
    for (int k = 0; k < 64; k++) {
        vals[k] = __expf(vals[k] - m);
        s += vals[k];
    }
    red[ty][tx] = s;
    __syncthreads();
#pragma unroll
    for (int off = 8; off >= 1; off >>= 1) {
        if (ty < off) red[ty][tx] += red[ty + off][tx];
        __syncthreads();
    }
    const float inv = 1.0f / red[0][tx];

#pragma unroll
    for (int k = 0; k < 64; k++) {
        const size_t idx = base + (size_t)(ty + 16 * k) * VDIM;
        out_h[idx] = __float2half_rn(vals[k] * inv);
    }
}

// ---------------------------------------------------------------------------
extern "C" void kernel_launch(void* const* d_in, const int* in_sizes, int n_in,
                              void* d_out, int out_size)
{
    const float* input = (const float*)d_in[0];
    const float* Wq    = (const float*)d_in[1];
    const float* bq    = (const float*)d_in[2];
    const float* Wk    = (const float*)d_in[3];
    const float* bk    = (const float*)d_in[4];
    const float* Wv    = (const float*)d_in[5];
    const float* bv    = (const float*)d_in[6];
    const float* gamma = (const float*)d_in[7];
    float* out = (float*)d_out;

    half *in_f16, *wq_f16, *wk_f16, *wv_f16, *qT, *kT, *v_f16, *att_f16;
    float* attnT;
    cudaGetSymbolAddress((void**)&in_f16, g_in_f16);
    cudaGetSymbolAddress((void**)&wq_f16, g_wq_f16);
    cudaGetSymbolAddress((void**)&wk_f16, g_wk_f16);
    cudaGetSymbolAddress((void**)&wv_f16, g_wv_f16);
    cudaGetSymbolAddress((void**)&qT, g_qT);
    cudaGetSymbolAddress((void**)&kT, g_kT);
    cudaGetSymbolAddress((void**)&v_f16, g_v_f16);
    cudaGetSymbolAddress((void**)&att_f16, g_att_f16);
    cudaGetSymbolAddress((void**)&attnT, g_attnT);

    cudaFuncSetAttribute(gemm_f16<0>, cudaFuncAttributeMaxDynamicSharedMemorySize, SMEM_F16);
    cudaFuncSetAttribute(gemm_f16<1>, cudaFuncAttributeMaxDynamicSharedMemorySize, SMEM_F16);
    cudaFuncSetAttribute(gemm_f16<2>, cudaFuncAttributeMaxDynamicSharedMemorySize, SMEM_F16);
    cudaFuncSetAttribute(gemm_f16<3>, cudaFuncAttributeMaxDynamicSharedMemorySize, SMEM_F16);

    // Side stream for the independent v-branch (created once, outside capture).
    static cudaStream_t sv = nullptr;
    static cudaEvent_t evFork = nullptr, evJoin = nullptr;
    if (sv == nullptr) {
        cudaStreamCreateWithFlags(&sv, cudaStreamNonBlocking);
        cudaEventCreateWithFlags(&evFork, cudaEventDisableTiming);
        cudaEventCreateWithFlags(&evJoin, cudaEventDisableTiming);
    }

    const long long MN = (long long)BATCH * SEQ;   // 32768
    const long long BSEQ = (long long)SEQ * VDIM;  // 4194304
    const long long AT = (long long)VDIM * VDIM;   // 1048576

    // Conversions — input first (both branches need it)
    convert_f16<<<2048, 256>>>(input, in_f16, (size_t)MN * VDIM / 4);

    // Fork: v branch on side stream (wv convert + v GEMM)
    cudaEventRecord(evFork, 0);
    cudaStreamWaitEvent(sv, evFork, 0);
    convert_f16<<<256, 256, 0, sv>>>(Wv, wv_f16, (size_t)VDIM * VDIM / 4);
    gemm_f16<2><<<dim3(8, 128, 1), 512, SMEM_F16, sv>>>(
        in_f16, VDIM, 0, wv_f16, VDIM, 0,
        nullptr, v_f16, VDIM, 0, bv, nullptr, nullptr, VDIM / 64);
    cudaEventRecord(evJoin, sv);

    // Main branch: q/k projections, attn, softmax
    convert_f16<<<64, 256>>>(Wq, wq_f16, (size_t)VDIM * KQDIM / 4);
    convert_f16<<<64, 256>>>(Wk, wk_f16, (size_t)VDIM * KQDIM / 4);

    // qT[w, n] = sum_e Wq[w,e] * input[n, 768+e]  (M=1024, N=32768, K=256)
    gemm_f16<1><<<dim3(256, 4, 1), 512, SMEM_F16>>>(
        wq_f16, KQDIM, 0,
        in_f16 + (VDIM - KQDIM), VDIM, 0,
        nullptr, qT, MN, 0, bq, nullptr, nullptr, KQDIM / 64);
    // kT[v, n]
    gemm_f16<1><<<dim3(256, 4, 1), 512, SMEM_F16>>>(
        wk_f16, KQDIM, 0,
        in_f16 + (VDIM - KQDIM), VDIM, 0,
        nullptr, kT, MN, 0, bk, nullptr, nullptr, KQDIM / 64);
    // attnT[b][w, v] = sum_n qT[w, bn] * kT[v, bn]  (per batch M=N=1024, K=4096)
    gemm_f16<0><<<dim3(8, 4, 8), 512, SMEM_F16>>>(
        qT, MN, SEQ, kT, MN, SEQ,
        attnT, nullptr, VDIM, AT, nullptr, nullptr, nullptr, SEQ / 64);
    // softmax over w; emit fp16
    softmax_col<<<dim3(VDIM / 32, BATCH), dim3(32, 16)>>>(attnT, att_f16);

    // Join: out GEMM needs v
    cudaStreamWaitEvent(0, evJoin, 0);
    // out[b][n, w] = gamma * sum_v v[bn, v] * attT[b][w, v] + input
    gemm_f16<3><<<dim3(8, 16, 8), 512, SMEM_F16>>>(
        v_f16, VDIM, BSEQ, att_f16, VDIM, AT,
        out, nullptr, VDIM, BSEQ, nullptr, input, gamma, VDIM / 64);
}

// round 11
// speedup vs baseline: 6.4875x; 1.0541x over previous
#include <cuda_runtime.h>
#include <cuda_fp16.h>
#include <cstdint>
#include <math.h>

// Problem constants
#define BATCH 8
#define SEQ   4096
#define VDIM  1024
#define KQDIM 256

// ---------------------------------------------------------------------------
// Scratch (device globals; no runtime allocation allowed) — all fp16 path
// ---------------------------------------------------------------------------
__device__ half g_in_f16[(size_t)BATCH * SEQ * VDIM];
__device__ half g_wq_f16[(size_t)VDIM * KQDIM];
__device__ half g_wk_f16[(size_t)VDIM * KQDIM];
__device__ half g_wv_f16[(size_t)VDIM * VDIM];
__device__ half g_qT[(size_t)VDIM * BATCH * SEQ];      // [1024 w][32768 n]
__device__ half g_kT[(size_t)VDIM * BATCH * SEQ];
__device__ half g_v_f16[(size_t)BATCH * SEQ * VDIM];   // [32768 n][1024 v]
__device__ float g_attnT[(size_t)BATCH * VDIM * VDIM]; // [8][1024 w][1024 v]
__device__ half g_att_f16[(size_t)BATCH * VDIM * VDIM];

// ---------------------------------------------------------------------------
// Helpers
// ---------------------------------------------------------------------------
__device__ __forceinline__ uint32_t smem_to_u32(const void* p) {
    uint32_t a;
    asm("{ .reg .u64 t; cvta.to.shared.u64 t, %1; cvt.u32.u64 %0, t; }"
        : "=r"(a) : "l"(p));
    return a;
}

__device__ __forceinline__ void ldsm_x4(uint32_t addr, uint32_t* r) {
    asm volatile("ldmatrix.sync.aligned.m8n8.x4.shared.b16 {%0,%1,%2,%3}, [%4];"
        : "=r"(r[0]), "=r"(r[1]), "=r"(r[2]), "=r"(r[3]) : "r"(addr));
}

__device__ __forceinline__ void mma_fp16(float* d, const uint32_t* a, const uint32_t* b) {
    asm volatile(
        "mma.sync.aligned.m16n8k16.row.col.f32.f16.f16.f32 "
        "{%0,%1,%2,%3}, {%4,%5,%6,%7}, {%8,%9}, {%0,%1,%2,%3};"
        : "+f"(d[0]), "+f"(d[1]), "+f"(d[2]), "+f"(d[3])
        : "r"(a[0]), "r"(a[1]), "r"(a[2]), "r"(a[3]), "r"(b[0]), "r"(b[1]));
}

#define CP_ASYNC16(s, g) \
    asm volatile("cp.async.cg.shared.global [%0], [%1], 16;" :: "r"(s), "l"(g))
#define CP_COMMIT() asm volatile("cp.async.commit_group;" ::: "memory")
#define CP_WAIT(n)  asm volatile("cp.async.wait_group %0;" :: "n"(n) : "memory")

// SMEM tile geometry: K-chunk 64 halfwords = 128B data + 16B pad = 144B rows.
// 144B = 9 x 16B (odd multiple) => ldsm / STS.128 phases stay conflict-free.
#define ROWB 144
#define A_COMP (128 * ROWB)            // 18432 (128-row M tile)
#define B_COMP (128 * ROWB)            // 18432
#define STAGE_F16 (A_COMP + B_COMP)    // 36864
#define PIPE_F16 3
#define SMEM_F16 (PIPE_F16 * STAGE_F16)  // 110592 -> 2 CTAs/SM

// ---------------------------------------------------------------------------
// Unified fp16 NT GEMM: C = A * B^T, K-major fp16 operands.
// CTA tile 128x128, K-chunk 64, 3-stage cp.async, 256 threads, 8 warps
// (2x4), warp tile 64x32. fp32 accumulate. 2 CTAs resident per SM.
// EPI: 0 = fp32 store (attn logits)
//      1 = +bias[row] -> fp16 (q/k projections, transposed layout)
//      2 = +bias[col] -> fp16 (v projection)
//      3 = gamma*acc + resid -> fp32 (final output)
// ---------------------------------------------------------------------------
template <int EPI>
__global__ __launch_bounds__(256, 2) void gemm_f16(
    const half* __restrict__ A, long long lda, long long a_bs,
    const half* __restrict__ B, long long ldb, long long b_bs,
    float* __restrict__ Cf, half* __restrict__ Ch, long long ldc, long long c_bs,
    const float* __restrict__ bias,
    const float* __restrict__ resid,
    const float* __restrict__ gamma,
    int nchunks)
{
    extern __shared__ char smem[];
    const int tid = threadIdx.x;
    const int wid = tid >> 5;
    const int lane = tid & 31;

    const size_t m0 = (size_t)blockIdx.y * 128;
    const size_t n0 = (size_t)blockIdx.x * 128;
    const size_t z = blockIdx.z;
    A += z * a_bs;
    B += z * b_bs;

    // cp.async mapping: seg = tid&7 (16B of the 128B row), r = tid>>3 (0..31)
    const int seg = tid & 7;
    const int r = tid >> 3;
    const uint32_t sb = smem_to_u32(smem);

    const half* Ag[4];
    uint32_t Asm[4];
#pragma unroll
    for (int j = 0; j < 4; j++) {
        Ag[j] = A + (m0 + r + 32 * j) * (size_t)lda + seg * 8;
        Asm[j] = (r + 32 * j) * ROWB + seg * 16;
    }
    const half* Bg[4];
    uint32_t Bsm[4];
#pragma unroll
    for (int j = 0; j < 4; j++) {
        Bg[j] = B + (n0 + r + 32 * j) * (size_t)ldb + seg * 8;
        Bsm[j] = A_COMP + (r + 32 * j) * ROWB + seg * 16;
    }

    auto load_stage = [&](int kc, int s) {
        const uint32_t st = sb + s * STAGE_F16;
        const size_t ko = (size_t)kc * 64;
#pragma unroll
        for (int j = 0; j < 4; j++) CP_ASYNC16(st + Asm[j], Ag[j] + ko);
#pragma unroll
        for (int j = 0; j < 4; j++) CP_ASYNC16(st + Bsm[j], Bg[j] + ko);
        CP_COMMIT();
    };

    // Warp tile origin (8 warps: 2 x 4)
    const int wm = (wid >> 2) * 64;
    const int wn = (wid & 3) * 32;

    float acc[4][4][4];
#pragma unroll
    for (int i = 0; i < 4; i++)
#pragma unroll
        for (int j = 0; j < 4; j++)
#pragma unroll
            for (int k = 0; k < 4; k++) acc[i][j][k] = 0.f;

    const uint32_t lrow16 = lane & 15;
    const uint32_t lcol16 = (lane >> 4) * 16;

#pragma unroll
    for (int s = 0; s < PIPE_F16 - 1; s++) load_stage(s, s);

    for (int i = 0; i < nchunks; i++) {
        CP_WAIT(PIPE_F16 - 2);
        __syncthreads();

        if (i + PIPE_F16 - 1 < nchunks)
            load_stage(i + PIPE_F16 - 1, (i + PIPE_F16 - 1) % PIPE_F16);

        const uint32_t st = sb + (i % PIPE_F16) * STAGE_F16;
#pragma unroll
        for (int kk = 0; kk < 4; kk++) {
            const uint32_t kb = kk * 32 + lcol16;
            uint32_t Bf[4][2];
#pragma unroll
            for (int p = 0; p < 2; p++) {
                uint32_t bd = st + A_COMP + (wn + p * 16 + lrow16) * ROWB + kb;
                uint32_t t[4];
                ldsm_x4(bd, t);
                Bf[2 * p][0] = t[0]; Bf[2 * p][1] = t[2];
                Bf[2 * p + 1][0] = t[1]; Bf[2 * p + 1][1] = t[3];
            }
            uint32_t Af[4][4];
#pragma unroll
            for (int mt = 0; mt < 4; mt++) {
                uint32_t ad = st + (wm + mt * 16 + lrow16) * ROWB + kb;
                ldsm_x4(ad, Af[mt]);
            }
#pragma unroll
            for (int mt = 0; mt < 4; mt++)
#pragma unroll
                for (int nt = 0; nt < 4; nt++)
                    mma_fp16(acc[mt][nt], Af[mt], Bf[nt]);
        }
    }

    // Epilogue
    const int er = lane >> 2;
    const int ec = (lane & 3) * 2;
    const float g = (EPI == 3) ? __ldg(gamma) : 0.f;
    const float* rz = (EPI == 3) ? (resid + z * c_bs) : (const float*)nullptr;
    float* Cfz = (EPI == 0 || EPI == 3) ? (Cf + z * c_bs) : nullptr;
    half* Chz = (EPI == 1 || EPI == 2) ? (Ch + z * c_bs) : nullptr;
#pragma unroll
    for (int mt = 0; mt < 4; mt++) {
#pragma unroll
        for (int half_i = 0; half_i < 2; half_i++) {
            const size_t row = m0 + wm + mt * 16 + er + half_i * 8;
            float rowbias = 0.f;
            if (EPI == 1) rowbias = bias[row];
#pragma unroll
            for (int nt = 0; nt < 4; nt++) {
                const size_t col = n0 + wn + nt * 8 + ec;
                float vx = acc[mt][nt][half_i * 2 + 0];
                float vy = acc[mt][nt][half_i * 2 + 1];
                if (EPI == 1) {
                    vx += rowbias; vy += rowbias;
                    *(__half2*)(Chz + row * (size_t)ldc + col) =
                        __floats2half2_rn(vx, vy);
                } else if (EPI == 2) {
                    vx += bias[col]; vy += bias[col + 1];
                    *(__half2*)(Chz + row * (size_t)ldc + col) =
                        __floats2half2_rn(vx, vy);
                } else if (EPI == 3) {
                    const float2 rv = *(const float2*)(rz + row * (size_t)ldc + col);
                    vx = fmaf(g, vx, rv.x);
                    vy = fmaf(g, vy, rv.y);
                    *(float2*)(Cfz + row * (size_t)ldc + col) = make_float2(vx, vy);
                } else {
                    *(float2*)(Cfz + row * (size_t)ldc + col) = make_float2(vx, vy);
                }
            }
        }
    }
}

// ---------------------------------------------------------------------------
// Convert fp32 array -> fp16. Grid-stride, float4 granularity.
// ---------------------------------------------------------------------------
__global__ void convert_f16(const float* __restrict__ x, half* __restrict__ o,
                            size_t n4)
{
    for (size_t i = blockIdx.x * (size_t)blockDim.x + threadIdx.x; i < n4;
         i += (size_t)gridDim.x * blockDim.x) {
        float4 v = ((const float4*)x)[i];
        ((__half2*)o)[2 * i] = __floats2half2_rn(v.x, v.y);
        ((__half2*)o)[2 * i + 1] = __floats2half2_rn(v.z, v.w);
    }
}

// ---------------------------------------------------------------------------
// Column softmax on attnT (softmax over w rows per (batch, v) column),
// writing fp16. block (32,16), grid (VDIM/32, BATCH).
// ---------------------------------------------------------------------------
__global__ __launch_bounds__(512) void softmax_col(
    const float* __restrict__ attnT, half* __restrict__ out_h)
{
    __shared__ float red[16][33];
    const int tx = threadIdx.x, ty = threadIdx.y;
    const size_t base = (size_t)blockIdx.y * VDIM * VDIM + (size_t)blockIdx.x * 32 + tx;

    float vals[64];
    float m = -INFINITY;
#pragma unroll
    for (int k = 0; k < 64; k++) {
        vals[k] = attnT[base + (size_t)(ty + 16 * k) * VDIM];
        m = fmaxf(m, vals[k]);
    }
    red[ty][tx] = m;
    __syncthreads();
#pragma unroll
    for (int off = 8; off >= 1; off >>= 1) {
        if (ty < off) red[ty][tx] = fmaxf(red[ty][tx], red[ty + off][tx]);
        __syncthreads();
    }
    m = red[0][tx];
    __syncthreads();

    float s = 0.f;
#pragma unroll
    for (int k = 0; k < 64; k++) {
        vals[k] = __expf(vals[k] - m);
        s += vals[k];
    }
    red[ty][tx] = s;
    __syncthreads();
#pragma unroll
    for (int off = 8; off >= 1; off >>= 1) {
        if (ty < off) red[ty][tx] += red[ty + off][tx];
        __syncthreads();
    }
    const float inv = 1.0f / red[0][tx];

#pragma unroll
    for (int k = 0; k < 64; k++) {
        const size_t idx = base + (size_t)(ty + 16 * k) * VDIM;
        out_h[idx] = __float2half_rn(vals[k] * inv);
    }
}

// ---------------------------------------------------------------------------
extern "C" void kernel_launch(void* const* d_in, const int* in_sizes, int n_in,
                              void* d_out, int out_size)
{
    const float* input = (const float*)d_in[0];
    const float* Wq    = (const float*)d_in[1];
    const float* bq    = (const float*)d_in[2];
    const float* Wk    = (const float*)d_in[3];
    const float* bk    = (const float*)d_in[4];
    const float* Wv    = (const float*)d_in[5];
    const float* bv    = (const float*)d_in[6];
    const float* gamma = (const float*)d_in[7];
    float* out = (float*)d_out;

    half *in_f16, *wq_f16, *wk_f16, *wv_f16, *qT, *kT, *v_f16, *att_f16;
    float* attnT;
    cudaGetSymbolAddress((void**)&in_f16, g_in_f16);
    cudaGetSymbolAddress((void**)&wq_f16, g_wq_f16);
    cudaGetSymbolAddress((void**)&wk_f16, g_wk_f16);
    cudaGetSymbolAddress((void**)&wv_f16, g_wv_f16);
    cudaGetSymbolAddress((void**)&qT, g_qT);
    cudaGetSymbolAddress((void**)&kT, g_kT);
    cudaGetSymbolAddress((void**)&v_f16, g_v_f16);
    cudaGetSymbolAddress((void**)&att_f16, g_att_f16);
    cudaGetSymbolAddress((void**)&attnT, g_attnT);

    cudaFuncSetAttribute(gemm_f16<0>, cudaFuncAttributeMaxDynamicSharedMemorySize, SMEM_F16);
    cudaFuncSetAttribute(gemm_f16<1>, cudaFuncAttributeMaxDynamicSharedMemorySize, SMEM_F16);
    cudaFuncSetAttribute(gemm_f16<2>, cudaFuncAttributeMaxDynamicSharedMemorySize, SMEM_F16);
    cudaFuncSetAttribute(gemm_f16<3>, cudaFuncAttributeMaxDynamicSharedMemorySize, SMEM_F16);

    // Side stream for the independent v-branch (created once, outside capture).
    static cudaStream_t sv = nullptr;
    static cudaEvent_t evFork = nullptr, evJoin = nullptr;
    if (sv == nullptr) {
        cudaStreamCreateWithFlags(&sv, cudaStreamNonBlocking);
        cudaEventCreateWithFlags(&evFork, cudaEventDisableTiming);
        cudaEventCreateWithFlags(&evJoin, cudaEventDisableTiming);
    }

    const long long MN = (long long)BATCH * SEQ;   // 32768
    const long long BSEQ = (long long)SEQ * VDIM;  // 4194304
    const long long AT = (long long)VDIM * VDIM;   // 1048576

    // Conversions — input first (both branches need it)
    convert_f16<<<2048, 256>>>(input, in_f16, (size_t)MN * VDIM / 4);

    // Fork: v branch on side stream (wv convert + v GEMM)
    cudaEventRecord(evFork, 0);
    cudaStreamWaitEvent(sv, evFork, 0);
    convert_f16<<<256, 256, 0, sv>>>(Wv, wv_f16, (size_t)VDIM * VDIM / 4);
    gemm_f16<2><<<dim3(8, 256, 1), 256, SMEM_F16, sv>>>(
        in_f16, VDIM, 0, wv_f16, VDIM, 0,
        nullptr, v_f16, VDIM, 0, bv, nullptr, nullptr, VDIM / 64);
    cudaEventRecord(evJoin, sv);

    // Main branch: q/k projections, attn, softmax
    convert_f16<<<64, 256>>>(Wq, wq_f16, (size_t)VDIM * KQDIM / 4);
    convert_f16<<<64, 256>>>(Wk, wk_f16, (size_t)VDIM * KQDIM / 4);

    // qT[w, n] = sum_e Wq[w,e] * input[n, 768+e]  (M=1024, N=32768, K=256)
    gemm_f16<1><<<dim3(256, 8, 1), 256, SMEM_F16>>>(
        wq_f16, KQDIM, 0,
        in_f16 + (VDIM - KQDIM), VDIM, 0,
        nullptr, qT, MN, 0, bq, nullptr, nullptr, KQDIM / 64);
    // kT[v, n]
    gemm_f16<1><<<dim3(256, 8, 1), 256, SMEM_F16>>>(
        wk_f16, KQDIM, 0,
        in_f16 + (VDIM - KQDIM), VDIM, 0,
        nullptr, kT, MN, 0, bk, nullptr, nullptr, KQDIM / 64);
    // attnT[b][w, v] = sum_n qT[w, bn] * kT[v, bn]  (per batch M=N=1024, K=4096)
    gemm_f16<0><<<dim3(8, 8, 8), 256, SMEM_F16>>>(
        qT, MN, SEQ, kT, MN, SEQ,
        attnT, nullptr, VDIM, AT, nullptr, nullptr, nullptr, SEQ / 64);
    // softmax over w; emit fp16
    softmax_col<<<dim3(VDIM / 32, BATCH), dim3(32, 16)>>>(attnT, att_f16);

    // Join: out GEMM needs v
    cudaStreamWaitEvent(0, evJoin, 0);
    // out[b][n, w] = gamma * sum_v v[bn, v] * attT[b][w, v] + input
    gemm_f16<3><<<dim3(8, 32, 8), 256, SMEM_F16>>>(
        v_f16, VDIM, BSEQ, att_f16, VDIM, AT,
        out, nullptr, VDIM, BSEQ, nullptr, input, gamma, VDIM / 64);
}